// round 1
// baseline (speedup 1.0000x reference)
#include <cuda_runtime.h>
#include <math.h>

#define EPSF 1e-5f
#define SCALEF 0.17677669529663687f

#define NB   64
#define NPIX 196
#define QKVC 1536
#define DHC  1024

// scratch (no cudaMalloc allowed)
__device__ float g_qkv[NB * QKVC * NPIX];   // [b][1536][196]; q @ ch 0, k @ 256, v @ 512
__device__ float g_vloc[NB * DHC * NPIX];   // [b][1024][196]
__device__ float g_att [NB * DHC * NPIX];   // [b][1024][196]

// ------------------------------------------------------------------
// QKV GEMM: g_qkv[b, choff+oc, n] = BN( W[M,384] @ x[b,384,n] + bias )
// Tiles: 128(M) x 128(N) x 16(K), 8x8 micro-tile per thread, 256 threads.
// N flattened over (b,n): 64*196 = 12544 = 98 * 128 exactly.
__global__ void __launch_bounds__(256) qkv_gemm_kernel(
    const float* __restrict__ W, const float* __restrict__ X,
    const float* __restrict__ bias, const float* __restrict__ bn,
    int M, int choff)
{
    const int K = 384;
    __shared__ float As[16][129];   // [kk][m_local], padded for conflict-free stores
    __shared__ float Bs[16][128];   // [kk][j_local]

    int tid = threadIdx.x;
    int tx = tid & 15, ty = tid >> 4;
    int m0 = blockIdx.y * 128;
    int j0 = blockIdx.x * 128;

    // B-loader column: fixed per thread
    int jl = tid & 127;
    int kb = tid >> 7;                 // 0 or 1
    int jg = j0 + jl;
    int bcol = jg / NPIX;
    int ncol = jg - bcol * NPIX;
    const float* xcol = X + (size_t)bcol * (384 * NPIX) + ncol;

    // A-loader: thread loads (akk, am0 + 16*i)
    int akk = tid & 15, am0 = tid >> 4;
    const float* wptr = W + (size_t)(m0 + am0) * K + akk;

    float acc[8][8];
#pragma unroll
    for (int i = 0; i < 8; i++)
#pragma unroll
        for (int j = 0; j < 8; j++) acc[i][j] = 0.f;

    for (int k0 = 0; k0 < K; k0 += 16) {
#pragma unroll
        for (int i = 0; i < 8; i++)
            As[akk][am0 + 16 * i] = wptr[(size_t)(16 * i) * K + k0];
#pragma unroll
        for (int i = 0; i < 8; i++) {
            int kk = kb + 2 * i;
            Bs[kk][jl] = xcol[(size_t)(k0 + kk) * NPIX];
        }
        __syncthreads();
#pragma unroll
        for (int kk = 0; kk < 16; kk++) {
            float a[8], bv[8];
#pragma unroll
            for (int i = 0; i < 8; i++) a[i] = As[kk][ty + 16 * i];
#pragma unroll
            for (int j = 0; j < 8; j++) bv[j] = Bs[kk][tx + 16 * j];
#pragma unroll
            for (int i = 0; i < 8; i++)
#pragma unroll
                for (int j = 0; j < 8; j++)
                    acc[i][j] = fmaf(a[i], bv[j], acc[i][j]);
        }
        __syncthreads();
    }

#pragma unroll
    for (int i = 0; i < 8; i++) {
        int oc = m0 + ty + 16 * i;
        float gmm  = bn[oc];
        float beta = bn[M + oc];
        float mean = bn[2 * M + oc];
        float var  = bn[3 * M + oc];
        float s = gmm * rsqrtf(var + EPSF);
        float t = (bias[oc] - mean) * s + beta;
#pragma unroll
        for (int j = 0; j < 8; j++) {
            int jgg = j0 + tx + 16 * j;
            int bb = jgg / NPIX, nn = jgg - bb * NPIX;
            g_qkv[(size_t)bb * (QKVC * NPIX) + (size_t)(choff + oc) * NPIX + nn]
                = acc[i][j] * s + t;
        }
    }
}

// ------------------------------------------------------------------
// Depthwise 3x3 'SAME' conv on v + BN -> g_vloc. One block per (c, b) plane.
__global__ void __launch_bounds__(256) dwconv_kernel(
    const float* __restrict__ wvl, const float* __restrict__ bvl,
    const float* __restrict__ bn)
{
    int c = blockIdx.x, b = blockIdx.y;
    __shared__ float p[196];
    __shared__ float wsh[9];
    int tid = threadIdx.x;
    const float* vp = g_qkv + (size_t)b * (QKVC * NPIX) + (size_t)(512 + c) * NPIX;
    if (tid < 196) p[tid] = vp[tid];
    if (tid < 9)   wsh[tid] = wvl[c * 9 + tid];
    __syncthreads();
    if (tid < 196) {
        int y = tid / 14, x = tid - y * 14;
        float acc = 0.f;
#pragma unroll
        for (int dy = 0; dy < 3; dy++) {
            int yy = y + dy - 1;
            if (yy < 0 || yy > 13) continue;
#pragma unroll
            for (int dx = 0; dx < 3; dx++) {
                int xx = x + dx - 1;
                if (xx < 0 || xx > 13) continue;
                acc = fmaf(p[yy * 14 + xx], wsh[dy * 3 + dx], acc);
            }
        }
        float s = bn[c] * rsqrtf(bn[3072 + c] + EPSF);
        float t = (bvl[c] - bn[2048 + c]) * s + bn[1024 + c];
        g_vloc[(size_t)b * (DHC * NPIX) + (size_t)c * NPIX + tid] = acc * s + t;
    }
}

// ------------------------------------------------------------------
// Fused attention: logits + bias, talking-heads-1, softmax, talking-heads-2, AV.
// One block = (batch b, n-tile of 14 rows). 256 threads.
// smem (floats): qs 3584 | L 21952 | ab 1568 | ks/vs 7168 | th 144  = 34416 (137664 B)
#define ATTN_SMEM_FLOATS (3584 + 21952 + 1568 + 7168 + 144)

__global__ void __launch_bounds__(256) attn_kernel(
    const float* __restrict__ th1w, const float* __restrict__ th1b,
    const float* __restrict__ th2w, const float* __restrict__ th2b,
    const float* __restrict__ ab,   const int* __restrict__ bidx)
{
    extern __shared__ float sm[];
    float* qs   = sm;                     // [(h*14+nl)*32 + d]
    float* L    = sm + 3584;              // [(h*14+nl)*196 + m]
    float* abs_ = L + 21952;              // [h*196 + p]
    float* ks   = abs_ + 1568;            // k-tile [(c)*28 + mm]; reused as v-tile [e*29+mm]
    float* th   = ks + 7168;              // th1w(64) th1b(8) th2w(64) th2b(8)

    int tid = threadIdx.x;
    int b = blockIdx.y;
    int n0 = blockIdx.x * 14;
    const float* qbase = g_qkv + (size_t)b * (QKVC * NPIX);
    const float* kbase = qbase + 256 * NPIX;
    const float* vbase = qbase + 512 * NPIX;

    // load q tile (coalesced along n), bias table, talking-head weights
    for (int i = tid; i < 3584; i += 256) {
        int c = i / 14, nl = i - c * 14;
        qs[((c >> 5) * 14 + nl) * 32 + (c & 31)] = qbase[(size_t)c * NPIX + n0 + nl];
    }
    for (int i = tid; i < 1568; i += 256) abs_[i] = ab[i];
    if (tid < 64)       th[tid] = th1w[tid];
    else if (tid < 72)  th[tid] = th1b[tid - 64];
    else if (tid < 136) th[tid] = th2w[tid - 72];
    else if (tid < 144) th[tid] = th2b[tid - 136];
    __syncthreads();

    // stage q row into registers: thread -> (h, nl, half of m-subtile)
    float qreg[32];
    int h = 0, nl = 0, half = 0;
    bool active = tid < 224;
    if (active) {
        int pair = tid >> 1;
        h = pair / 14; nl = pair - h * 14; half = tid & 1;
#pragma unroll
        for (int d = 0; d < 32; d++) qreg[d] = qs[(h * 14 + nl) * 32 + d];
    }

    // ---- logits: s*SCALE + ab[h, bidx[n,m]] ----
    for (int mt = 0; mt < 7; mt++) {
        int m0 = mt * 28;
        __syncthreads();
        for (int i = tid; i < 7168; i += 256) {
            int c = i / 28, mm = i - c * 28;
            ks[i] = kbase[(size_t)c * NPIX + m0 + mm];
        }
        __syncthreads();
        if (active) {
            const float* kcol = ks + (h * 32) * 28;
            const int* brow = bidx + (size_t)(n0 + nl) * NPIX;
#pragma unroll
            for (int jm = 0; jm < 14; jm++) {
                int mm = half * 14 + jm;
                float s = 0.f;
#pragma unroll
                for (int d = 0; d < 32; d++)
                    s = fmaf(qreg[d], kcol[d * 28 + mm], s);
                int m = m0 + mm;
                L[(h * 14 + nl) * 196 + m] = s * SCALEF + abs_[h * 196 + brow[m]];
            }
        }
    }
    __syncthreads();

    // ---- talking-heads 1 (per (n,m) in-place head mix; race-free) ----
    for (int idx = tid; idx < 2744; idx += 256) {
        int n_ = idx / 196, m = idx - n_ * 196;
        float v[8], o_[8];
#pragma unroll
        for (int hh = 0; hh < 8; hh++) v[hh] = L[(hh * 14 + n_) * 196 + m];
#pragma unroll
        for (int oo = 0; oo < 8; oo++) {
            float s = th[64 + oo];
#pragma unroll
            for (int hh = 0; hh < 8; hh++) s = fmaf(th[oo * 8 + hh], v[hh], s);
            o_[oo] = s;
        }
#pragma unroll
        for (int oo = 0; oo < 8; oo++) L[(oo * 14 + n_) * 196 + m] = o_[oo];
    }
    __syncthreads();

    // ---- softmax over m (warp w owns head o = w) ----
    {
        int w = tid >> 5, lane = tid & 31;
        for (int r = 0; r < 14; r++) {
            float* row = L + (w * 14 + r) * 196;
            float mx = -1e30f;
            for (int m = lane; m < 196; m += 32) mx = fmaxf(mx, row[m]);
#pragma unroll
            for (int off = 16; off > 0; off >>= 1)
                mx = fmaxf(mx, __shfl_xor_sync(0xffffffffu, mx, off));
            float sum = 0.f;
            for (int m = lane; m < 196; m += 32) {
                float e = __expf(row[m] - mx);
                row[m] = e; sum += e;
            }
#pragma unroll
            for (int off = 16; off > 0; off >>= 1)
                sum += __shfl_xor_sync(0xffffffffu, sum, off);
            float inv = 1.f / sum;
            for (int m = lane; m < 196; m += 32) row[m] *= inv;
        }
    }
    __syncthreads();

    // ---- talking-heads 2 ----
    for (int idx = tid; idx < 2744; idx += 256) {
        int n_ = idx / 196, m = idx - n_ * 196;
        float v[8], o_[8];
#pragma unroll
        for (int hh = 0; hh < 8; hh++) v[hh] = L[(hh * 14 + n_) * 196 + m];
#pragma unroll
        for (int oo = 0; oo < 8; oo++) {
            float s = th[136 + oo];
#pragma unroll
            for (int hh = 0; hh < 8; hh++) s = fmaf(th[72 + oo * 8 + hh], v[hh], s);
            o_[oo] = s;
        }
#pragma unroll
        for (int oo = 0; oo < 8; oo++) L[(oo * 14 + n_) * 196 + m] = o_[oo];
    }
    __syncthreads();

    // ---- AV: out[o, n, e] = sum_m P[o,n,m] * v[b, o*128+e, m] ----
    {
        int e = tid & 127, g = tid >> 7;   // thread owns (e, 7 n-rows)
        float* vs = ks;                    // reuse: [e*29 + mm], 128*29 = 3712 floats
        for (int o = 0; o < 8; o++) {
            float acc[7];
#pragma unroll
            for (int j = 0; j < 7; j++) acc[j] = 0.f;
            for (int mt = 0; mt < 7; mt++) {
                int m0 = mt * 28;
                __syncthreads();
                for (int i = tid; i < 3584; i += 256) {
                    int ee = i / 28, mm = i - ee * 28;
                    vs[ee * 29 + mm] = vbase[(size_t)(o * 128 + ee) * NPIX + m0 + mm];
                }
                __syncthreads();
                const float* lbase = L + (o * 14 + g * 7) * 196 + m0;
#pragma unroll
                for (int mm = 0; mm < 28; mm++) {
                    float vv = vs[e * 29 + mm];
#pragma unroll
                    for (int j = 0; j < 7; j++)
                        acc[j] = fmaf(lbase[j * 196 + mm], vv, acc[j]);
                }
            }
            float* obase = g_att + (size_t)b * (DHC * NPIX)
                         + (size_t)(o * 128 + e) * NPIX + n0 + g * 7;
#pragma unroll
            for (int j = 0; j < 7; j++) obase[j] = acc[j];
        }
    }
}

// ------------------------------------------------------------------
// Projection GEMM: out = BN( wp[384,1024] @ relu(g_att + g_vloc) + bp )
__global__ void __launch_bounds__(256) proj_gemm_kernel(
    const float* __restrict__ W, const float* __restrict__ bias,
    const float* __restrict__ bn, float* __restrict__ out)
{
    const int K = 1024, M = 384;
    __shared__ float As[16][129];
    __shared__ float Bs[16][128];

    int tid = threadIdx.x;
    int tx = tid & 15, ty = tid >> 4;
    int m0 = blockIdx.y * 128;
    int j0 = blockIdx.x * 128;

    int jl = tid & 127;
    int kb = tid >> 7;
    int jg = j0 + jl;
    int bcol = jg / NPIX;
    int ncol = jg - bcol * NPIX;
    const float* abase = g_att  + (size_t)bcol * (DHC * NPIX) + ncol;
    const float* lbase = g_vloc + (size_t)bcol * (DHC * NPIX) + ncol;

    int akk = tid & 15, am0 = tid >> 4;
    const float* wptr = W + (size_t)(m0 + am0) * K + akk;

    float acc[8][8];
#pragma unroll
    for (int i = 0; i < 8; i++)
#pragma unroll
        for (int j = 0; j < 8; j++) acc[i][j] = 0.f;

    for (int k0 = 0; k0 < K; k0 += 16) {
#pragma unroll
        for (int i = 0; i < 8; i++)
            As[akk][am0 + 16 * i] = wptr[(size_t)(16 * i) * K + k0];
#pragma unroll
        for (int i = 0; i < 8; i++) {
            int kk = kb + 2 * i;
            size_t off = (size_t)(k0 + kk) * NPIX;
            Bs[kk][jl] = fmaxf(abase[off] + lbase[off], 0.f);
        }
        __syncthreads();
#pragma unroll
        for (int kk = 0; kk < 16; kk++) {
            float a[8], bv[8];
#pragma unroll
            for (int i = 0; i < 8; i++) a[i] = As[kk][ty + 16 * i];
#pragma unroll
            for (int j = 0; j < 8; j++) bv[j] = Bs[kk][tx + 16 * j];
#pragma unroll
            for (int i = 0; i < 8; i++)
#pragma unroll
                for (int j = 0; j < 8; j++)
                    acc[i][j] = fmaf(a[i], bv[j], acc[i][j]);
        }
        __syncthreads();
    }

#pragma unroll
    for (int i = 0; i < 8; i++) {
        int oc = m0 + ty + 16 * i;
        float gmm  = bn[oc];
        float beta = bn[M + oc];
        float mean = bn[2 * M + oc];
        float var  = bn[3 * M + oc];
        float s = gmm * rsqrtf(var + EPSF);
        float t = (bias[oc] - mean) * s + beta;
#pragma unroll
        for (int j = 0; j < 8; j++) {
            int jgg = j0 + tx + 16 * j;
            int bb = jgg / NPIX, nn = jgg - bb * NPIX;
            out[(size_t)bb * (384 * NPIX) + (size_t)oc * NPIX + nn] = acc[i][j] * s + t;
        }
    }
}

// ------------------------------------------------------------------
extern "C" void kernel_launch(void* const* d_in, const int* in_sizes, int n_in,
                              void* d_out, int out_size)
{
    const float* x    = (const float*)d_in[0];
    const float* wq   = (const float*)d_in[1];
    const float* bq   = (const float*)d_in[2];
    const float* bnq  = (const float*)d_in[3];
    const float* wk   = (const float*)d_in[4];
    const float* bk   = (const float*)d_in[5];
    const float* bnk  = (const float*)d_in[6];
    const float* wv   = (const float*)d_in[7];
    const float* bv   = (const float*)d_in[8];
    const float* bnv  = (const float*)d_in[9];
    const float* wvl  = (const float*)d_in[10];
    const float* bvl  = (const float*)d_in[11];
    const float* bnvl = (const float*)d_in[12];
    const float* th1w = (const float*)d_in[13];
    const float* th1b = (const float*)d_in[14];
    const float* th2w = (const float*)d_in[15];
    const float* th2b = (const float*)d_in[16];
    const float* wp   = (const float*)d_in[17];
    const float* bp   = (const float*)d_in[18];
    const float* bnp  = (const float*)d_in[19];
    const float* ab   = (const float*)d_in[20];
    const int*   bidx = (const int*)d_in[21];
    float* out = (float*)d_out;

    const int smem_bytes = ATTN_SMEM_FLOATS * (int)sizeof(float);
    cudaFuncSetAttribute(attn_kernel,
                         cudaFuncAttributeMaxDynamicSharedMemorySize, smem_bytes);

    // q, k, v channel GEMMs (fused BN)
    qkv_gemm_kernel<<<dim3(98, 2), 256>>>(wq, x, bq, bnq, 256, 0);
    qkv_gemm_kernel<<<dim3(98, 2), 256>>>(wk, x, bk, bnk, 256, 256);
    qkv_gemm_kernel<<<dim3(98, 8), 256>>>(wv, x, bv, bnv, 1024, 512);

    // depthwise 3x3 + BN on v
    dwconv_kernel<<<dim3(1024, 64), 256>>>(wvl, bvl, bnvl);

    // fused attention
    attn_kernel<<<dim3(14, 64), 256, smem_bytes>>>(th1w, th1b, th2w, th2b, ab, bidx);

    // relu(att + v_local) -> projection GEMM -> BN
    proj_gemm_kernel<<<dim3(98, 3), 256>>>(wp, bp, bnp, out);
}

// round 3
// speedup vs baseline: 1.1470x; 1.1470x over previous
#include <cuda_runtime.h>
#include <cuda_bf16.h>
#include <math.h>
#include <stdint.h>

#define EPSF 1e-5f
#define SCALEF 0.17677669529663687f

#define NB   64
#define NPIX 196
#define QKVC 1536
#define DHC  1024
#define NCOL 12544   // 64*196

// ------------------------------------------------------------------
// scratch (no cudaMalloc allowed)
__device__ float g_qkv [NB * QKVC * NPIX];   // [b][1536][196]; q@0, k@256, v@512
__device__ float g_vloc[NB * DHC * NPIX];    // [b][1024][196]
__device__ float g_att [NB * DHC * NPIX];    // [b][1024][196]

__device__ __align__(16) __nv_bfloat16 g_xt_hi[NCOL * 384];   // [j][k]
__device__ __align__(16) __nv_bfloat16 g_xt_lo[NCOL * 384];
__device__ __align__(16) __nv_bfloat16 g_pt_hi[NCOL * 1024];  // [j][k]
__device__ __align__(16) __nv_bfloat16 g_pt_lo[NCOL * 1024];
__device__ __align__(16) __nv_bfloat16 g_wqkv_hi[1536 * 384]; // [m][k]
__device__ __align__(16) __nv_bfloat16 g_wqkv_lo[1536 * 384];
__device__ __align__(16) __nv_bfloat16 g_wp_hi[384 * 1024];
__device__ __align__(16) __nv_bfloat16 g_wp_lo[384 * 1024];
__device__ float g_s[1920];   // folded BN scale: [0:1536) qkv, [1536:1920) proj
__device__ float g_t[1920];   // folded BN shift

// ------------------------------------------------------------------
static __device__ __forceinline__ uint32_t s2u(const void* p) {
    uint32_t a;
    asm("{ .reg .u64 t; cvta.to.shared.u64 t, %1; cvt.u32.u64 %0, t; }"
        : "=r"(a) : "l"(p));
    return a;
}

static __device__ __forceinline__ void ldmat_x4(
    uint32_t& r0, uint32_t& r1, uint32_t& r2, uint32_t& r3, uint32_t addr)
{
    asm volatile("ldmatrix.sync.aligned.m8n8.x4.shared.b16 {%0,%1,%2,%3}, [%4];"
                 : "=r"(r0), "=r"(r1), "=r"(r2), "=r"(r3) : "r"(addr));
}

static __device__ __forceinline__ void mma_bf16(
    float& d0, float& d1, float& d2, float& d3,
    uint32_t a0, uint32_t a1, uint32_t a2, uint32_t a3,
    uint32_t b0, uint32_t b1)
{
    asm volatile(
        "mma.sync.aligned.m16n8k16.row.col.f32.bf16.bf16.f32 "
        "{%0,%1,%2,%3}, {%4,%5,%6,%7}, {%8,%9}, {%0,%1,%2,%3};"
        : "+f"(d0), "+f"(d1), "+f"(d2), "+f"(d3)
        : "r"(a0), "r"(a1), "r"(a2), "r"(a3), "r"(b0), "r"(b1));
}

// ------------------------------------------------------------------
// Prep: fold BN into (s,t) per output channel; split weights into bf16 hi/lo
__global__ void __launch_bounds__(256) prep_kernel(
    const float* __restrict__ wq, const float* __restrict__ wk,
    const float* __restrict__ wv, const float* __restrict__ wp,
    const float* __restrict__ bq, const float* __restrict__ bk,
    const float* __restrict__ bv, const float* __restrict__ bp,
    const float* __restrict__ bnq, const float* __restrict__ bnk,
    const float* __restrict__ bnv, const float* __restrict__ bnp)
{
    int idx = blockIdx.x * 256 + threadIdx.x;
    int stride = gridDim.x * 256;

    for (int i = idx; i < 1536 * 384; i += stride) {
        int m = i / 384;
        float w = (m < 256) ? wq[i]
                : (m < 512) ? wk[i - 256 * 384]
                            : wv[i - 512 * 384];
        __nv_bfloat16 h = __float2bfloat16(w);
        g_wqkv_hi[i] = h;
        g_wqkv_lo[i] = __float2bfloat16(w - __bfloat162float(h));
    }
    for (int i = idx; i < 384 * 1024; i += stride) {
        float w = wp[i];
        __nv_bfloat16 h = __float2bfloat16(w);
        g_wp_hi[i] = h;
        g_wp_lo[i] = __float2bfloat16(w - __bfloat162float(h));
    }
    if (idx < 1920) {
        const float* bn; const float* bias; int c; int C;
        if (idx < 256)       { bn = bnq; bias = bq; c = idx;        C = 256; }
        else if (idx < 512)  { bn = bnk; bias = bk; c = idx - 256;  C = 256; }
        else if (idx < 1536) { bn = bnv; bias = bv; c = idx - 512;  C = 1024; }
        else                 { bn = bnp; bias = bp; c = idx - 1536; C = 384; }
        float s = bn[c] * rsqrtf(bn[3 * C + c] + EPSF);
        g_s[idx] = s;
        g_t[idx] = (bias[c] - bn[2 * C + c]) * s + bn[C + c];
    }
}

// ------------------------------------------------------------------
// Transpose+split x: [b][384][196] -> Xt[j=b*196+n][k=c] bf16 hi/lo
__global__ void __launch_bounds__(256) xt_cvt_kernel(const float* __restrict__ X)
{
    __shared__ float t[32][29];
    int b = blockIdx.z, c0 = blockIdx.y * 32, n0 = blockIdx.x * 28;
    int tid = threadIdx.x;
    const float* src = X + ((size_t)b * 384 + c0) * 196 + n0;
    for (int i = tid; i < 32 * 28; i += 256) {
        int ci = i / 28, nj = i - ci * 28;
        t[ci][nj] = src[(size_t)ci * 196 + nj];
    }
    __syncthreads();
    for (int i = tid; i < 32 * 28; i += 256) {
        int nj = i >> 5, ci = i & 31;
        float v = t[ci][nj];
        __nv_bfloat16 h = __float2bfloat16(v);
        size_t o = ((size_t)(b * 196 + n0 + nj)) * 384 + c0 + ci;
        g_xt_hi[o] = h;
        g_xt_lo[o] = __float2bfloat16(v - __bfloat162float(h));
    }
}

// Transpose+split relu(g_att + g_vloc): -> Pt[j][k=c(1024)] bf16 hi/lo
__global__ void __launch_bounds__(256) pt_cvt_kernel()
{
    __shared__ float t[32][29];
    int b = blockIdx.z, c0 = blockIdx.y * 32, n0 = blockIdx.x * 28;
    int tid = threadIdx.x;
    const float* ap = g_att  + ((size_t)b * 1024 + c0) * 196 + n0;
    const float* lp = g_vloc + ((size_t)b * 1024 + c0) * 196 + n0;
    for (int i = tid; i < 32 * 28; i += 256) {
        int ci = i / 28, nj = i - ci * 28;
        size_t off = (size_t)ci * 196 + nj;
        t[ci][nj] = fmaxf(ap[off] + lp[off], 0.f);
    }
    __syncthreads();
    for (int i = tid; i < 32 * 28; i += 256) {
        int nj = i >> 5, ci = i & 31;
        float v = t[ci][nj];
        __nv_bfloat16 h = __float2bfloat16(v);
        size_t o = ((size_t)(b * 196 + n0 + nj)) * 1024 + c0 + ci;
        g_pt_hi[o] = h;
        g_pt_lo[o] = __float2bfloat16(v - __bfloat162float(h));
    }
}

// ------------------------------------------------------------------
// bf16 mma.sync GEMM with hi/lo error compensation (3 passes).
// D[m0..+127][j0..+127] = sum_k A[m][k]*B[j][k]; out = D*s[oc]+t[oc],
// written to [b][Cout][196] with j = b*196+n.
// 8 warps: 2(M) x 4(N); each warp 64x32 via m16n8k16 atoms.
// smem: A tile 128x64bf16 (SW128 swizzled, 16KB) + B tile (16KB) = 32KB.
#define GEMM_SMEM_BYTES 32768

__global__ void __launch_bounds__(256) gemm_mma_kernel(
    const __nv_bfloat16* __restrict__ Ahi, const __nv_bfloat16* __restrict__ Alo,
    const __nv_bfloat16* __restrict__ Bhi, const __nv_bfloat16* __restrict__ Blo,
    int K, const float* __restrict__ svec, const float* __restrict__ tvec,
    float* __restrict__ out, int Cout)
{
    extern __shared__ __align__(1024) char smem[];
    const uint32_t sb = s2u(smem);
    const int tid = threadIdx.x;
    const int wid = tid >> 5, lane = tid & 31;
    const int warp_m = wid & 1;        // 0..1 -> 64 rows each
    const int warp_n = wid >> 1;       // 0..3 -> 32 cols each
    const int m0 = blockIdx.y * 128;
    const int j0 = blockIdx.x * 128;

    float acc[4][4][4];
#pragma unroll
    for (int i = 0; i < 4; i++)
#pragma unroll
        for (int j = 0; j < 4; j++)
#pragma unroll
            for (int c = 0; c < 4; c++) acc[i][j][c] = 0.f;

    // ldmatrix address pieces (same pattern for A and B tiles):
    // matrix row-in-16 = lane&15, k-half (16B) = lane>>4
    const int lrow = lane & 15;
    const uint32_t lkoff = (uint32_t)((lane >> 4) << 4);

    const int nk = K >> 6;        // 64-wide k-chunks
    const int nch = 3 * nk;       // 3 compensation passes

    for (int ch = 0; ch < nch; ch++) {
        const int pass = ch / nk;
        const int kb = (ch - pass * nk) << 6;
        const __nv_bfloat16* Asel = (pass == 1) ? Alo : Ahi;
        const __nv_bfloat16* Bsel = (pass == 2) ? Blo : Bhi;

        if (ch) __syncthreads();
#pragma unroll
        for (int i = 0; i < 4; i++) {
            int q = tid + (i << 8);
            int row = q >> 3, k8 = q & 7;
            uint32_t off = (uint32_t)(row * 128 + k8 * 16);
            uint32_t sw = off ^ ((off >> 3) & 0x70);
            uint4 va = *(const uint4*)(Asel + (size_t)(m0 + row) * K + kb + (k8 << 3));
            *(uint4*)(smem + sw) = va;
            uint4 vb = *(const uint4*)(Bsel + (size_t)(j0 + row) * K + kb + (k8 << 3));
            *(uint4*)(smem + 16384 + sw) = vb;
        }
        __syncthreads();

#pragma unroll
        for (int ks = 0; ks < 4; ks++) {
            uint32_t a[4][4];
#pragma unroll
            for (int mt = 0; mt < 4; mt++) {
                uint32_t off = (uint32_t)((warp_m * 64 + mt * 16 + lrow) * 128)
                             + (uint32_t)(ks * 32) + lkoff;
                uint32_t sw = off ^ ((off >> 3) & 0x70);
                ldmat_x4(a[mt][0], a[mt][1], a[mt][2], a[mt][3], sb + sw);
            }
            uint32_t b[4][2];
#pragma unroll
            for (int p = 0; p < 2; p++) {
                uint32_t off = (uint32_t)((warp_n * 32 + p * 16 + lrow) * 128)
                             + (uint32_t)(ks * 32) + lkoff;
                uint32_t sw = off ^ ((off >> 3) & 0x70);
                uint32_t r0, r1, r2, r3;
                ldmat_x4(r0, r1, r2, r3, sb + 16384u + sw);
                b[p * 2 + 0][0] = r0; b[p * 2 + 1][0] = r1;
                b[p * 2 + 0][1] = r2; b[p * 2 + 1][1] = r3;
            }
#pragma unroll
            for (int mt = 0; mt < 4; mt++)
#pragma unroll
                for (int nt = 0; nt < 4; nt++)
                    mma_bf16(acc[mt][nt][0], acc[mt][nt][1],
                             acc[mt][nt][2], acc[mt][nt][3],
                             a[mt][0], a[mt][1], a[mt][2], a[mt][3],
                             b[nt][0], b[nt][1]);
        }
    }

    // epilogue: D[row=group(+8)][col=tig*2+{0,1}] per (mt, nt)
    const int group = lane >> 2, tig = lane & 3;
#pragma unroll
    for (int mt = 0; mt < 4; mt++) {
        int oc0 = m0 + warp_m * 64 + mt * 16 + group;
        int oc1 = oc0 + 8;
        float s0 = svec[oc0], t0 = tvec[oc0];
        float s1 = svec[oc1], t1 = tvec[oc1];
#pragma unroll
        for (int nt = 0; nt < 4; nt++) {
            int j = j0 + warp_n * 32 + nt * 8 + tig * 2;
            int b = j / 196, n = j - b * 196;
            float* p0 = out + ((size_t)b * Cout + oc0) * 196 + n;
            float* p1 = out + ((size_t)b * Cout + oc1) * 196 + n;
            p0[0] = acc[mt][nt][0] * s0 + t0;
            p0[1] = acc[mt][nt][1] * s0 + t0;
            p1[0] = acc[mt][nt][2] * s1 + t1;
            p1[1] = acc[mt][nt][3] * s1 + t1;
        }
    }
}

// ------------------------------------------------------------------
// Depthwise 3x3 'SAME' conv on v + BN -> g_vloc.
// One block per (b, group of 8 channels); fully coalesced loads/stores.
__global__ void __launch_bounds__(256) dwconv_kernel(
    const float* __restrict__ wvl, const float* __restrict__ bvl,
    const float* __restrict__ bn)
{
    int c0 = blockIdx.x * 8, b = blockIdx.y;
    __shared__ float p[8 * 196];
    __shared__ float wsh[72];
    __shared__ float cs[8], ct[8];
    int tid = threadIdx.x;
    const float* src = g_qkv + (size_t)b * (QKVC * NPIX) + (size_t)(512 + c0) * NPIX;
    for (int i = tid; i < 1568; i += 256) p[i] = src[i];
    if (tid < 72) wsh[tid] = wvl[c0 * 9 + tid];
    if (tid < 8) {
        int c = c0 + tid;
        float s = bn[c] * rsqrtf(bn[3072 + c] + EPSF);
        cs[tid] = s;
        ct[tid] = (bvl[c] - bn[2048 + c]) * s + bn[1024 + c];
    }
    __syncthreads();
    float* dst = g_vloc + (size_t)b * (DHC * NPIX) + (size_t)c0 * NPIX;
    for (int i = tid; i < 1568; i += 256) {
        int c = i / 196, pix = i - c * 196;
        int y = pix / 14, x = pix - y * 14;
        const float* pc = p + c * 196;
        const float* w = wsh + c * 9;
        float acc = 0.f;
#pragma unroll
        for (int dy = 0; dy < 3; dy++) {
            int yy = y + dy - 1;
            if (yy < 0 || yy > 13) continue;
#pragma unroll
            for (int dx = 0; dx < 3; dx++) {
                int xx = x + dx - 1;
                if (xx < 0 || xx > 13) continue;
                acc = fmaf(pc[yy * 14 + xx], w[dy * 3 + dx], acc);
            }
        }
        dst[i] = acc * cs[c] + ct[c];
    }
}

// ------------------------------------------------------------------
// Fused attention (unchanged from passing R1 version).
#define ATTN_SMEM_FLOATS (3584 + 21952 + 1568 + 7168 + 144)

__global__ void __launch_bounds__(256) attn_kernel(
    const float* __restrict__ th1w, const float* __restrict__ th1b,
    const float* __restrict__ th2w, const float* __restrict__ th2b,
    const float* __restrict__ ab,   const int* __restrict__ bidx)
{
    extern __shared__ float sm[];
    float* qs   = sm;
    float* L    = sm + 3584;
    float* abs_ = L + 21952;
    float* ks   = abs_ + 1568;
    float* th   = ks + 7168;

    int tid = threadIdx.x;
    int b = blockIdx.y;
    int n0 = blockIdx.x * 14;
    const float* qbase = g_qkv + (size_t)b * (QKVC * NPIX);
    const float* kbase = qbase + 256 * NPIX;
    const float* vbase = qbase + 512 * NPIX;

    for (int i = tid; i < 3584; i += 256) {
        int c = i / 14, nl = i - c * 14;
        qs[((c >> 5) * 14 + nl) * 32 + (c & 31)] = qbase[(size_t)c * NPIX + n0 + nl];
    }
    for (int i = tid; i < 1568; i += 256) abs_[i] = ab[i];
    if (tid < 64)       th[tid] = th1w[tid];
    else if (tid < 72)  th[tid] = th1b[tid - 64];
    else if (tid < 136) th[tid] = th2w[tid - 72];
    else if (tid < 144) th[tid] = th2b[tid - 136];
    __syncthreads();

    float qreg[32];
    int h = 0, nl = 0, half = 0;
    bool active = tid < 224;
    if (active) {
        int pair = tid >> 1;
        h = pair / 14; nl = pair - h * 14; half = tid & 1;
#pragma unroll
        for (int d = 0; d < 32; d++) qreg[d] = qs[(h * 14 + nl) * 32 + d];
    }

    for (int mt = 0; mt < 7; mt++) {
        int m0 = mt * 28;
        __syncthreads();
        for (int i = tid; i < 7168; i += 256) {
            int c = i / 28, mm = i - c * 28;
            ks[i] = kbase[(size_t)c * NPIX + m0 + mm];
        }
        __syncthreads();
        if (active) {
            const float* kcol = ks + (h * 32) * 28;
            const int* brow = bidx + (size_t)(n0 + nl) * NPIX;
#pragma unroll
            for (int jm = 0; jm < 14; jm++) {
                int mm = half * 14 + jm;
                float s = 0.f;
#pragma unroll
                for (int d = 0; d < 32; d++)
                    s = fmaf(qreg[d], kcol[d * 28 + mm], s);
                int m = m0 + mm;
                L[(h * 14 + nl) * 196 + m] = s * SCALEF + abs_[h * 196 + brow[m]];
            }
        }
    }
    __syncthreads();

    for (int idx = tid; idx < 2744; idx += 256) {
        int n_ = idx / 196, m = idx - n_ * 196;
        float v[8], o_[8];
#pragma unroll
        for (int hh = 0; hh < 8; hh++) v[hh] = L[(hh * 14 + n_) * 196 + m];
#pragma unroll
        for (int oo = 0; oo < 8; oo++) {
            float s = th[64 + oo];
#pragma unroll
            for (int hh = 0; hh < 8; hh++) s = fmaf(th[oo * 8 + hh], v[hh], s);
            o_[oo] = s;
        }
#pragma unroll
        for (int oo = 0; oo < 8; oo++) L[(oo * 14 + n_) * 196 + m] = o_[oo];
    }
    __syncthreads();

    {
        int w = tid >> 5, lane = tid & 31;
        for (int r = 0; r < 14; r++) {
            float* row = L + (w * 14 + r) * 196;
            float mx = -1e30f;
            for (int m = lane; m < 196; m += 32) mx = fmaxf(mx, row[m]);
#pragma unroll
            for (int off = 16; off > 0; off >>= 1)
                mx = fmaxf(mx, __shfl_xor_sync(0xffffffffu, mx, off));
            float sum = 0.f;
            for (int m = lane; m < 196; m += 32) {
                float e = __expf(row[m] - mx);
                row[m] = e; sum += e;
            }
#pragma unroll
            for (int off = 16; off > 0; off >>= 1)
                sum += __shfl_xor_sync(0xffffffffu, sum, off);
            float inv = 1.f / sum;
            for (int m = lane; m < 196; m += 32) row[m] *= inv;
        }
    }
    __syncthreads();

    for (int idx = tid; idx < 2744; idx += 256) {
        int n_ = idx / 196, m = idx - n_ * 196;
        float v[8], o_[8];
#pragma unroll
        for (int hh = 0; hh < 8; hh++) v[hh] = L[(hh * 14 + n_) * 196 + m];
#pragma unroll
        for (int oo = 0; oo < 8; oo++) {
            float s = th[136 + oo];
#pragma unroll
            for (int hh = 0; hh < 8; hh++) s = fmaf(th[72 + oo * 8 + hh], v[hh], s);
            o_[oo] = s;
        }
#pragma unroll
        for (int oo = 0; oo < 8; oo++) L[(oo * 14 + n_) * 196 + m] = o_[oo];
    }
    __syncthreads();

    {
        int e = tid & 127, g = tid >> 7;
        float* vs = ks;
        for (int o = 0; o < 8; o++) {
            float acc[7];
#pragma unroll
            for (int j = 0; j < 7; j++) acc[j] = 0.f;
            for (int mt = 0; mt < 7; mt++) {
                int m0 = mt * 28;
                __syncthreads();
                for (int i = tid; i < 3584; i += 256) {
                    int ee = i / 28, mm = i - ee * 28;
                    vs[ee * 29 + mm] = vbase[(size_t)(o * 128 + ee) * NPIX + m0 + mm];
                }
                __syncthreads();
                const float* lbase = L + (o * 14 + g * 7) * 196 + m0;
#pragma unroll
                for (int mm = 0; mm < 28; mm++) {
                    float vv = vs[e * 29 + mm];
#pragma unroll
                    for (int j = 0; j < 7; j++)
                        acc[j] = fmaf(lbase[j * 196 + mm], vv, acc[j]);
                }
            }
            float* obase = g_att + (size_t)b * (DHC * NPIX)
                         + (size_t)(o * 128 + e) * NPIX + n0 + g * 7;
#pragma unroll
            for (int j = 0; j < 7; j++) obase[j] = acc[j];
        }
    }
}

// ------------------------------------------------------------------
extern "C" void kernel_launch(void* const* d_in, const int* in_sizes, int n_in,
                              void* d_out, int out_size)
{
    const float* x    = (const float*)d_in[0];
    const float* wq   = (const float*)d_in[1];
    const float* bq   = (const float*)d_in[2];
    const float* bnq  = (const float*)d_in[3];
    const float* wk   = (const float*)d_in[4];
    const float* bk   = (const float*)d_in[5];
    const float* bnk  = (const float*)d_in[6];
    const float* wv   = (const float*)d_in[7];
    const float* bv   = (const float*)d_in[8];
    const float* bnv  = (const float*)d_in[9];
    const float* wvl  = (const float*)d_in[10];
    const float* bvl  = (const float*)d_in[11];
    const float* bnvl = (const float*)d_in[12];
    const float* th1w = (const float*)d_in[13];
    const float* th1b = (const float*)d_in[14];
    const float* th2w = (const float*)d_in[15];
    const float* th2b = (const float*)d_in[16];
    const float* wp   = (const float*)d_in[17];
    const float* bp   = (const float*)d_in[18];
    const float* bnp  = (const float*)d_in[19];
    const float* ab   = (const float*)d_in[20];
    const int*   bidx = (const int*)d_in[21];
    float* out = (float*)d_out;

    const int attn_smem = ATTN_SMEM_FLOATS * (int)sizeof(float);
    cudaFuncSetAttribute(attn_kernel,
                         cudaFuncAttributeMaxDynamicSharedMemorySize, attn_smem);
    cudaFuncSetAttribute(gemm_mma_kernel,
                         cudaFuncAttributeMaxDynamicSharedMemorySize, GEMM_SMEM_BYTES);

    __nv_bfloat16 *wqkv_hi, *wqkv_lo, *xt_hi, *xt_lo, *wp_hi, *wp_lo, *pt_hi, *pt_lo;
    float *sv, *tv, *qkv_out;
    cudaGetSymbolAddress((void**)&wqkv_hi, g_wqkv_hi);
    cudaGetSymbolAddress((void**)&wqkv_lo, g_wqkv_lo);
    cudaGetSymbolAddress((void**)&xt_hi, g_xt_hi);
    cudaGetSymbolAddress((void**)&xt_lo, g_xt_lo);
    cudaGetSymbolAddress((void**)&wp_hi, g_wp_hi);
    cudaGetSymbolAddress((void**)&wp_lo, g_wp_lo);
    cudaGetSymbolAddress((void**)&pt_hi, g_pt_hi);
    cudaGetSymbolAddress((void**)&pt_lo, g_pt_lo);
    cudaGetSymbolAddress((void**)&sv, g_s);
    cudaGetSymbolAddress((void**)&tv, g_t);
    cudaGetSymbolAddress((void**)&qkv_out, g_qkv);

    // 1. fold BN + split weights
    prep_kernel<<<2304, 256>>>(wq, wk, wv, wp, bq, bk, bv, bp, bnq, bnk, bnv, bnp);
    // 2. transpose+split x
    xt_cvt_kernel<<<dim3(7, 12, 64), 256>>>(x);
    // 3. fused qkv GEMM on tensor cores (M=1536)
    gemm_mma_kernel<<<dim3(98, 12), 256, GEMM_SMEM_BYTES>>>(
        wqkv_hi, wqkv_lo, xt_hi, xt_lo, 384, sv, tv, qkv_out, 1536);
    // 4. depthwise conv + BN
    dwconv_kernel<<<dim3(128, 64), 256>>>(wvl, bvl, bnvl);
    // 5. fused attention
    attn_kernel<<<dim3(14, 64), 256, attn_smem>>>(th1w, th1b, th2w, th2b, ab, bidx);
    // 6. transpose+split relu(att + v_local)
    pt_cvt_kernel<<<dim3(7, 32, 64), 256>>>();
    // 7. projection GEMM on tensor cores
    gemm_mma_kernel<<<dim3(98, 3), 256, GEMM_SMEM_BYTES>>>(
        wp_hi, wp_lo, pt_hi, pt_lo, 1024, sv + 1536, tv + 1536, out, 384);
}

// round 5
// speedup vs baseline: 1.2314x; 1.0736x over previous
#include <cuda_runtime.h>
#include <cuda_bf16.h>
#include <math.h>
#include <stdint.h>

#define EPSF 1e-5f
#define SCALEF 0.17677669529663687f

#define NB   64
#define NPIX 196
#define QKVC 1536
#define DHC  1024
#define NCOL 12544   // 64*196

// ------------------------------------------------------------------
// scratch (no cudaMalloc allowed)
__device__ float g_qkv [NB * QKVC * NPIX];   // [b][1536][196]; q@0, k@256, v@512
__device__ float g_vloc[NB * DHC * NPIX];    // [b][1024][196]
__device__ float g_att [NB * DHC * NPIX];    // [b][1024][196]

__device__ __align__(16) __nv_bfloat16 g_xt_hi[NCOL * 384];   // [j][k]
__device__ __align__(16) __nv_bfloat16 g_xt_lo[NCOL * 384];
__device__ __align__(16) __nv_bfloat16 g_pt_hi[NCOL * 1024];  // [j][k]
__device__ __align__(16) __nv_bfloat16 g_pt_lo[NCOL * 1024];
__device__ __align__(16) __nv_bfloat16 g_wqkv_hi[1536 * 384]; // [m][k]
__device__ __align__(16) __nv_bfloat16 g_wqkv_lo[1536 * 384];
__device__ __align__(16) __nv_bfloat16 g_wp_hi[384 * 1024];
__device__ __align__(16) __nv_bfloat16 g_wp_lo[384 * 1024];
__device__ float g_s[1920];   // folded BN scale: [0:1536) qkv, [1536:1920) proj
__device__ float g_t[1920];   // folded BN shift

// ------------------------------------------------------------------
static __device__ __forceinline__ uint32_t s2u(const void* p) {
    uint32_t a;
    asm("{ .reg .u64 t; cvta.to.shared.u64 t, %1; cvt.u32.u64 %0, t; }"
        : "=r"(a) : "l"(p));
    return a;
}

static __device__ __forceinline__ void cp_async16(uint32_t saddr, const void* gptr) {
    asm volatile("cp.async.cg.shared.global [%0], [%1], 16;"
                 :: "r"(saddr), "l"(gptr) : "memory");
}

static __device__ __forceinline__ void ldmat_x4(
    uint32_t& r0, uint32_t& r1, uint32_t& r2, uint32_t& r3, uint32_t addr)
{
    asm volatile("ldmatrix.sync.aligned.m8n8.x4.shared.b16 {%0,%1,%2,%3}, [%4];"
                 : "=r"(r0), "=r"(r1), "=r"(r2), "=r"(r3) : "r"(addr));
}

static __device__ __forceinline__ void mma_bf16(
    float& d0, float& d1, float& d2, float& d3,
    uint32_t a0, uint32_t a1, uint32_t a2, uint32_t a3,
    uint32_t b0, uint32_t b1)
{
    asm volatile(
        "mma.sync.aligned.m16n8k16.row.col.f32.bf16.bf16.f32 "
        "{%0,%1,%2,%3}, {%4,%5,%6,%7}, {%8,%9}, {%0,%1,%2,%3};"
        : "+f"(d0), "+f"(d1), "+f"(d2), "+f"(d3)
        : "r"(a0), "r"(a1), "r"(a2), "r"(a3), "r"(b0), "r"(b1));
}

// ------------------------------------------------------------------
// Prep: fold BN into (s,t) per output channel; split weights into bf16 hi/lo
__global__ void __launch_bounds__(256) prep_kernel(
    const float* __restrict__ wq, const float* __restrict__ wk,
    const float* __restrict__ wv, const float* __restrict__ wp,
    const float* __restrict__ bq, const float* __restrict__ bk,
    const float* __restrict__ bv, const float* __restrict__ bp,
    const float* __restrict__ bnq, const float* __restrict__ bnk,
    const float* __restrict__ bnv, const float* __restrict__ bnp)
{
    int idx = blockIdx.x * 256 + threadIdx.x;
    int stride = gridDim.x * 256;

    for (int i = idx; i < 1536 * 384; i += stride) {
        int m = i / 384;
        float w = (m < 256) ? wq[i]
                : (m < 512) ? wk[i - 256 * 384]
                            : wv[i - 512 * 384];
        __nv_bfloat16 h = __float2bfloat16(w);
        g_wqkv_hi[i] = h;
        g_wqkv_lo[i] = __float2bfloat16(w - __bfloat162float(h));
    }
    for (int i = idx; i < 384 * 1024; i += stride) {
        float w = wp[i];
        __nv_bfloat16 h = __float2bfloat16(w);
        g_wp_hi[i] = h;
        g_wp_lo[i] = __float2bfloat16(w - __bfloat162float(h));
    }
    if (idx < 1920) {
        const float* bn; const float* bias; int c; int C;
        if (idx < 256)       { bn = bnq; bias = bq; c = idx;        C = 256; }
        else if (idx < 512)  { bn = bnk; bias = bk; c = idx - 256;  C = 256; }
        else if (idx < 1536) { bn = bnv; bias = bv; c = idx - 512;  C = 1024; }
        else                 { bn = bnp; bias = bp; c = idx - 1536; C = 384; }
        float s = bn[c] * rsqrtf(bn[3 * C + c] + EPSF);
        g_s[idx] = s;
        g_t[idx] = (bias[c] - bn[2 * C + c]) * s + bn[C + c];
    }
}

// ------------------------------------------------------------------
// Transpose+split x: [b][384][196] -> Xt[j=b*196+n][k=c] bf16 hi/lo
__global__ void __launch_bounds__(256) xt_cvt_kernel(const float* __restrict__ X)
{
    __shared__ float t[32][29];
    int b = blockIdx.z, c0 = blockIdx.y * 32, n0 = blockIdx.x * 28;
    int tid = threadIdx.x;
    const float* src = X + ((size_t)b * 384 + c0) * 196 + n0;
    for (int i = tid; i < 32 * 28; i += 256) {
        int ci = i / 28, nj = i - ci * 28;
        t[ci][nj] = src[(size_t)ci * 196 + nj];
    }
    __syncthreads();
    for (int i = tid; i < 32 * 28; i += 256) {
        int nj = i >> 5, ci = i & 31;
        float v = t[ci][nj];
        __nv_bfloat16 h = __float2bfloat16(v);
        size_t o = ((size_t)(b * 196 + n0 + nj)) * 384 + c0 + ci;
        g_xt_hi[o] = h;
        g_xt_lo[o] = __float2bfloat16(v - __bfloat162float(h));
    }
}

// Transpose+split relu(g_att + g_vloc): -> Pt[j][k=c(1024)] bf16 hi/lo
__global__ void __launch_bounds__(256) pt_cvt_kernel()
{
    __shared__ float t[32][29];
    int b = blockIdx.z, c0 = blockIdx.y * 32, n0 = blockIdx.x * 28;
    int tid = threadIdx.x;
    const float* ap = g_att  + ((size_t)b * 1024 + c0) * 196 + n0;
    const float* lp = g_vloc + ((size_t)b * 1024 + c0) * 196 + n0;
    for (int i = tid; i < 32 * 28; i += 256) {
        int ci = i / 28, nj = i - ci * 28;
        size_t off = (size_t)ci * 196 + nj;
        t[ci][nj] = fmaxf(ap[off] + lp[off], 0.f);
    }
    __syncthreads();
    for (int i = tid; i < 32 * 28; i += 256) {
        int nj = i >> 5, ci = i & 31;
        float v = t[ci][nj];
        __nv_bfloat16 h = __float2bfloat16(v);
        size_t o = ((size_t)(b * 196 + n0 + nj)) * 1024 + c0 + ci;
        g_pt_hi[o] = h;
        g_pt_lo[o] = __float2bfloat16(v - __bfloat162float(h));
    }
}

// ------------------------------------------------------------------
// bf16 mma.sync GEMM, 3-term compensation fused per K-chunk:
//   D = Ahi*Bhi + Alo*Bhi + Ahi*Blo
// cp.async 2-stage pipeline; each tile loaded once per chunk.
// 8 warps: 2(M) x 4(N); each warp 64x32 via m16n8k16 atoms.
// smem per stage: Ahi 16K | Alo 16K | Bhi 16K | Blo 16K = 64K; 2 stages = 128K.
#define GEMM_STAGE_BYTES 65536
#define GEMM_SMEM_BYTES  (2 * GEMM_STAGE_BYTES)

__global__ void __launch_bounds__(256) gemm_mma_kernel(
    const __nv_bfloat16* __restrict__ Ahi, const __nv_bfloat16* __restrict__ Alo,
    const __nv_bfloat16* __restrict__ Bhi, const __nv_bfloat16* __restrict__ Blo,
    int K, const float* __restrict__ svec, const float* __restrict__ tvec,
    float* __restrict__ out, int Cout)
{
    extern __shared__ __align__(1024) char smem[];
    const uint32_t sb = s2u(smem);
    const int tid = threadIdx.x;
    const int wid = tid >> 5, lane = tid & 31;
    const int warp_m = wid & 1;        // 0..1 -> 64 rows each
    const int warp_n = wid >> 1;       // 0..3 -> 32 cols each
    const int m0 = blockIdx.y * 128;
    const int j0 = blockIdx.x * 128;
    const int nk = K >> 6;             // 64-wide k-chunks

    float acc[4][4][4];
#pragma unroll
    for (int i = 0; i < 4; i++)
#pragma unroll
        for (int j = 0; j < 4; j++)
#pragma unroll
            for (int c = 0; c < 4; c++) acc[i][j][c] = 0.f;

    const int lrow = lane & 15;
    const uint32_t lkoff = (uint32_t)((lane >> 4) << 4);

    auto issue = [&](int kb, uint32_t stage_off) {
#pragma unroll
        for (int i = 0; i < 4; i++) {
            int q = tid + (i << 8);
            int row = q >> 3, k8 = q & 7;
            uint32_t off = (uint32_t)(row * 128 + k8 * 16);
            uint32_t sw = off ^ ((off >> 3) & 0x70);
            size_t ga = (size_t)(m0 + row) * K + kb + (k8 << 3);
            size_t gb = (size_t)(j0 + row) * K + kb + (k8 << 3);
            cp_async16(sb + stage_off + sw,           Ahi + ga);
            cp_async16(sb + stage_off + 16384u + sw,  Alo + ga);
            cp_async16(sb + stage_off + 32768u + sw,  Bhi + gb);
            cp_async16(sb + stage_off + 49152u + sw,  Blo + gb);
        }
        asm volatile("cp.async.commit_group;" ::: "memory");
    };

    issue(0, 0u);
    if (nk > 1) issue(64, GEMM_STAGE_BYTES);

    for (int ch = 0; ch < nk; ch++) {
        if (ch + 1 < nk) asm volatile("cp.async.wait_group 1;" ::: "memory");
        else             asm volatile("cp.async.wait_group 0;" ::: "memory");
        __syncthreads();

        const uint32_t buf = (ch & 1) ? (uint32_t)GEMM_STAGE_BYTES : 0u;
#pragma unroll
        for (int ks = 0; ks < 4; ks++) {
            // B fragments (hi and lo)
            uint32_t bh[4][2], bl[4][2];
#pragma unroll
            for (int p = 0; p < 2; p++) {
                uint32_t off = (uint32_t)((warp_n * 32 + p * 16 + lrow) * 128)
                             + (uint32_t)(ks * 32) + lkoff;
                uint32_t sw = off ^ ((off >> 3) & 0x70);
                uint32_t r0, r1, r2, r3;
                ldmat_x4(r0, r1, r2, r3, sb + buf + 32768u + sw);
                bh[p * 2 + 0][0] = r0; bh[p * 2 + 1][0] = r1;
                bh[p * 2 + 0][1] = r2; bh[p * 2 + 1][1] = r3;
                ldmat_x4(r0, r1, r2, r3, sb + buf + 49152u + sw);
                bl[p * 2 + 0][0] = r0; bl[p * 2 + 1][0] = r1;
                bl[p * 2 + 0][1] = r2; bl[p * 2 + 1][1] = r3;
            }
#pragma unroll
            for (int mt = 0; mt < 4; mt++) {
                uint32_t off = (uint32_t)((warp_m * 64 + mt * 16 + lrow) * 128)
                             + (uint32_t)(ks * 32) + lkoff;
                uint32_t sw = off ^ ((off >> 3) & 0x70);
                uint32_t a0, a1, a2, a3;
                // hi*hi and hi*lo
                ldmat_x4(a0, a1, a2, a3, sb + buf + sw);
#pragma unroll
                for (int nt = 0; nt < 4; nt++)
                    mma_bf16(acc[mt][nt][0], acc[mt][nt][1],
                             acc[mt][nt][2], acc[mt][nt][3],
                             a0, a1, a2, a3, bh[nt][0], bh[nt][1]);
#pragma unroll
                for (int nt = 0; nt < 4; nt++)
                    mma_bf16(acc[mt][nt][0], acc[mt][nt][1],
                             acc[mt][nt][2], acc[mt][nt][3],
                             a0, a1, a2, a3, bl[nt][0], bl[nt][1]);
                // lo*hi
                ldmat_x4(a0, a1, a2, a3, sb + buf + 16384u + sw);
#pragma unroll
                for (int nt = 0; nt < 4; nt++)
                    mma_bf16(acc[mt][nt][0], acc[mt][nt][1],
                             acc[mt][nt][2], acc[mt][nt][3],
                             a0, a1, a2, a3, bh[nt][0], bh[nt][1]);
            }
        }

        if (ch + 2 < nk) {
            __syncthreads();
            issue((ch + 2) << 6, buf);
        }
    }

    // epilogue
    const int group = lane >> 2, tig = lane & 3;
#pragma unroll
    for (int mt = 0; mt < 4; mt++) {
        int oc0 = m0 + warp_m * 64 + mt * 16 + group;
        int oc1 = oc0 + 8;
        float s0 = svec[oc0], t0 = tvec[oc0];
        float s1 = svec[oc1], t1 = tvec[oc1];
#pragma unroll
        for (int nt = 0; nt < 4; nt++) {
            int j = j0 + warp_n * 32 + nt * 8 + tig * 2;
            int b = j / 196, n = j - b * 196;
            float* p0 = out + ((size_t)b * Cout + oc0) * 196 + n;
            float* p1 = out + ((size_t)b * Cout + oc1) * 196 + n;
            p0[0] = acc[mt][nt][0] * s0 + t0;
            p0[1] = acc[mt][nt][1] * s0 + t0;
            p1[0] = acc[mt][nt][2] * s1 + t1;
            p1[1] = acc[mt][nt][3] * s1 + t1;
        }
    }
}

// ------------------------------------------------------------------
// Depthwise 3x3 'SAME' conv on v + BN -> g_vloc.
__global__ void __launch_bounds__(256) dwconv_kernel(
    const float* __restrict__ wvl, const float* __restrict__ bvl,
    const float* __restrict__ bn)
{
    int c0 = blockIdx.x * 8, b = blockIdx.y;
    __shared__ float p[8 * 196];
    __shared__ float wsh[72];
    __shared__ float cs[8], ct[8];
    int tid = threadIdx.x;
    const float* src = g_qkv + (size_t)b * (QKVC * NPIX) + (size_t)(512 + c0) * NPIX;
    for (int i = tid; i < 1568; i += 256) p[i] = src[i];
    if (tid < 72) wsh[tid] = wvl[c0 * 9 + tid];
    if (tid < 8) {
        int c = c0 + tid;
        float s = bn[c] * rsqrtf(bn[3072 + c] + EPSF);
        cs[tid] = s;
        ct[tid] = (bvl[c] - bn[2048 + c]) * s + bn[1024 + c];
    }
    __syncthreads();
    float* dst = g_vloc + (size_t)b * (DHC * NPIX) + (size_t)c0 * NPIX;
    for (int i = tid; i < 1568; i += 256) {
        int c = i / 196, pix = i - c * 196;
        int y = pix / 14, x = pix - y * 14;
        const float* pc = p + c * 196;
        const float* w = wsh + c * 9;
        float acc = 0.f;
#pragma unroll
        for (int dy = 0; dy < 3; dy++) {
            int yy = y + dy - 1;
            if (yy < 0 || yy > 13) continue;
#pragma unroll
            for (int dx = 0; dx < 3; dx++) {
                int xx = x + dx - 1;
                if (xx < 0 || xx > 13) continue;
                acc = fmaf(pc[yy * 14 + xx], w[dy * 3 + dx], acc);
            }
        }
        dst[i] = acc * cs[c] + ct[c];
    }
}

// ------------------------------------------------------------------
// Fused attention (unchanged).
#define ATTN_SMEM_FLOATS (3584 + 21952 + 1568 + 7168 + 144)

__global__ void __launch_bounds__(256) attn_kernel(
    const float* __restrict__ th1w, const float* __restrict__ th1b,
    const float* __restrict__ th2w, const float* __restrict__ th2b,
    const float* __restrict__ ab,   const int* __restrict__ bidx)
{
    extern __shared__ float sm[];
    float* qs   = sm;
    float* L    = sm + 3584;
    float* abs_ = L + 21952;
    float* ks   = abs_ + 1568;
    float* th   = ks + 7168;

    int tid = threadIdx.x;
    int b = blockIdx.y;
    int n0 = blockIdx.x * 14;
    const float* qbase = g_qkv + (size_t)b * (QKVC * NPIX);
    const float* kbase = qbase + 256 * NPIX;
    const float* vbase = qbase + 512 * NPIX;

    for (int i = tid; i < 3584; i += 256) {
        int c = i / 14, nl = i - c * 14;
        qs[((c >> 5) * 14 + nl) * 32 + (c & 31)] = qbase[(size_t)c * NPIX + n0 + nl];
    }
    for (int i = tid; i < 1568; i += 256) abs_[i] = ab[i];
    if (tid < 64)       th[tid] = th1w[tid];
    else if (tid < 72)  th[tid] = th1b[tid - 64];
    else if (tid < 136) th[tid] = th2w[tid - 72];
    else if (tid < 144) th[tid] = th2b[tid - 136];
    __syncthreads();

    float qreg[32];
    int h = 0, nl = 0, half = 0;
    bool active = tid < 224;
    if (active) {
        int pair = tid >> 1;
        h = pair / 14; nl = pair - h * 14; half = tid & 1;
#pragma unroll
        for (int d = 0; d < 32; d++) qreg[d] = qs[(h * 14 + nl) * 32 + d];
    }

    for (int mt = 0; mt < 7; mt++) {
        int m0 = mt * 28;
        __syncthreads();
        for (int i = tid; i < 7168; i += 256) {
            int c = i / 28, mm = i - c * 28;
            ks[i] = kbase[(size_t)c * NPIX + m0 + mm];
        }
        __syncthreads();
        if (active) {
            const float* kcol = ks + (h * 32) * 28;
            const int* brow = bidx + (size_t)(n0 + nl) * NPIX;
#pragma unroll
            for (int jm = 0; jm < 14; jm++) {
                int mm = half * 14 + jm;
                float s = 0.f;
#pragma unroll
                for (int d = 0; d < 32; d++)
                    s = fmaf(qreg[d], kcol[d * 28 + mm], s);
                int m = m0 + mm;
                L[(h * 14 + nl) * 196 + m] = s * SCALEF + abs_[h * 196 + brow[m]];
            }
        }
    }
    __syncthreads();

    for (int idx = tid; idx < 2744; idx += 256) {
        int n_ = idx / 196, m = idx - n_ * 196;
        float v[8], o_[8];
#pragma unroll
        for (int hh = 0; hh < 8; hh++) v[hh] = L[(hh * 14 + n_) * 196 + m];
#pragma unroll
        for (int oo = 0; oo < 8; oo++) {
            float s = th[64 + oo];
#pragma unroll
            for (int hh = 0; hh < 8; hh++) s = fmaf(th[oo * 8 + hh], v[hh], s);
            o_[oo] = s;
        }
#pragma unroll
        for (int oo = 0; oo < 8; oo++) L[(oo * 14 + n_) * 196 + m] = o_[oo];
    }
    __syncthreads();

    {
        int w = tid >> 5, lane = tid & 31;
        for (int r = 0; r < 14; r++) {
            float* row = L + (w * 14 + r) * 196;
            float mx = -1e30f;
            for (int m = lane; m < 196; m += 32) mx = fmaxf(mx, row[m]);
#pragma unroll
            for (int off = 16; off > 0; off >>= 1)
                mx = fmaxf(mx, __shfl_xor_sync(0xffffffffu, mx, off));
            float sum = 0.f;
            for (int m = lane; m < 196; m += 32) {
                float e = __expf(row[m] - mx);
                row[m] = e; sum += e;
            }
#pragma unroll
            for (int off = 16; off > 0; off >>= 1)
                sum += __shfl_xor_sync(0xffffffffu, sum, off);
            float inv = 1.f / sum;
            for (int m = lane; m < 196; m += 32) row[m] *= inv;
        }
    }
    __syncthreads();

    for (int idx = tid; idx < 2744; idx += 256) {
        int n_ = idx / 196, m = idx - n_ * 196;
        float v[8], o_[8];
#pragma unroll
        for (int hh = 0; hh < 8; hh++) v[hh] = L[(hh * 14 + n_) * 196 + m];
#pragma unroll
        for (int oo = 0; oo < 8; oo++) {
            float s = th[136 + oo];
#pragma unroll
            for (int hh = 0; hh < 8; hh++) s = fmaf(th[72 + oo * 8 + hh], v[hh], s);
            o_[oo] = s;
        }
#pragma unroll
        for (int oo = 0; oo < 8; oo++) L[(oo * 14 + n_) * 196 + m] = o_[oo];
    }
    __syncthreads();

    {
        int e = tid & 127, g = tid >> 7;
        float* vs = ks;
        for (int o = 0; o < 8; o++) {
            float acc[7];
#pragma unroll
            for (int j = 0; j < 7; j++) acc[j] = 0.f;
            for (int mt = 0; mt < 7; mt++) {
                int m0 = mt * 28;
                __syncthreads();
                for (int i = tid; i < 3584; i += 256) {
                    int ee = i / 28, mm = i - ee * 28;
                    vs[ee * 29 + mm] = vbase[(size_t)(o * 128 + ee) * NPIX + m0 + mm];
                }
                __syncthreads();
                const float* lbase = L + (o * 14 + g * 7) * 196 + m0;
#pragma unroll
                for (int mm = 0; mm < 28; mm++) {
                    float vv = vs[e * 29 + mm];
#pragma unroll
                    for (int j = 0; j < 7; j++)
                        acc[j] = fmaf(lbase[j * 196 + mm], vv, acc[j]);
                }
            }
            float* obase = g_att + (size_t)b * (DHC * NPIX)
                         + (size_t)(o * 128 + e) * NPIX + n0 + g * 7;
#pragma unroll
            for (int j = 0; j < 7; j++) obase[j] = acc[j];
        }
    }
}

// ------------------------------------------------------------------
extern "C" void kernel_launch(void* const* d_in, const int* in_sizes, int n_in,
                              void* d_out, int out_size)
{
    const float* x    = (const float*)d_in[0];
    const float* wq   = (const float*)d_in[1];
    const float* bq   = (const float*)d_in[2];
    const float* bnq  = (const float*)d_in[3];
    const float* wk   = (const float*)d_in[4];
    const float* bk   = (const float*)d_in[5];
    const float* bnk  = (const float*)d_in[6];
    const float* wv   = (const float*)d_in[7];
    const float* bv   = (const float*)d_in[8];
    const float* bnv  = (const float*)d_in[9];
    const float* wvl  = (const float*)d_in[10];
    const float* bvl  = (const float*)d_in[11];
    const float* bnvl = (const float*)d_in[12];
    const float* th1w = (const float*)d_in[13];
    const float* th1b = (const float*)d_in[14];
    const float* th2w = (const float*)d_in[15];
    const float* th2b = (const float*)d_in[16];
    const float* wp   = (const float*)d_in[17];
    const float* bp   = (const float*)d_in[18];
    const float* bnp  = (const float*)d_in[19];
    const float* ab   = (const float*)d_in[20];
    const int*   bidx = (const int*)d_in[21];
    float* out = (float*)d_out;

    const int attn_smem = ATTN_SMEM_FLOATS * (int)sizeof(float);
    cudaFuncSetAttribute(attn_kernel,
                         cudaFuncAttributeMaxDynamicSharedMemorySize, attn_smem);
    cudaFuncSetAttribute(gemm_mma_kernel,
                         cudaFuncAttributeMaxDynamicSharedMemorySize, GEMM_SMEM_BYTES);

    __nv_bfloat16 *wqkv_hi, *wqkv_lo, *xt_hi, *xt_lo, *wp_hi, *wp_lo, *pt_hi, *pt_lo;
    float *sv, *tv, *qkv_out;
    cudaGetSymbolAddress((void**)&wqkv_hi, g_wqkv_hi);
    cudaGetSymbolAddress((void**)&wqkv_lo, g_wqkv_lo);
    cudaGetSymbolAddress((void**)&xt_hi, g_xt_hi);
    cudaGetSymbolAddress((void**)&xt_lo, g_xt_lo);
    cudaGetSymbolAddress((void**)&wp_hi, g_wp_hi);
    cudaGetSymbolAddress((void**)&wp_lo, g_wp_lo);
    cudaGetSymbolAddress((void**)&pt_hi, g_pt_hi);
    cudaGetSymbolAddress((void**)&pt_lo, g_pt_lo);
    cudaGetSymbolAddress((void**)&sv, g_s);
    cudaGetSymbolAddress((void**)&tv, g_t);
    cudaGetSymbolAddress((void**)&qkv_out, g_qkv);

    // 1. fold BN + split weights
    prep_kernel<<<2304, 256>>>(wq, wk, wv, wp, bq, bk, bv, bp, bnq, bnk, bnv, bnp);
    // 2. transpose+split x
    xt_cvt_kernel<<<dim3(7, 12, 64), 256>>>(x);
    // 3. fused qkv GEMM (M=1536, K=384)
    gemm_mma_kernel<<<dim3(98, 12), 256, GEMM_SMEM_BYTES>>>(
        wqkv_hi, wqkv_lo, xt_hi, xt_lo, 384, sv, tv, qkv_out, 1536);
    // 4. depthwise conv + BN
    dwconv_kernel<<<dim3(128, 64), 256>>>(wvl, bvl, bnvl);
    // 5. fused attention
    attn_kernel<<<dim3(14, 64), 256, attn_smem>>>(th1w, th1b, th2w, th2b, ab, bidx);
    // 6. transpose+split relu(att + v_local)
    pt_cvt_kernel<<<dim3(7, 32, 64), 256>>>();
    // 7. projection GEMM (M=384, K=1024)
    gemm_mma_kernel<<<dim3(98, 3), 256, GEMM_SMEM_BYTES>>>(
        wp_hi, wp_lo, pt_hi, pt_lo, 1024, sv + 1536, tv + 1536, out, 384);
}

// round 6
// speedup vs baseline: 1.8742x; 1.5219x over previous
#include <cuda_runtime.h>
#include <cuda_bf16.h>
#include <math.h>
#include <stdint.h>

#define EPSF 1e-5f
#define SCALEF 0.17677669529663687f

#define NB   64
#define NPIX 196
#define QKVC 1536
#define DHC  1024
#define NCOL 12544   // 64*196

// ------------------------------------------------------------------
// scratch (no cudaMalloc allowed)
__device__ float g_qkv [NB * QKVC * NPIX];   // [b][1536][196]; q@0, k@256, v@512
__device__ float g_vloc[NB * DHC * NPIX];    // [b][1024][196]
__device__ float g_att [NB * DHC * NPIX];    // [b][1024][196]

__device__ __align__(16) __nv_bfloat16 g_xt_hi[NCOL * 384];   // [j][k]
__device__ __align__(16) __nv_bfloat16 g_xt_lo[NCOL * 384];
__device__ __align__(16) __nv_bfloat16 g_pt_hi[NCOL * 1024];  // [j][k]
__device__ __align__(16) __nv_bfloat16 g_pt_lo[NCOL * 1024];
__device__ __align__(16) __nv_bfloat16 g_wqkv_hi[1536 * 384]; // [m][k]
__device__ __align__(16) __nv_bfloat16 g_wqkv_lo[1536 * 384];
__device__ __align__(16) __nv_bfloat16 g_wp_hi[384 * 1024];
__device__ __align__(16) __nv_bfloat16 g_wp_lo[384 * 1024];
__device__ float g_s[1920];   // folded BN scale: [0:1536) qkv, [1536:1920) proj
__device__ float g_t[1920];   // folded BN shift

// ------------------------------------------------------------------
static __device__ __forceinline__ uint32_t s2u(const void* p) {
    uint32_t a;
    asm("{ .reg .u64 t; cvta.to.shared.u64 t, %1; cvt.u32.u64 %0, t; }"
        : "=r"(a) : "l"(p));
    return a;
}

static __device__ __forceinline__ void cp_async16(uint32_t saddr, const void* gptr) {
    asm volatile("cp.async.cg.shared.global [%0], [%1], 16;"
                 :: "r"(saddr), "l"(gptr) : "memory");
}

static __device__ __forceinline__ void ldmat_x4(
    uint32_t& r0, uint32_t& r1, uint32_t& r2, uint32_t& r3, uint32_t addr)
{
    asm volatile("ldmatrix.sync.aligned.m8n8.x4.shared.b16 {%0,%1,%2,%3}, [%4];"
                 : "=r"(r0), "=r"(r1), "=r"(r2), "=r"(r3) : "r"(addr));
}

static __device__ __forceinline__ void mma_bf16(
    float& d0, float& d1, float& d2, float& d3,
    uint32_t a0, uint32_t a1, uint32_t a2, uint32_t a3,
    uint32_t b0, uint32_t b1)
{
    asm volatile(
        "mma.sync.aligned.m16n8k16.row.col.f32.bf16.bf16.f32 "
        "{%0,%1,%2,%3}, {%4,%5,%6,%7}, {%8,%9}, {%0,%1,%2,%3};"
        : "+f"(d0), "+f"(d1), "+f"(d2), "+f"(d3)
        : "r"(a0), "r"(a1), "r"(a2), "r"(a3), "r"(b0), "r"(b1));
}

// ------------------------------------------------------------------
// Prep: fold BN into (s,t) per output channel; split weights into bf16 hi/lo
__global__ void __launch_bounds__(256) prep_kernel(
    const float* __restrict__ wq, const float* __restrict__ wk,
    const float* __restrict__ wv, const float* __restrict__ wp,
    const float* __restrict__ bq, const float* __restrict__ bk,
    const float* __restrict__ bv, const float* __restrict__ bp,
    const float* __restrict__ bnq, const float* __restrict__ bnk,
    const float* __restrict__ bnv, const float* __restrict__ bnp)
{
    int idx = blockIdx.x * 256 + threadIdx.x;
    int stride = gridDim.x * 256;

    for (int i = idx; i < 1536 * 384; i += stride) {
        int m = i / 384;
        float w = (m < 256) ? wq[i]
                : (m < 512) ? wk[i - 256 * 384]
                            : wv[i - 512 * 384];
        __nv_bfloat16 h = __float2bfloat16(w);
        g_wqkv_hi[i] = h;
        g_wqkv_lo[i] = __float2bfloat16(w - __bfloat162float(h));
    }
    for (int i = idx; i < 384 * 1024; i += stride) {
        float w = wp[i];
        __nv_bfloat16 h = __float2bfloat16(w);
        g_wp_hi[i] = h;
        g_wp_lo[i] = __float2bfloat16(w - __bfloat162float(h));
    }
    if (idx < 1920) {
        const float* bn; const float* bias; int c; int C;
        if (idx < 256)       { bn = bnq; bias = bq; c = idx;        C = 256; }
        else if (idx < 512)  { bn = bnk; bias = bk; c = idx - 256;  C = 256; }
        else if (idx < 1536) { bn = bnv; bias = bv; c = idx - 512;  C = 1024; }
        else                 { bn = bnp; bias = bp; c = idx - 1536; C = 384; }
        float s = bn[c] * rsqrtf(bn[3 * C + c] + EPSF);
        g_s[idx] = s;
        g_t[idx] = (bias[c] - bn[2 * C + c]) * s + bn[C + c];
    }
}

// ------------------------------------------------------------------
// Transpose+split x: [b][384][196] -> Xt[j=b*196+n][k=c] bf16 hi/lo
__global__ void __launch_bounds__(256) xt_cvt_kernel(const float* __restrict__ X)
{
    __shared__ float t[32][29];
    int b = blockIdx.z, c0 = blockIdx.y * 32, n0 = blockIdx.x * 28;
    int tid = threadIdx.x;
    const float* src = X + ((size_t)b * 384 + c0) * 196 + n0;
    for (int i = tid; i < 32 * 28; i += 256) {
        int ci = i / 28, nj = i - ci * 28;
        t[ci][nj] = src[(size_t)ci * 196 + nj];
    }
    __syncthreads();
    for (int i = tid; i < 32 * 28; i += 256) {
        int nj = i >> 5, ci = i & 31;
        float v = t[ci][nj];
        __nv_bfloat16 h = __float2bfloat16(v);
        size_t o = ((size_t)(b * 196 + n0 + nj)) * 384 + c0 + ci;
        g_xt_hi[o] = h;
        g_xt_lo[o] = __float2bfloat16(v - __bfloat162float(h));
    }
}

// Transpose+split relu(g_att + g_vloc): -> Pt[j][k=c(1024)] bf16 hi/lo
__global__ void __launch_bounds__(256) pt_cvt_kernel()
{
    __shared__ float t[32][29];
    int b = blockIdx.z, c0 = blockIdx.y * 32, n0 = blockIdx.x * 28;
    int tid = threadIdx.x;
    const float* ap = g_att  + ((size_t)b * 1024 + c0) * 196 + n0;
    const float* lp = g_vloc + ((size_t)b * 1024 + c0) * 196 + n0;
    for (int i = tid; i < 32 * 28; i += 256) {
        int ci = i / 28, nj = i - ci * 28;
        size_t off = (size_t)ci * 196 + nj;
        t[ci][nj] = fmaxf(ap[off] + lp[off], 0.f);
    }
    __syncthreads();
    for (int i = tid; i < 32 * 28; i += 256) {
        int nj = i >> 5, ci = i & 31;
        float v = t[ci][nj];
        __nv_bfloat16 h = __float2bfloat16(v);
        size_t o = ((size_t)(b * 196 + n0 + nj)) * 1024 + c0 + ci;
        g_pt_hi[o] = h;
        g_pt_lo[o] = __float2bfloat16(v - __bfloat162float(h));
    }
}

// ------------------------------------------------------------------
// bf16 mma.sync GEMM, 3-term compensation fused per K-chunk (unchanged R5).
#define GEMM_STAGE_BYTES 65536
#define GEMM_SMEM_BYTES  (2 * GEMM_STAGE_BYTES)

__global__ void __launch_bounds__(256) gemm_mma_kernel(
    const __nv_bfloat16* __restrict__ Ahi, const __nv_bfloat16* __restrict__ Alo,
    const __nv_bfloat16* __restrict__ Bhi, const __nv_bfloat16* __restrict__ Blo,
    int K, const float* __restrict__ svec, const float* __restrict__ tvec,
    float* __restrict__ out, int Cout)
{
    extern __shared__ __align__(1024) char smem[];
    const uint32_t sb = s2u(smem);
    const int tid = threadIdx.x;
    const int wid = tid >> 5, lane = tid & 31;
    const int warp_m = wid & 1;
    const int warp_n = wid >> 1;
    const int m0 = blockIdx.y * 128;
    const int j0 = blockIdx.x * 128;
    const int nk = K >> 6;

    float acc[4][4][4];
#pragma unroll
    for (int i = 0; i < 4; i++)
#pragma unroll
        for (int j = 0; j < 4; j++)
#pragma unroll
            for (int c = 0; c < 4; c++) acc[i][j][c] = 0.f;

    const int lrow = lane & 15;
    const uint32_t lkoff = (uint32_t)((lane >> 4) << 4);

    auto issue = [&](int kb, uint32_t stage_off) {
#pragma unroll
        for (int i = 0; i < 4; i++) {
            int q = tid + (i << 8);
            int row = q >> 3, k8 = q & 7;
            uint32_t off = (uint32_t)(row * 128 + k8 * 16);
            uint32_t sw = off ^ ((off >> 3) & 0x70);
            size_t ga = (size_t)(m0 + row) * K + kb + (k8 << 3);
            size_t gb = (size_t)(j0 + row) * K + kb + (k8 << 3);
            cp_async16(sb + stage_off + sw,           Ahi + ga);
            cp_async16(sb + stage_off + 16384u + sw,  Alo + ga);
            cp_async16(sb + stage_off + 32768u + sw,  Bhi + gb);
            cp_async16(sb + stage_off + 49152u + sw,  Blo + gb);
        }
        asm volatile("cp.async.commit_group;" ::: "memory");
    };

    issue(0, 0u);
    if (nk > 1) issue(64, GEMM_STAGE_BYTES);

    for (int ch = 0; ch < nk; ch++) {
        if (ch + 1 < nk) asm volatile("cp.async.wait_group 1;" ::: "memory");
        else             asm volatile("cp.async.wait_group 0;" ::: "memory");
        __syncthreads();

        const uint32_t buf = (ch & 1) ? (uint32_t)GEMM_STAGE_BYTES : 0u;
#pragma unroll
        for (int ks = 0; ks < 4; ks++) {
            uint32_t bh[4][2], bl[4][2];
#pragma unroll
            for (int p = 0; p < 2; p++) {
                uint32_t off = (uint32_t)((warp_n * 32 + p * 16 + lrow) * 128)
                             + (uint32_t)(ks * 32) + lkoff;
                uint32_t sw = off ^ ((off >> 3) & 0x70);
                uint32_t r0, r1, r2, r3;
                ldmat_x4(r0, r1, r2, r3, sb + buf + 32768u + sw);
                bh[p * 2 + 0][0] = r0; bh[p * 2 + 1][0] = r1;
                bh[p * 2 + 0][1] = r2; bh[p * 2 + 1][1] = r3;
                ldmat_x4(r0, r1, r2, r3, sb + buf + 49152u + sw);
                bl[p * 2 + 0][0] = r0; bl[p * 2 + 1][0] = r1;
                bl[p * 2 + 0][1] = r2; bl[p * 2 + 1][1] = r3;
            }
#pragma unroll
            for (int mt = 0; mt < 4; mt++) {
                uint32_t off = (uint32_t)((warp_m * 64 + mt * 16 + lrow) * 128)
                             + (uint32_t)(ks * 32) + lkoff;
                uint32_t sw = off ^ ((off >> 3) & 0x70);
                uint32_t a0, a1, a2, a3;
                ldmat_x4(a0, a1, a2, a3, sb + buf + sw);
#pragma unroll
                for (int nt = 0; nt < 4; nt++)
                    mma_bf16(acc[mt][nt][0], acc[mt][nt][1],
                             acc[mt][nt][2], acc[mt][nt][3],
                             a0, a1, a2, a3, bh[nt][0], bh[nt][1]);
#pragma unroll
                for (int nt = 0; nt < 4; nt++)
                    mma_bf16(acc[mt][nt][0], acc[mt][nt][1],
                             acc[mt][nt][2], acc[mt][nt][3],
                             a0, a1, a2, a3, bl[nt][0], bl[nt][1]);
                ldmat_x4(a0, a1, a2, a3, sb + buf + 16384u + sw);
#pragma unroll
                for (int nt = 0; nt < 4; nt++)
                    mma_bf16(acc[mt][nt][0], acc[mt][nt][1],
                             acc[mt][nt][2], acc[mt][nt][3],
                             a0, a1, a2, a3, bh[nt][0], bh[nt][1]);
            }
        }

        if (ch + 2 < nk) {
            __syncthreads();
            issue((ch + 2) << 6, buf);
        }
    }

    const int group = lane >> 2, tig = lane & 3;
#pragma unroll
    for (int mt = 0; mt < 4; mt++) {
        int oc0 = m0 + warp_m * 64 + mt * 16 + group;
        int oc1 = oc0 + 8;
        float s0 = svec[oc0], t0 = tvec[oc0];
        float s1 = svec[oc1], t1 = tvec[oc1];
#pragma unroll
        for (int nt = 0; nt < 4; nt++) {
            int j = j0 + warp_n * 32 + nt * 8 + tig * 2;
            int b = j / 196, n = j - b * 196;
            float* p0 = out + ((size_t)b * Cout + oc0) * 196 + n;
            float* p1 = out + ((size_t)b * Cout + oc1) * 196 + n;
            p0[0] = acc[mt][nt][0] * s0 + t0;
            p0[1] = acc[mt][nt][1] * s0 + t0;
            p1[0] = acc[mt][nt][2] * s1 + t1;
            p1[1] = acc[mt][nt][3] * s1 + t1;
        }
    }
}

// ------------------------------------------------------------------
// Depthwise 3x3 'SAME' conv on v + BN -> g_vloc.
__global__ void __launch_bounds__(256) dwconv_kernel(
    const float* __restrict__ wvl, const float* __restrict__ bvl,
    const float* __restrict__ bn)
{
    int c0 = blockIdx.x * 8, b = blockIdx.y;
    __shared__ float p[8 * 196];
    __shared__ float wsh[72];
    __shared__ float cs[8], ct[8];
    int tid = threadIdx.x;
    const float* src = g_qkv + (size_t)b * (QKVC * NPIX) + (size_t)(512 + c0) * NPIX;
    for (int i = tid; i < 1568; i += 256) p[i] = src[i];
    if (tid < 72) wsh[tid] = wvl[c0 * 9 + tid];
    if (tid < 8) {
        int c = c0 + tid;
        float s = bn[c] * rsqrtf(bn[3072 + c] + EPSF);
        cs[tid] = s;
        ct[tid] = (bvl[c] - bn[2048 + c]) * s + bn[1024 + c];
    }
    __syncthreads();
    float* dst = g_vloc + (size_t)b * (DHC * NPIX) + (size_t)c0 * NPIX;
    for (int i = tid; i < 1568; i += 256) {
        int c = i / 196, pix = i - c * 196;
        int y = pix / 14, x = pix - y * 14;
        const float* pc = p + c * 196;
        const float* w = wsh + c * 9;
        float acc = 0.f;
#pragma unroll
        for (int dy = 0; dy < 3; dy++) {
            int yy = y + dy - 1;
            if (yy < 0 || yy > 13) continue;
#pragma unroll
            for (int dx = 0; dx < 3; dx++) {
                int xx = x + dx - 1;
                if (xx < 0 || xx > 13) continue;
                acc = fmaf(pc[yy * 14 + xx], w[dy * 3 + dx], acc);
            }
        }
        dst[i] = acc * cs[c] + ct[c];
    }
}

// ------------------------------------------------------------------
// Fused attention, v2: 109.5 KB smem -> 2 blocks/SM.
// smem (floats): L 21952 | ab 1568 | tile 3712 | th 144  = 27376
#define ATTN_SMEM_FLOATS (21952 + 1568 + 3712 + 144)

__global__ void __launch_bounds__(256, 2) attn_kernel(
    const float* __restrict__ th1w, const float* __restrict__ th1b,
    const float* __restrict__ th2w, const float* __restrict__ th2b,
    const float* __restrict__ ab,   const int* __restrict__ bidx)
{
    extern __shared__ float sm[];
    float* L    = sm;                 // [(h*14+nl)*196 + m]
    float* abs_ = sm + 21952;         // [h*196 + p]
    float* tile = abs_ + 1568;        // k-tile [c*14+mm] (3584) / v-tile [e*29+mm] (3712)
    float* th   = tile + 3712;        // th1w(64) th1b(8) th2w(64) th2b(8)

    int tid = threadIdx.x;
    int b = blockIdx.y;
    int n0 = blockIdx.x * 14;
    const float* qbase = g_qkv + (size_t)b * (QKVC * NPIX);
    const float* kbase = qbase + 256 * NPIX;
    const float* vbase = qbase + 512 * NPIX;

    for (int i = tid; i < 1568; i += 256) abs_[i] = ab[i];
    if (tid < 64)       th[tid] = th1w[tid];
    else if (tid < 72)  th[tid] = th1b[tid - 64];
    else if (tid < 136) th[tid] = th2w[tid - 72];
    else if (tid < 144) th[tid] = th2b[tid - 136];

    // q straight into registers (coalesced across nl within a warp)
    float qreg[32];
    int h = 0, nl = 0, half = 0;
    bool active = tid < 224;
    if (active) {
        int pair = tid >> 1;
        h = pair / 14; nl = pair - h * 14; half = tid & 1;
#pragma unroll
        for (int d = 0; d < 32; d++)
            qreg[d] = qbase[(size_t)(h * 32 + d) * NPIX + n0 + nl];
    }

    // ---- logits: s*SCALE + ab[h, bidx[n,m]]; 14 m-tiles of width 14 ----
    for (int mt = 0; mt < 14; mt++) {
        int m0 = mt * 14;
        __syncthreads();
        for (int i = tid; i < 3584; i += 256) {
            int c = i / 14, mm = i - c * 14;
            tile[i] = kbase[(size_t)c * NPIX + m0 + mm];
        }
        __syncthreads();
        if (active) {
            const float* kcol = tile + (h * 32) * 14;
            const int* brow = bidx + (size_t)(n0 + nl) * NPIX;
#pragma unroll
            for (int jm = 0; jm < 7; jm++) {
                int mm = half * 7 + jm;
                float s = 0.f;
#pragma unroll
                for (int d = 0; d < 32; d++)
                    s = fmaf(qreg[d], kcol[d * 14 + mm], s);
                int m = m0 + mm;
                L[(h * 14 + nl) * 196 + m] = s * SCALEF + abs_[h * 196 + brow[m]];
            }
        }
    }
    __syncthreads();

    // ---- talking-heads 1 ----
    for (int idx = tid; idx < 2744; idx += 256) {
        int n_ = idx / 196, m = idx - n_ * 196;
        float v[8], o_[8];
#pragma unroll
        for (int hh = 0; hh < 8; hh++) v[hh] = L[(hh * 14 + n_) * 196 + m];
#pragma unroll
        for (int oo = 0; oo < 8; oo++) {
            float s = th[64 + oo];
#pragma unroll
            for (int hh = 0; hh < 8; hh++) s = fmaf(th[oo * 8 + hh], v[hh], s);
            o_[oo] = s;
        }
#pragma unroll
        for (int oo = 0; oo < 8; oo++) L[(oo * 14 + n_) * 196 + m] = o_[oo];
    }
    __syncthreads();

    // ---- softmax over m (warp w owns head o = w) ----
    {
        int w = tid >> 5, lane = tid & 31;
        for (int r = 0; r < 14; r++) {
            float* row = L + (w * 14 + r) * 196;
            float mx = -1e30f;
            for (int m = lane; m < 196; m += 32) mx = fmaxf(mx, row[m]);
#pragma unroll
            for (int off = 16; off > 0; off >>= 1)
                mx = fmaxf(mx, __shfl_xor_sync(0xffffffffu, mx, off));
            float sum = 0.f;
            for (int m = lane; m < 196; m += 32) {
                float e = __expf(row[m] - mx);
                row[m] = e; sum += e;
            }
#pragma unroll
            for (int off = 16; off > 0; off >>= 1)
                sum += __shfl_xor_sync(0xffffffffu, sum, off);
            float inv = 1.f / sum;
            for (int m = lane; m < 196; m += 32) row[m] *= inv;
        }
    }
    __syncthreads();

    // ---- talking-heads 2 ----
    for (int idx = tid; idx < 2744; idx += 256) {
        int n_ = idx / 196, m = idx - n_ * 196;
        float v[8], o_[8];
#pragma unroll
        for (int hh = 0; hh < 8; hh++) v[hh] = L[(hh * 14 + n_) * 196 + m];
#pragma unroll
        for (int oo = 0; oo < 8; oo++) {
            float s = th[136 + oo];
#pragma unroll
            for (int hh = 0; hh < 8; hh++) s = fmaf(th[72 + oo * 8 + hh], v[hh], s);
            o_[oo] = s;
        }
#pragma unroll
        for (int oo = 0; oo < 8; oo++) L[(oo * 14 + n_) * 196 + m] = o_[oo];
    }
    __syncthreads();

    // ---- AV: out[o, n, e] = sum_m P[o,n,m] * v[b, o*128+e, m] ----
    {
        int e = tid & 127, g = tid >> 7;
        float* vs = tile;                  // [e*29 + mm], 128*29 = 3712 floats
        for (int o = 0; o < 8; o++) {
            float acc[7];
#pragma unroll
            for (int j = 0; j < 7; j++) acc[j] = 0.f;
            for (int mt = 0; mt < 7; mt++) {
                int m0 = mt * 28;
                __syncthreads();
                for (int i = tid; i < 3584; i += 256) {
                    int ee = i / 28, mm = i - ee * 28;
                    vs[ee * 29 + mm] = vbase[(size_t)(o * 128 + ee) * NPIX + m0 + mm];
                }
                __syncthreads();
                const float* lbase = L + (o * 14 + g * 7) * 196 + m0;
#pragma unroll
                for (int mm = 0; mm < 28; mm++) {
                    float vv = vs[e * 29 + mm];
#pragma unroll
                    for (int j = 0; j < 7; j++)
                        acc[j] = fmaf(lbase[j * 196 + mm], vv, acc[j]);
                }
            }
            float* obase = g_att + (size_t)b * (DHC * NPIX)
                         + (size_t)(o * 128 + e) * NPIX + n0 + g * 7;
#pragma unroll
            for (int j = 0; j < 7; j++) obase[j] = acc[j];
        }
    }
}

// ------------------------------------------------------------------
extern "C" void kernel_launch(void* const* d_in, const int* in_sizes, int n_in,
                              void* d_out, int out_size)
{
    const float* x    = (const float*)d_in[0];
    const float* wq   = (const float*)d_in[1];
    const float* bq   = (const float*)d_in[2];
    const float* bnq  = (const float*)d_in[3];
    const float* wk   = (const float*)d_in[4];
    const float* bk   = (const float*)d_in[5];
    const float* bnk  = (const float*)d_in[6];
    const float* wv   = (const float*)d_in[7];
    const float* bv   = (const float*)d_in[8];
    const float* bnv  = (const float*)d_in[9];
    const float* wvl  = (const float*)d_in[10];
    const float* bvl  = (const float*)d_in[11];
    const float* bnvl = (const float*)d_in[12];
    const float* th1w = (const float*)d_in[13];
    const float* th1b = (const float*)d_in[14];
    const float* th2w = (const float*)d_in[15];
    const float* th2b = (const float*)d_in[16];
    const float* wp   = (const float*)d_in[17];
    const float* bp   = (const float*)d_in[18];
    const float* bnp  = (const float*)d_in[19];
    const float* ab   = (const float*)d_in[20];
    const int*   bidx = (const int*)d_in[21];
    float* out = (float*)d_out;

    const int attn_smem = ATTN_SMEM_FLOATS * (int)sizeof(float);
    cudaFuncSetAttribute(attn_kernel,
                         cudaFuncAttributeMaxDynamicSharedMemorySize, attn_smem);
    cudaFuncSetAttribute(gemm_mma_kernel,
                         cudaFuncAttributeMaxDynamicSharedMemorySize, GEMM_SMEM_BYTES);

    __nv_bfloat16 *wqkv_hi, *wqkv_lo, *xt_hi, *xt_lo, *wp_hi, *wp_lo, *pt_hi, *pt_lo;
    float *sv, *tv, *qkv_out;
    cudaGetSymbolAddress((void**)&wqkv_hi, g_wqkv_hi);
    cudaGetSymbolAddress((void**)&wqkv_lo, g_wqkv_lo);
    cudaGetSymbolAddress((void**)&xt_hi, g_xt_hi);
    cudaGetSymbolAddress((void**)&xt_lo, g_xt_lo);
    cudaGetSymbolAddress((void**)&wp_hi, g_wp_hi);
    cudaGetSymbolAddress((void**)&wp_lo, g_wp_lo);
    cudaGetSymbolAddress((void**)&pt_hi, g_pt_hi);
    cudaGetSymbolAddress((void**)&pt_lo, g_pt_lo);
    cudaGetSymbolAddress((void**)&sv, g_s);
    cudaGetSymbolAddress((void**)&tv, g_t);
    cudaGetSymbolAddress((void**)&qkv_out, g_qkv);

    // 1. fold BN + split weights
    prep_kernel<<<2304, 256>>>(wq, wk, wv, wp, bq, bk, bv, bp, bnq, bnk, bnv, bnp);
    // 2. transpose+split x
    xt_cvt_kernel<<<dim3(7, 12, 64), 256>>>(x);
    // 3. fused qkv GEMM (M=1536, K=384)
    gemm_mma_kernel<<<dim3(98, 12), 256, GEMM_SMEM_BYTES>>>(
        wqkv_hi, wqkv_lo, xt_hi, xt_lo, 384, sv, tv, qkv_out, 1536);
    // 4. depthwise conv + BN
    dwconv_kernel<<<dim3(128, 64), 256>>>(wvl, bvl, bnvl);
    // 5. fused attention
    attn_kernel<<<dim3(14, 64), 256, attn_smem>>>(th1w, th1b, th2w, th2b, ab, bidx);
    // 6. transpose+split relu(att + v_local)
    pt_cvt_kernel<<<dim3(7, 32, 64), 256>>>();
    // 7. projection GEMM (M=384, K=1024)
    gemm_mma_kernel<<<dim3(98, 3), 256, GEMM_SMEM_BYTES>>>(
        wp_hi, wp_lo, pt_hi, pt_lo, 1024, sv + 1536, tv + 1536, out, 384);
}

// round 7
// speedup vs baseline: 2.6490x; 1.4134x over previous
#include <cuda_runtime.h>
#include <cuda_bf16.h>
#include <math.h>
#include <stdint.h>

#define EPSF 1e-5f
#define SCALEF 0.17677669529663687f

#define NB   64
#define NPIX 196
#define QKVC 1536
#define DHC  1024
#define NCOL 12544   // 64*196
#define KPAD 256     // padded k (m) dimension for AV mma

// ------------------------------------------------------------------
// scratch (no cudaMalloc allowed)
__device__ float g_qkv [NB * QKVC * NPIX];   // [b][1536][196]; q@0, k@256, v@512
__device__ float g_vloc[NB * DHC * NPIX];    // [b][1024][196]
__device__ float g_att [NB * DHC * NPIX];    // [b][1024][196]

__device__ __align__(16) __nv_bfloat16 g_xt_hi[NCOL * 384];   // [j][k]
__device__ __align__(16) __nv_bfloat16 g_xt_lo[NCOL * 384];
__device__ __align__(16) __nv_bfloat16 g_pt_hi[NCOL * 1024];  // [j][k]
__device__ __align__(16) __nv_bfloat16 g_pt_lo[NCOL * 1024];
__device__ __align__(16) __nv_bfloat16 g_wqkv_hi[1536 * 384]; // [m][k]
__device__ __align__(16) __nv_bfloat16 g_wqkv_lo[1536 * 384];
__device__ __align__(16) __nv_bfloat16 g_wp_hi[384 * 1024];
__device__ __align__(16) __nv_bfloat16 g_wp_lo[384 * 1024];
// attention P (post-softmax/TH2) bf16 hi/lo: [(b*8+o)*196 + n][k=KPAD]
__device__ __align__(16) __nv_bfloat16 g_phi[512 * 196 * KPAD];
__device__ __align__(16) __nv_bfloat16 g_plo[512 * 196 * KPAD];
// raw V bf16 hi/lo: [b][c(1024)][k=KPAD]
__device__ __align__(16) __nv_bfloat16 g_vhi[NB * 1024 * KPAD];
__device__ __align__(16) __nv_bfloat16 g_vlo[NB * 1024 * KPAD];
__device__ float g_s[1920];   // folded BN scale: [0:1536) qkv, [1536:1920) proj
__device__ float g_t[1920];   // folded BN shift

// ------------------------------------------------------------------
static __device__ __forceinline__ uint32_t s2u(const void* p) {
    uint32_t a;
    asm("{ .reg .u64 t; cvta.to.shared.u64 t, %1; cvt.u32.u64 %0, t; }"
        : "=r"(a) : "l"(p));
    return a;
}

static __device__ __forceinline__ void cp_async16(uint32_t saddr, const void* gptr) {
    asm volatile("cp.async.cg.shared.global [%0], [%1], 16;"
                 :: "r"(saddr), "l"(gptr) : "memory");
}

// zero-fill variant: src-size register (16 = copy, 0 = fill 16B of zeros)
static __device__ __forceinline__ void cp_async16_zf(uint32_t saddr, const void* gptr, int valid) {
    int sz = valid ? 16 : 0;
    asm volatile("cp.async.cg.shared.global [%0], [%1], 16, %2;"
                 :: "r"(saddr), "l"(gptr), "r"(sz) : "memory");
}

static __device__ __forceinline__ void ldmat_x4(
    uint32_t& r0, uint32_t& r1, uint32_t& r2, uint32_t& r3, uint32_t addr)
{
    asm volatile("ldmatrix.sync.aligned.m8n8.x4.shared.b16 {%0,%1,%2,%3}, [%4];"
                 : "=r"(r0), "=r"(r1), "=r"(r2), "=r"(r3) : "r"(addr));
}

static __device__ __forceinline__ void mma_bf16(
    float& d0, float& d1, float& d2, float& d3,
    uint32_t a0, uint32_t a1, uint32_t a2, uint32_t a3,
    uint32_t b0, uint32_t b1)
{
    asm volatile(
        "mma.sync.aligned.m16n8k16.row.col.f32.bf16.bf16.f32 "
        "{%0,%1,%2,%3}, {%4,%5,%6,%7}, {%8,%9}, {%0,%1,%2,%3};"
        : "+f"(d0), "+f"(d1), "+f"(d2), "+f"(d3)
        : "r"(a0), "r"(a1), "r"(a2), "r"(a3), "r"(b0), "r"(b1));
}

// ------------------------------------------------------------------
// Prep: fold BN; split weights into bf16 hi/lo; zero static k-pads of P/V exports.
__global__ void __launch_bounds__(256) prep_kernel(
    const float* __restrict__ wq, const float* __restrict__ wk,
    const float* __restrict__ wv, const float* __restrict__ wp,
    const float* __restrict__ bq, const float* __restrict__ bk,
    const float* __restrict__ bv, const float* __restrict__ bp,
    const float* __restrict__ bnq, const float* __restrict__ bnk,
    const float* __restrict__ bnv, const float* __restrict__ bnp)
{
    int idx = blockIdx.x * 256 + threadIdx.x;
    int stride = gridDim.x * 256;
    const __nv_bfloat16 z = __float2bfloat16(0.f);

    for (int i = idx; i < 1536 * 384; i += stride) {
        int m = i / 384;
        float w = (m < 256) ? wq[i]
                : (m < 512) ? wk[i - 256 * 384]
                            : wv[i - 512 * 384];
        __nv_bfloat16 h = __float2bfloat16(w);
        g_wqkv_hi[i] = h;
        g_wqkv_lo[i] = __float2bfloat16(w - __bfloat162float(h));
    }
    for (int i = idx; i < 384 * 1024; i += stride) {
        float w = wp[i];
        __nv_bfloat16 h = __float2bfloat16(w);
        g_wp_hi[i] = h;
        g_wp_lo[i] = __float2bfloat16(w - __bfloat162float(h));
    }
    // zero P k-pad (cols 196..255 of every row)
    for (long i = idx; i < (long)512 * 196 * 60; i += stride) {
        long r = i / 60; int c = 196 + (int)(i % 60);
        g_phi[r * KPAD + c] = z;
        g_plo[r * KPAD + c] = z;
    }
    // zero V k-pad
    for (long i = idx; i < (long)NB * 1024 * 60; i += stride) {
        long r = i / 60; int c = 196 + (int)(i % 60);
        g_vhi[r * KPAD + c] = z;
        g_vlo[r * KPAD + c] = z;
    }
    if (idx < 1920) {
        const float* bn; const float* bias; int c; int C;
        if (idx < 256)       { bn = bnq; bias = bq; c = idx;        C = 256; }
        else if (idx < 512)  { bn = bnk; bias = bk; c = idx - 256;  C = 256; }
        else if (idx < 1536) { bn = bnv; bias = bv; c = idx - 512;  C = 1024; }
        else                 { bn = bnp; bias = bp; c = idx - 1536; C = 384; }
        float s = bn[c] * rsqrtf(bn[3 * C + c] + EPSF);
        g_s[idx] = s;
        g_t[idx] = (bias[c] - bn[2 * C + c]) * s + bn[C + c];
    }
}

// ------------------------------------------------------------------
// Transpose+split x: [b][384][196] -> Xt[j=b*196+n][k=c] bf16 hi/lo
__global__ void __launch_bounds__(256) xt_cvt_kernel(const float* __restrict__ X)
{
    __shared__ float t[32][29];
    int b = blockIdx.z, c0 = blockIdx.y * 32, n0 = blockIdx.x * 28;
    int tid = threadIdx.x;
    const float* src = X + ((size_t)b * 384 + c0) * 196 + n0;
    for (int i = tid; i < 32 * 28; i += 256) {
        int ci = i / 28, nj = i - ci * 28;
        t[ci][nj] = src[(size_t)ci * 196 + nj];
    }
    __syncthreads();
    for (int i = tid; i < 32 * 28; i += 256) {
        int nj = i >> 5, ci = i & 31;
        float v = t[ci][nj];
        __nv_bfloat16 h = __float2bfloat16(v);
        size_t o = ((size_t)(b * 196 + n0 + nj)) * 384 + c0 + ci;
        g_xt_hi[o] = h;
        g_xt_lo[o] = __float2bfloat16(v - __bfloat162float(h));
    }
}

// Transpose+split relu(g_att + g_vloc): -> Pt[j][k=c(1024)] bf16 hi/lo
__global__ void __launch_bounds__(256) pt_cvt_kernel()
{
    __shared__ float t[32][29];
    int b = blockIdx.z, c0 = blockIdx.y * 32, n0 = blockIdx.x * 28;
    int tid = threadIdx.x;
    const float* ap = g_att  + ((size_t)b * 1024 + c0) * 196 + n0;
    const float* lp = g_vloc + ((size_t)b * 1024 + c0) * 196 + n0;
    for (int i = tid; i < 32 * 28; i += 256) {
        int ci = i / 28, nj = i - ci * 28;
        size_t off = (size_t)ci * 196 + nj;
        t[ci][nj] = fmaxf(ap[off] + lp[off], 0.f);
    }
    __syncthreads();
    for (int i = tid; i < 32 * 28; i += 256) {
        int nj = i >> 5, ci = i & 31;
        float v = t[ci][nj];
        __nv_bfloat16 h = __float2bfloat16(v);
        size_t o = ((size_t)(b * 196 + n0 + nj)) * 1024 + c0 + ci;
        g_pt_hi[o] = h;
        g_pt_lo[o] = __float2bfloat16(v - __bfloat162float(h));
    }
}

// ------------------------------------------------------------------
// bf16 mma.sync GEMM, 3-term compensation fused per K-chunk (unchanged R5/R6).
#define GEMM_STAGE_BYTES 65536
#define GEMM_SMEM_BYTES  (2 * GEMM_STAGE_BYTES)

__global__ void __launch_bounds__(256) gemm_mma_kernel(
    const __nv_bfloat16* __restrict__ Ahi, const __nv_bfloat16* __restrict__ Alo,
    const __nv_bfloat16* __restrict__ Bhi, const __nv_bfloat16* __restrict__ Blo,
    int K, const float* __restrict__ svec, const float* __restrict__ tvec,
    float* __restrict__ out, int Cout)
{
    extern __shared__ __align__(1024) char smem[];
    const uint32_t sb = s2u(smem);
    const int tid = threadIdx.x;
    const int wid = tid >> 5, lane = tid & 31;
    const int warp_m = wid & 1;
    const int warp_n = wid >> 1;
    const int m0 = blockIdx.y * 128;
    const int j0 = blockIdx.x * 128;
    const int nk = K >> 6;

    float acc[4][4][4];
#pragma unroll
    for (int i = 0; i < 4; i++)
#pragma unroll
        for (int j = 0; j < 4; j++)
#pragma unroll
            for (int c = 0; c < 4; c++) acc[i][j][c] = 0.f;

    const int lrow = lane & 15;
    const uint32_t lkoff = (uint32_t)((lane >> 4) << 4);

    auto issue = [&](int kb, uint32_t stage_off) {
#pragma unroll
        for (int i = 0; i < 4; i++) {
            int q = tid + (i << 8);
            int row = q >> 3, k8 = q & 7;
            uint32_t off = (uint32_t)(row * 128 + k8 * 16);
            uint32_t sw = off ^ ((off >> 3) & 0x70);
            size_t ga = (size_t)(m0 + row) * K + kb + (k8 << 3);
            size_t gb = (size_t)(j0 + row) * K + kb + (k8 << 3);
            cp_async16(sb + stage_off + sw,           Ahi + ga);
            cp_async16(sb + stage_off + 16384u + sw,  Alo + ga);
            cp_async16(sb + stage_off + 32768u + sw,  Bhi + gb);
            cp_async16(sb + stage_off + 49152u + sw,  Blo + gb);
        }
        asm volatile("cp.async.commit_group;" ::: "memory");
    };

    issue(0, 0u);
    if (nk > 1) issue(64, GEMM_STAGE_BYTES);

    for (int ch = 0; ch < nk; ch++) {
        if (ch + 1 < nk) asm volatile("cp.async.wait_group 1;" ::: "memory");
        else             asm volatile("cp.async.wait_group 0;" ::: "memory");
        __syncthreads();

        const uint32_t buf = (ch & 1) ? (uint32_t)GEMM_STAGE_BYTES : 0u;
#pragma unroll
        for (int ks = 0; ks < 4; ks++) {
            uint32_t bh[4][2], bl[4][2];
#pragma unroll
            for (int p = 0; p < 2; p++) {
                uint32_t off = (uint32_t)((warp_n * 32 + p * 16 + lrow) * 128)
                             + (uint32_t)(ks * 32) + lkoff;
                uint32_t sw = off ^ ((off >> 3) & 0x70);
                uint32_t r0, r1, r2, r3;
                ldmat_x4(r0, r1, r2, r3, sb + buf + 32768u + sw);
                bh[p * 2 + 0][0] = r0; bh[p * 2 + 1][0] = r1;
                bh[p * 2 + 0][1] = r2; bh[p * 2 + 1][1] = r3;
                ldmat_x4(r0, r1, r2, r3, sb + buf + 49152u + sw);
                bl[p * 2 + 0][0] = r0; bl[p * 2 + 1][0] = r1;
                bl[p * 2 + 0][1] = r2; bl[p * 2 + 1][1] = r3;
            }
#pragma unroll
            for (int mt = 0; mt < 4; mt++) {
                uint32_t off = (uint32_t)((warp_m * 64 + mt * 16 + lrow) * 128)
                             + (uint32_t)(ks * 32) + lkoff;
                uint32_t sw = off ^ ((off >> 3) & 0x70);
                uint32_t a0, a1, a2, a3;
                ldmat_x4(a0, a1, a2, a3, sb + buf + sw);
#pragma unroll
                for (int nt = 0; nt < 4; nt++)
                    mma_bf16(acc[mt][nt][0], acc[mt][nt][1],
                             acc[mt][nt][2], acc[mt][nt][3],
                             a0, a1, a2, a3, bh[nt][0], bh[nt][1]);
#pragma unroll
                for (int nt = 0; nt < 4; nt++)
                    mma_bf16(acc[mt][nt][0], acc[mt][nt][1],
                             acc[mt][nt][2], acc[mt][nt][3],
                             a0, a1, a2, a3, bl[nt][0], bl[nt][1]);
                ldmat_x4(a0, a1, a2, a3, sb + buf + 16384u + sw);
#pragma unroll
                for (int nt = 0; nt < 4; nt++)
                    mma_bf16(acc[mt][nt][0], acc[mt][nt][1],
                             acc[mt][nt][2], acc[mt][nt][3],
                             a0, a1, a2, a3, bh[nt][0], bh[nt][1]);
            }
        }

        if (ch + 2 < nk) {
            __syncthreads();
            issue((ch + 2) << 6, buf);
        }
    }

    const int group = lane >> 2, tig = lane & 3;
#pragma unroll
    for (int mt = 0; mt < 4; mt++) {
        int oc0 = m0 + warp_m * 64 + mt * 16 + group;
        int oc1 = oc0 + 8;
        float s0 = svec[oc0], t0 = tvec[oc0];
        float s1 = svec[oc1], t1 = tvec[oc1];
#pragma unroll
        for (int nt = 0; nt < 4; nt++) {
            int j = j0 + warp_n * 32 + nt * 8 + tig * 2;
            int b = j / 196, n = j - b * 196;
            float* p0 = out + ((size_t)b * Cout + oc0) * 196 + n;
            float* p1 = out + ((size_t)b * Cout + oc1) * 196 + n;
            p0[0] = acc[mt][nt][0] * s0 + t0;
            p0[1] = acc[mt][nt][1] * s0 + t0;
            p1[0] = acc[mt][nt][2] * s1 + t1;
            p1[1] = acc[mt][nt][3] * s1 + t1;
        }
    }
}

// ------------------------------------------------------------------
// AV batched mma: D[e,n] = sum_m V[b,o*128+e,m] * P[bo,n,m], 3-term bf16.
// grid = (2 n-tiles, 512 bo). A = V rows (128), B = P rows (128 of 196, zfill).
// K = 256 (padded, zeros). Output: g_att[b][o*128+e][n] fp32.
__global__ void __launch_bounds__(256) av_mma_kernel()
{
    extern __shared__ __align__(1024) char smem[];
    const uint32_t sb = s2u(smem);
    const int tid = threadIdx.x;
    const int wid = tid >> 5, lane = tid & 31;
    const int warp_m = wid & 1;
    const int warp_n = wid >> 1;
    const int bo = blockIdx.y;          // b*8 + o
    const int b  = bo >> 3, o = bo & 7;
    const int j0 = blockIdx.x * 128;    // n-tile origin
    const int nk = 4;                   // K = 256

    const __nv_bfloat16* Ahi = g_vhi + ((size_t)b * 1024 + o * 128) * KPAD;
    const __nv_bfloat16* Alo = g_vlo + ((size_t)b * 1024 + o * 128) * KPAD;
    const __nv_bfloat16* Bhi = g_phi + ((size_t)bo * 196) * KPAD;
    const __nv_bfloat16* Blo = g_plo + ((size_t)bo * 196) * KPAD;

    float acc[4][4][4];
#pragma unroll
    for (int i = 0; i < 4; i++)
#pragma unroll
        for (int j = 0; j < 4; j++)
#pragma unroll
            for (int c = 0; c < 4; c++) acc[i][j][c] = 0.f;

    const int lrow = lane & 15;
    const uint32_t lkoff = (uint32_t)((lane >> 4) << 4);

    auto issue = [&](int kb, uint32_t stage_off) {
#pragma unroll
        for (int i = 0; i < 4; i++) {
            int q = tid + (i << 8);
            int row = q >> 3, k8 = q & 7;
            uint32_t off = (uint32_t)(row * 128 + k8 * 16);
            uint32_t sw = off ^ ((off >> 3) & 0x70);
            size_t ga = (size_t)row * KPAD + kb + (k8 << 3);
            cp_async16(sb + stage_off + sw,          Ahi + ga);
            cp_async16(sb + stage_off + 16384u + sw, Alo + ga);
            int jrow = j0 + row;
            int valid = (jrow < 196);
            size_t gb = (size_t)jrow * KPAD + kb + (k8 << 3);
            if (!valid) gb = 0;
            cp_async16_zf(sb + stage_off + 32768u + sw, Bhi + gb, valid);
            cp_async16_zf(sb + stage_off + 49152u + sw, Blo + gb, valid);
        }
        asm volatile("cp.async.commit_group;" ::: "memory");
    };

    issue(0, 0u);
    issue(64, GEMM_STAGE_BYTES);

    for (int ch = 0; ch < nk; ch++) {
        if (ch + 1 < nk) asm volatile("cp.async.wait_group 1;" ::: "memory");
        else             asm volatile("cp.async.wait_group 0;" ::: "memory");
        __syncthreads();

        const uint32_t buf = (ch & 1) ? (uint32_t)GEMM_STAGE_BYTES : 0u;
#pragma unroll
        for (int ks = 0; ks < 4; ks++) {
            uint32_t bh[4][2], bl[4][2];
#pragma unroll
            for (int p = 0; p < 2; p++) {
                uint32_t off = (uint32_t)((warp_n * 32 + p * 16 + lrow) * 128)
                             + (uint32_t)(ks * 32) + lkoff;
                uint32_t sw = off ^ ((off >> 3) & 0x70);
                uint32_t r0, r1, r2, r3;
                ldmat_x4(r0, r1, r2, r3, sb + buf + 32768u + sw);
                bh[p * 2 + 0][0] = r0; bh[p * 2 + 1][0] = r1;
                bh[p * 2 + 0][1] = r2; bh[p * 2 + 1][1] = r3;
                ldmat_x4(r0, r1, r2, r3, sb + buf + 49152u + sw);
                bl[p * 2 + 0][0] = r0; bl[p * 2 + 1][0] = r1;
                bl[p * 2 + 0][1] = r2; bl[p * 2 + 1][1] = r3;
            }
#pragma unroll
            for (int mt = 0; mt < 4; mt++) {
                uint32_t off = (uint32_t)((warp_m * 64 + mt * 16 + lrow) * 128)
                             + (uint32_t)(ks * 32) + lkoff;
                uint32_t sw = off ^ ((off >> 3) & 0x70);
                uint32_t a0, a1, a2, a3;
                ldmat_x4(a0, a1, a2, a3, sb + buf + sw);
#pragma unroll
                for (int nt = 0; nt < 4; nt++)
                    mma_bf16(acc[mt][nt][0], acc[mt][nt][1],
                             acc[mt][nt][2], acc[mt][nt][3],
                             a0, a1, a2, a3, bh[nt][0], bh[nt][1]);
#pragma unroll
                for (int nt = 0; nt < 4; nt++)
                    mma_bf16(acc[mt][nt][0], acc[mt][nt][1],
                             acc[mt][nt][2], acc[mt][nt][3],
                             a0, a1, a2, a3, bl[nt][0], bl[nt][1]);
                ldmat_x4(a0, a1, a2, a3, sb + buf + 16384u + sw);
#pragma unroll
                for (int nt = 0; nt < 4; nt++)
                    mma_bf16(acc[mt][nt][0], acc[mt][nt][1],
                             acc[mt][nt][2], acc[mt][nt][3],
                             a0, a1, a2, a3, bh[nt][0], bh[nt][1]);
            }
        }

        if (ch + 2 < nk) {
            __syncthreads();
            issue((ch + 2) << 6, buf);
        }
    }

    // epilogue: g_att[b][o*128 + e][n]
    const int group = lane >> 2, tig = lane & 3;
    float* obase = g_att + ((size_t)b * 1024 + o * 128) * NPIX;
#pragma unroll
    for (int mt = 0; mt < 4; mt++) {
        int e0 = warp_m * 64 + mt * 16 + group;
        int e1 = e0 + 8;
#pragma unroll
        for (int nt = 0; nt < 4; nt++) {
            int j = j0 + warp_n * 32 + nt * 8 + tig * 2;
            if (j < 196) {
                float* p0 = obase + (size_t)e0 * NPIX + j;
                float* p1 = obase + (size_t)e1 * NPIX + j;
                p0[0] = acc[mt][nt][0];
                p0[1] = acc[mt][nt][1];
                p1[0] = acc[mt][nt][2];
                p1[1] = acc[mt][nt][3];
            }
        }
    }
}

// ------------------------------------------------------------------
// Depthwise 3x3 'SAME' conv on v + BN -> g_vloc; also exports raw V as bf16 hi/lo.
__global__ void __launch_bounds__(256) dwconv_kernel(
    const float* __restrict__ wvl, const float* __restrict__ bvl,
    const float* __restrict__ bn)
{
    int c0 = blockIdx.x * 8, b = blockIdx.y;
    __shared__ float p[8 * 196];
    __shared__ float wsh[72];
    __shared__ float cs[8], ct[8];
    int tid = threadIdx.x;
    const float* src = g_qkv + (size_t)b * (QKVC * NPIX) + (size_t)(512 + c0) * NPIX;
    __nv_bfloat16* vhi = g_vhi + ((size_t)b * 1024 + c0) * KPAD;
    __nv_bfloat16* vlo = g_vlo + ((size_t)b * 1024 + c0) * KPAD;
    for (int i = tid; i < 1568; i += 256) {
        float v = src[i];
        p[i] = v;
        int c = i / 196, pix = i - c * 196;
        __nv_bfloat16 h = __float2bfloat16(v);
        vhi[(size_t)c * KPAD + pix] = h;
        vlo[(size_t)c * KPAD + pix] = __float2bfloat16(v - __bfloat162float(h));
    }
    if (tid < 72) wsh[tid] = wvl[c0 * 9 + tid];
    if (tid < 8) {
        int c = c0 + tid;
        float s = bn[c] * rsqrtf(bn[3072 + c] + EPSF);
        cs[tid] = s;
        ct[tid] = (bvl[c] - bn[2048 + c]) * s + bn[1024 + c];
    }
    __syncthreads();
    float* dst = g_vloc + (size_t)b * (DHC * NPIX) + (size_t)c0 * NPIX;
    for (int i = tid; i < 1568; i += 256) {
        int c = i / 196, pix = i - c * 196;
        int y = pix / 14, x = pix - y * 14;
        const float* pc = p + c * 196;
        const float* w = wsh + c * 9;
        float acc = 0.f;
#pragma unroll
        for (int dy = 0; dy < 3; dy++) {
            int yy = y + dy - 1;
            if (yy < 0 || yy > 13) continue;
#pragma unroll
            for (int dx = 0; dx < 3; dx++) {
                int xx = x + dx - 1;
                if (xx < 0 || xx > 13) continue;
                acc = fmaf(pc[yy * 14 + xx], w[dy * 3 + dx], acc);
            }
        }
        dst[i] = acc * cs[c] + ct[c];
    }
}

// ------------------------------------------------------------------
// Fused attention v3: logits + TH1 + softmax + TH2 + P export (no AV).
// smem (floats): L 21952 | ab 1568 | ktile 3584 | th 144 = 27248 (108,992 B)
#define ATTN_SMEM_FLOATS (21952 + 1568 + 3584 + 144)

__global__ void __launch_bounds__(256, 2) attn_kernel(
    const float* __restrict__ th1w, const float* __restrict__ th1b,
    const float* __restrict__ th2w, const float* __restrict__ th2b,
    const float* __restrict__ ab,   const int* __restrict__ bidx)
{
    extern __shared__ float sm[];
    float* L    = sm;                 // [(h*14+nl)*196 + m]
    float* abs_ = sm + 21952;         // [h*196 + p]
    float* tile = abs_ + 1568;        // k-tile [c*14+mm] (3584)
    float* th   = tile + 3584;        // th1w(64) th1b(8) th2w(64) th2b(8)

    int tid = threadIdx.x;
    int b = blockIdx.y;
    int n0 = blockIdx.x * 14;
    const float* qbase = g_qkv + (size_t)b * (QKVC * NPIX);
    const float* kbase = qbase + 256 * NPIX;

    for (int i = tid; i < 1568; i += 256) abs_[i] = ab[i];
    if (tid < 64)       th[tid] = th1w[tid];
    else if (tid < 72)  th[tid] = th1b[tid - 64];
    else if (tid < 136) th[tid] = th2w[tid - 72];
    else if (tid < 144) th[tid] = th2b[tid - 136];

    // q straight into registers (coalesced across nl within a warp)
    float qreg[32];
    int h = 0, nl = 0, half = 0;
    bool active = tid < 224;
    if (active) {
        int pair = tid >> 1;
        h = pair / 14; nl = pair - h * 14; half = tid & 1;
#pragma unroll
        for (int d = 0; d < 32; d++)
            qreg[d] = qbase[(size_t)(h * 32 + d) * NPIX + n0 + nl];
    }

    // ---- logits: s*SCALE + ab[h, bidx[n,m]]; 14 m-tiles of width 14 ----
    for (int mt = 0; mt < 14; mt++) {
        int m0 = mt * 14;
        __syncthreads();
        for (int i = tid; i < 3584; i += 256) {
            int c = i / 14, mm = i - c * 14;
            tile[i] = kbase[(size_t)c * NPIX + m0 + mm];
        }
        __syncthreads();
        if (active) {
            const float* kcol = tile + (h * 32) * 14;
            const int* brow = bidx + (size_t)(n0 + nl) * NPIX;
#pragma unroll
            for (int jm = 0; jm < 7; jm++) {
                int mm = half * 7 + jm;
                float s = 0.f;
#pragma unroll
                for (int d = 0; d < 32; d++)
                    s = fmaf(qreg[d], kcol[d * 14 + mm], s);
                int m = m0 + mm;
                L[(h * 14 + nl) * 196 + m] = s * SCALEF + abs_[h * 196 + brow[m]];
            }
        }
    }
    __syncthreads();

    // ---- talking-heads 1 ----
    for (int idx = tid; idx < 2744; idx += 256) {
        int n_ = idx / 196, m = idx - n_ * 196;
        float v[8], o_[8];
#pragma unroll
        for (int hh = 0; hh < 8; hh++) v[hh] = L[(hh * 14 + n_) * 196 + m];
#pragma unroll
        for (int oo = 0; oo < 8; oo++) {
            float s = th[64 + oo];
#pragma unroll
            for (int hh = 0; hh < 8; hh++) s = fmaf(th[oo * 8 + hh], v[hh], s);
            o_[oo] = s;
        }
#pragma unroll
        for (int oo = 0; oo < 8; oo++) L[(oo * 14 + n_) * 196 + m] = o_[oo];
    }
    __syncthreads();

    // ---- softmax over m (warp w owns head o = w) ----
    {
        int w = tid >> 5, lane = tid & 31;
        for (int r = 0; r < 14; r++) {
            float* row = L + (w * 14 + r) * 196;
            float mx = -1e30f;
            for (int m = lane; m < 196; m += 32) mx = fmaxf(mx, row[m]);
#pragma unroll
            for (int off = 16; off > 0; off >>= 1)
                mx = fmaxf(mx, __shfl_xor_sync(0xffffffffu, mx, off));
            float sum = 0.f;
            for (int m = lane; m < 196; m += 32) {
                float e = __expf(row[m] - mx);
                row[m] = e; sum += e;
            }
#pragma unroll
            for (int off = 16; off > 0; off >>= 1)
                sum += __shfl_xor_sync(0xffffffffu, sum, off);
            float inv = 1.f / sum;
            for (int m = lane; m < 196; m += 32) row[m] *= inv;
        }
    }
    __syncthreads();

    // ---- talking-heads 2 ----
    for (int idx = tid; idx < 2744; idx += 256) {
        int n_ = idx / 196, m = idx - n_ * 196;
        float v[8], o_[8];
#pragma unroll
        for (int hh = 0; hh < 8; hh++) v[hh] = L[(hh * 14 + n_) * 196 + m];
#pragma unroll
        for (int oo = 0; oo < 8; oo++) {
            float s = th[136 + oo];
#pragma unroll
            for (int hh = 0; hh < 8; hh++) s = fmaf(th[72 + oo * 8 + hh], v[hh], s);
            o_[oo] = s;
        }
#pragma unroll
        for (int oo = 0; oo < 8; oo++) L[(oo * 14 + n_) * 196 + m] = o_[oo];
    }
    __syncthreads();

    // ---- export P as bf16 hi/lo: row (b*8+o)*196 + n0+nl, col m ----
    for (int i = tid; i < 21952; i += 256) {
        int o = i / 2744;
        int rem = i - o * 2744;
        int n_ = rem / 196, m = rem - n_ * 196;
        float p = L[i];
        __nv_bfloat16 hh = __float2bfloat16(p);
        size_t row = (size_t)(b * 8 + o) * 196 + n0 + n_;
        g_phi[row * KPAD + m] = hh;
        g_plo[row * KPAD + m] = __float2bfloat16(p - __bfloat162float(hh));
    }
}

// ------------------------------------------------------------------
extern "C" void kernel_launch(void* const* d_in, const int* in_sizes, int n_in,
                              void* d_out, int out_size)
{
    const float* x    = (const float*)d_in[0];
    const float* wq   = (const float*)d_in[1];
    const float* bq   = (const float*)d_in[2];
    const float* bnq  = (const float*)d_in[3];
    const float* wk   = (const float*)d_in[4];
    const float* bk   = (const float*)d_in[5];
    const float* bnk  = (const float*)d_in[6];
    const float* wv   = (const float*)d_in[7];
    const float* bv   = (const float*)d_in[8];
    const float* bnv  = (const float*)d_in[9];
    const float* wvl  = (const float*)d_in[10];
    const float* bvl  = (const float*)d_in[11];
    const float* bnvl = (const float*)d_in[12];
    const float* th1w = (const float*)d_in[13];
    const float* th1b = (const float*)d_in[14];
    const float* th2w = (const float*)d_in[15];
    const float* th2b = (const float*)d_in[16];
    const float* wp   = (const float*)d_in[17];
    const float* bp   = (const float*)d_in[18];
    const float* bnp  = (const float*)d_in[19];
    const float* ab   = (const float*)d_in[20];
    const int*   bidx = (const int*)d_in[21];
    float* out = (float*)d_out;

    const int attn_smem = ATTN_SMEM_FLOATS * (int)sizeof(float);
    cudaFuncSetAttribute(attn_kernel,
                         cudaFuncAttributeMaxDynamicSharedMemorySize, attn_smem);
    cudaFuncSetAttribute(gemm_mma_kernel,
                         cudaFuncAttributeMaxDynamicSharedMemorySize, GEMM_SMEM_BYTES);
    cudaFuncSetAttribute(av_mma_kernel,
                         cudaFuncAttributeMaxDynamicSharedMemorySize, GEMM_SMEM_BYTES);

    __nv_bfloat16 *wqkv_hi, *wqkv_lo, *xt_hi, *xt_lo, *wp_hi, *wp_lo, *pt_hi, *pt_lo;
    float *sv, *tv, *qkv_out;
    cudaGetSymbolAddress((void**)&wqkv_hi, g_wqkv_hi);
    cudaGetSymbolAddress((void**)&wqkv_lo, g_wqkv_lo);
    cudaGetSymbolAddress((void**)&xt_hi, g_xt_hi);
    cudaGetSymbolAddress((void**)&xt_lo, g_xt_lo);
    cudaGetSymbolAddress((void**)&wp_hi, g_wp_hi);
    cudaGetSymbolAddress((void**)&wp_lo, g_wp_lo);
    cudaGetSymbolAddress((void**)&pt_hi, g_pt_hi);
    cudaGetSymbolAddress((void**)&pt_lo, g_pt_lo);
    cudaGetSymbolAddress((void**)&sv, g_s);
    cudaGetSymbolAddress((void**)&tv, g_t);
    cudaGetSymbolAddress((void**)&qkv_out, g_qkv);

    // 1. fold BN + split weights + zero k-pads
    prep_kernel<<<2304, 256>>>(wq, wk, wv, wp, bq, bk, bv, bp, bnq, bnk, bnv, bnp);
    // 2. transpose+split x
    xt_cvt_kernel<<<dim3(7, 12, 64), 256>>>(x);
    // 3. fused qkv GEMM (M=1536, K=384)
    gemm_mma_kernel<<<dim3(98, 12), 256, GEMM_SMEM_BYTES>>>(
        wqkv_hi, wqkv_lo, xt_hi, xt_lo, 384, sv, tv, qkv_out, 1536);
    // 4. depthwise conv + BN (+ V bf16 export)
    dwconv_kernel<<<dim3(128, 64), 256>>>(wvl, bvl, bnvl);
    // 5. attention core (logits..TH2, exports P)
    attn_kernel<<<dim3(14, 64), 256, attn_smem>>>(th1w, th1b, th2w, th2b, ab, bidx);
    // 6. AV on tensor cores
    av_mma_kernel<<<dim3(2, 512), 256, GEMM_SMEM_BYTES>>>();
    // 7. transpose+split relu(att + v_local)
    pt_cvt_kernel<<<dim3(7, 32, 64), 256>>>();
    // 8. projection GEMM (M=384, K=1024)
    gemm_mma_kernel<<<dim3(98, 3), 256, GEMM_SMEM_BYTES>>>(
        wp_hi, wp_lo, pt_hi, pt_lo, 1024, sv + 1536, tv + 1536, out, 384);
}

// round 8
// speedup vs baseline: 3.2198x; 1.2155x over previous
#include <cuda_runtime.h>
#include <cuda_bf16.h>
#include <math.h>
#include <stdint.h>

#define EPSF 1e-5f
#define SCALEF 0.17677669529663687f

#define NB   64
#define NPIX 196
#define QKVC 1536
#define DHC  1024
#define NCOL 12544   // 64*196
#define KPAD 256     // padded k (m) dimension for AV mma

// ------------------------------------------------------------------
// scratch (no cudaMalloc allowed)
__device__ float g_qkv [NB * QKVC * NPIX];   // [b][1536][196]; q@0, k@256, v@512
__device__ float g_vloc[NB * DHC * NPIX];    // [b][1024][196]
__device__ float g_logits[512 * 196 * 196];  // [(b*8+h)][n][m] post-bias logits

__device__ __align__(16) __nv_bfloat16 g_xt_hi[NCOL * 384];   // [j][k]
__device__ __align__(16) __nv_bfloat16 g_xt_lo[NCOL * 384];
__device__ __align__(16) __nv_bfloat16 g_pt_hi[NCOL * 1024];  // [j][k]
__device__ __align__(16) __nv_bfloat16 g_pt_lo[NCOL * 1024];
__device__ __align__(16) __nv_bfloat16 g_wqkv_hi[1536 * 384]; // [m][k]
__device__ __align__(16) __nv_bfloat16 g_wqkv_lo[1536 * 384];
__device__ __align__(16) __nv_bfloat16 g_wp_hi[384 * 1024];
__device__ __align__(16) __nv_bfloat16 g_wp_lo[384 * 1024];
// q/k export: [(b*16 + hh)][n][d=32] bf16 hi/lo; hh 0-7 = q heads, 8-15 = k heads
__device__ __align__(16) __nv_bfloat16 g_qkh_hi[NB * 16 * 196 * 32];
__device__ __align__(16) __nv_bfloat16 g_qkh_lo[NB * 16 * 196 * 32];
// attention P (post-softmax/TH2) bf16 hi/lo: [(b*8+o)*196 + n][k=KPAD]
__device__ __align__(16) __nv_bfloat16 g_phi[512 * 196 * KPAD];
__device__ __align__(16) __nv_bfloat16 g_plo[512 * 196 * KPAD];
// raw V bf16 hi/lo: [b][c(1024)][k=KPAD]
__device__ __align__(16) __nv_bfloat16 g_vhi[NB * 1024 * KPAD];
__device__ __align__(16) __nv_bfloat16 g_vlo[NB * 1024 * KPAD];
__device__ float g_s[1920];   // folded BN scale: [0:1536) qkv, [1536:1920) proj
__device__ float g_t[1920];   // folded BN shift

// ------------------------------------------------------------------
static __device__ __forceinline__ uint32_t s2u(const void* p) {
    uint32_t a;
    asm("{ .reg .u64 t; cvta.to.shared.u64 t, %1; cvt.u32.u64 %0, t; }"
        : "=r"(a) : "l"(p));
    return a;
}

static __device__ __forceinline__ void cp_async16(uint32_t saddr, const void* gptr) {
    asm volatile("cp.async.cg.shared.global [%0], [%1], 16;"
                 :: "r"(saddr), "l"(gptr) : "memory");
}

static __device__ __forceinline__ void cp_async16_zf(uint32_t saddr, const void* gptr, int valid) {
    int sz = valid ? 16 : 0;
    asm volatile("cp.async.cg.shared.global [%0], [%1], 16, %2;"
                 :: "r"(saddr), "l"(gptr), "r"(sz) : "memory");
}

static __device__ __forceinline__ void ldmat_x4(
    uint32_t& r0, uint32_t& r1, uint32_t& r2, uint32_t& r3, uint32_t addr)
{
    asm volatile("ldmatrix.sync.aligned.m8n8.x4.shared.b16 {%0,%1,%2,%3}, [%4];"
                 : "=r"(r0), "=r"(r1), "=r"(r2), "=r"(r3) : "r"(addr));
}

static __device__ __forceinline__ void mma_bf16(
    float& d0, float& d1, float& d2, float& d3,
    uint32_t a0, uint32_t a1, uint32_t a2, uint32_t a3,
    uint32_t b0, uint32_t b1)
{
    asm volatile(
        "mma.sync.aligned.m16n8k16.row.col.f32.bf16.bf16.f32 "
        "{%0,%1,%2,%3}, {%4,%5,%6,%7}, {%8,%9}, {%0,%1,%2,%3};"
        : "+f"(d0), "+f"(d1), "+f"(d2), "+f"(d3)
        : "r"(a0), "r"(a1), "r"(a2), "r"(a3), "r"(b0), "r"(b1));
}

// ------------------------------------------------------------------
// Prep: fold BN; split weights into bf16 hi/lo; zero static k-pads of P/V exports.
__global__ void __launch_bounds__(256) prep_kernel(
    const float* __restrict__ wq, const float* __restrict__ wk,
    const float* __restrict__ wv, const float* __restrict__ wp,
    const float* __restrict__ bq, const float* __restrict__ bk,
    const float* __restrict__ bv, const float* __restrict__ bp,
    const float* __restrict__ bnq, const float* __restrict__ bnk,
    const float* __restrict__ bnv, const float* __restrict__ bnp)
{
    int idx = blockIdx.x * 256 + threadIdx.x;
    int stride = gridDim.x * 256;
    const __nv_bfloat16 z = __float2bfloat16(0.f);

    for (int i = idx; i < 1536 * 384; i += stride) {
        int m = i / 384;
        float w = (m < 256) ? wq[i]
                : (m < 512) ? wk[i - 256 * 384]
                            : wv[i - 512 * 384];
        __nv_bfloat16 h = __float2bfloat16(w);
        g_wqkv_hi[i] = h;
        g_wqkv_lo[i] = __float2bfloat16(w - __bfloat162float(h));
    }
    for (int i = idx; i < 384 * 1024; i += stride) {
        float w = wp[i];
        __nv_bfloat16 h = __float2bfloat16(w);
        g_wp_hi[i] = h;
        g_wp_lo[i] = __float2bfloat16(w - __bfloat162float(h));
    }
    // zero P k-pad (cols 196..255 of every row)
    for (long i = idx; i < (long)512 * 196 * 60; i += stride) {
        long r = i / 60; int c = 196 + (int)(i % 60);
        g_phi[r * KPAD + c] = z;
        g_plo[r * KPAD + c] = z;
    }
    // zero V k-pad
    for (long i = idx; i < (long)NB * 1024 * 60; i += stride) {
        long r = i / 60; int c = 196 + (int)(i % 60);
        g_vhi[r * KPAD + c] = z;
        g_vlo[r * KPAD + c] = z;
    }
    if (idx < 1920) {
        const float* bn; const float* bias; int c; int C;
        if (idx < 256)       { bn = bnq; bias = bq; c = idx;        C = 256; }
        else if (idx < 512)  { bn = bnk; bias = bk; c = idx - 256;  C = 256; }
        else if (idx < 1536) { bn = bnv; bias = bv; c = idx - 512;  C = 1024; }
        else                 { bn = bnp; bias = bp; c = idx - 1536; C = 384; }
        float s = bn[c] * rsqrtf(bn[3 * C + c] + EPSF);
        g_s[idx] = s;
        g_t[idx] = (bias[c] - bn[2 * C + c]) * s + bn[C + c];
    }
}

// ------------------------------------------------------------------
// Transpose+split x: [b][384][196] -> Xt[j=b*196+n][k=c] bf16 hi/lo
__global__ void __launch_bounds__(256) xt_cvt_kernel(const float* __restrict__ X)
{
    __shared__ float t[32][29];
    int b = blockIdx.z, c0 = blockIdx.y * 32, n0 = blockIdx.x * 28;
    int tid = threadIdx.x;
    const float* src = X + ((size_t)b * 384 + c0) * 196 + n0;
    for (int i = tid; i < 32 * 28; i += 256) {
        int ci = i / 28, nj = i - ci * 28;
        t[ci][nj] = src[(size_t)ci * 196 + nj];
    }
    __syncthreads();
    for (int i = tid; i < 32 * 28; i += 256) {
        int nj = i >> 5, ci = i & 31;
        float v = t[ci][nj];
        __nv_bfloat16 h = __float2bfloat16(v);
        size_t o = ((size_t)(b * 196 + n0 + nj)) * 384 + c0 + ci;
        g_xt_hi[o] = h;
        g_xt_lo[o] = __float2bfloat16(v - __bfloat162float(h));
    }
}

// ------------------------------------------------------------------
// bf16 mma.sync GEMM, 3-term compensation fused per K-chunk.
// Optional epilogue export of BN'd q/k channels (oc<512) as bf16 hi/lo.
#define GEMM_STAGE_BYTES 65536
#define GEMM_SMEM_BYTES  (2 * GEMM_STAGE_BYTES)

__global__ void __launch_bounds__(256) gemm_mma_kernel(
    const __nv_bfloat16* __restrict__ Ahi, const __nv_bfloat16* __restrict__ Alo,
    const __nv_bfloat16* __restrict__ Bhi, const __nv_bfloat16* __restrict__ Blo,
    int K, const float* __restrict__ svec, const float* __restrict__ tvec,
    float* __restrict__ out, int Cout,
    __nv_bfloat16* __restrict__ qk_hi, __nv_bfloat16* __restrict__ qk_lo)
{
    extern __shared__ __align__(1024) char smem[];
    const uint32_t sb = s2u(smem);
    const int tid = threadIdx.x;
    const int wid = tid >> 5, lane = tid & 31;
    const int warp_m = wid & 1;
    const int warp_n = wid >> 1;
    const int m0 = blockIdx.y * 128;
    const int j0 = blockIdx.x * 128;
    const int nk = K >> 6;
    const bool doexp = (qk_hi != nullptr) && (m0 < 512);

    float acc[4][4][4];
#pragma unroll
    for (int i = 0; i < 4; i++)
#pragma unroll
        for (int j = 0; j < 4; j++)
#pragma unroll
            for (int c = 0; c < 4; c++) acc[i][j][c] = 0.f;

    const int lrow = lane & 15;
    const uint32_t lkoff = (uint32_t)((lane >> 4) << 4);

    auto issue = [&](int kb, uint32_t stage_off) {
#pragma unroll
        for (int i = 0; i < 4; i++) {
            int q = tid + (i << 8);
            int row = q >> 3, k8 = q & 7;
            uint32_t off = (uint32_t)(row * 128 + k8 * 16);
            uint32_t sw = off ^ ((off >> 3) & 0x70);
            size_t ga = (size_t)(m0 + row) * K + kb + (k8 << 3);
            size_t gb = (size_t)(j0 + row) * K + kb + (k8 << 3);
            cp_async16(sb + stage_off + sw,           Ahi + ga);
            cp_async16(sb + stage_off + 16384u + sw,  Alo + ga);
            cp_async16(sb + stage_off + 32768u + sw,  Bhi + gb);
            cp_async16(sb + stage_off + 49152u + sw,  Blo + gb);
        }
        asm volatile("cp.async.commit_group;" ::: "memory");
    };

    issue(0, 0u);
    if (nk > 1) issue(64, GEMM_STAGE_BYTES);

    for (int ch = 0; ch < nk; ch++) {
        if (ch + 1 < nk) asm volatile("cp.async.wait_group 1;" ::: "memory");
        else             asm volatile("cp.async.wait_group 0;" ::: "memory");
        __syncthreads();

        const uint32_t buf = (ch & 1) ? (uint32_t)GEMM_STAGE_BYTES : 0u;
#pragma unroll
        for (int ks = 0; ks < 4; ks++) {
            uint32_t bh[4][2], bl[4][2];
#pragma unroll
            for (int p = 0; p < 2; p++) {
                uint32_t off = (uint32_t)((warp_n * 32 + p * 16 + lrow) * 128)
                             + (uint32_t)(ks * 32) + lkoff;
                uint32_t sw = off ^ ((off >> 3) & 0x70);
                uint32_t r0, r1, r2, r3;
                ldmat_x4(r0, r1, r2, r3, sb + buf + 32768u + sw);
                bh[p * 2 + 0][0] = r0; bh[p * 2 + 1][0] = r1;
                bh[p * 2 + 0][1] = r2; bh[p * 2 + 1][1] = r3;
                ldmat_x4(r0, r1, r2, r3, sb + buf + 49152u + sw);
                bl[p * 2 + 0][0] = r0; bl[p * 2 + 1][0] = r1;
                bl[p * 2 + 0][1] = r2; bl[p * 2 + 1][1] = r3;
            }
#pragma unroll
            for (int mt = 0; mt < 4; mt++) {
                uint32_t off = (uint32_t)((warp_m * 64 + mt * 16 + lrow) * 128)
                             + (uint32_t)(ks * 32) + lkoff;
                uint32_t sw = off ^ ((off >> 3) & 0x70);
                uint32_t a0, a1, a2, a3;
                ldmat_x4(a0, a1, a2, a3, sb + buf + sw);
#pragma unroll
                for (int nt = 0; nt < 4; nt++)
                    mma_bf16(acc[mt][nt][0], acc[mt][nt][1],
                             acc[mt][nt][2], acc[mt][nt][3],
                             a0, a1, a2, a3, bh[nt][0], bh[nt][1]);
#pragma unroll
                for (int nt = 0; nt < 4; nt++)
                    mma_bf16(acc[mt][nt][0], acc[mt][nt][1],
                             acc[mt][nt][2], acc[mt][nt][3],
                             a0, a1, a2, a3, bl[nt][0], bl[nt][1]);
                ldmat_x4(a0, a1, a2, a3, sb + buf + 16384u + sw);
#pragma unroll
                for (int nt = 0; nt < 4; nt++)
                    mma_bf16(acc[mt][nt][0], acc[mt][nt][1],
                             acc[mt][nt][2], acc[mt][nt][3],
                             a0, a1, a2, a3, bh[nt][0], bh[nt][1]);
            }
        }

        if (ch + 2 < nk) {
            __syncthreads();
            issue((ch + 2) << 6, buf);
        }
    }

    const int group = lane >> 2, tig = lane & 3;
#pragma unroll
    for (int mt = 0; mt < 4; mt++) {
        int oc0 = m0 + warp_m * 64 + mt * 16 + group;
        int oc1 = oc0 + 8;
        float s0 = svec[oc0], t0 = tvec[oc0];
        float s1 = svec[oc1], t1 = tvec[oc1];
#pragma unroll
        for (int nt = 0; nt < 4; nt++) {
            int j = j0 + warp_n * 32 + nt * 8 + tig * 2;
            int b = j / 196, n = j - b * 196;
            float* p0 = out + ((size_t)b * Cout + oc0) * 196 + n;
            float* p1 = out + ((size_t)b * Cout + oc1) * 196 + n;
            float v00 = acc[mt][nt][0] * s0 + t0;
            float v01 = acc[mt][nt][1] * s0 + t0;
            float v10 = acc[mt][nt][2] * s1 + t1;
            float v11 = acc[mt][nt][3] * s1 + t1;
            p0[0] = v00; p0[1] = v01;
            p1[0] = v10; p1[1] = v11;
            if (doexp) {
                size_t r0 = (((size_t)(b * 16) + (oc0 >> 5)) * 196 + n) * 32 + (oc0 & 31);
                size_t r1 = (((size_t)(b * 16) + (oc1 >> 5)) * 196 + n) * 32 + (oc1 & 31);
                __nv_bfloat16 h;
                h = __float2bfloat16(v00); qk_hi[r0] = h;
                qk_lo[r0] = __float2bfloat16(v00 - __bfloat162float(h));
                h = __float2bfloat16(v01); qk_hi[r0 + 32] = h;
                qk_lo[r0 + 32] = __float2bfloat16(v01 - __bfloat162float(h));
                h = __float2bfloat16(v10); qk_hi[r1] = h;
                qk_lo[r1] = __float2bfloat16(v10 - __bfloat162float(h));
                h = __float2bfloat16(v11); qk_hi[r1 + 32] = h;
                qk_lo[r1 + 32] = __float2bfloat16(v11 - __bfloat162float(h));
            }
        }
    }
}

// ------------------------------------------------------------------
// QK logits mma: L[n,m] = SCALE * sum_d q[n,d]*k[m,d] + ab[h, bidx[n,m]].
// grid (2 n-tiles, 2 m-tiles, 512 bh). K=32, single stage, 3-term.
#define QK_SMEM_BYTES 65536

__global__ void __launch_bounds__(256) qk_mma_kernel(
    const float* __restrict__ ab, const int* __restrict__ bidx)
{
    extern __shared__ __align__(1024) char smem[];
    const uint32_t sb = s2u(smem);
    const int tid = threadIdx.x;
    const int wid = tid >> 5, lane = tid & 31;
    const int warp_m = wid & 1;
    const int warp_n = wid >> 1;
    const int bh = blockIdx.z;
    const int b = bh >> 3, h = bh & 7;
    const int n0 = blockIdx.x * 128;
    const int m0c = blockIdx.y * 128;

    const __nv_bfloat16* Qhi = g_qkh_hi + (size_t)(b * 16 + h) * 196 * 32;
    const __nv_bfloat16* Qlo = g_qkh_lo + (size_t)(b * 16 + h) * 196 * 32;
    const __nv_bfloat16* Khi = g_qkh_hi + (size_t)(b * 16 + 8 + h) * 196 * 32;
    const __nv_bfloat16* Klo = g_qkh_lo + (size_t)(b * 16 + 8 + h) * 196 * 32;

    // load tiles (rows padded to 128B in smem; only first 64B used)
#pragma unroll
    for (int t = 0; t < 2; t++) {
        int q = tid + (t << 8);
        int row = q >> 2, k8 = q & 3;
        uint32_t off = (uint32_t)(row * 128 + k8 * 16);
        uint32_t sw = off ^ ((off >> 3) & 0x70);
        int nr = n0 + row;
        int vq = nr < 196;
        size_t gq = vq ? ((size_t)nr * 32 + (k8 << 3)) : 0;
        cp_async16_zf(sb + sw,           Qhi + gq, vq);
        cp_async16_zf(sb + 16384u + sw,  Qlo + gq, vq);
        int mr = m0c + row;
        int vk = mr < 196;
        size_t gk = vk ? ((size_t)mr * 32 + (k8 << 3)) : 0;
        cp_async16_zf(sb + 32768u + sw,  Khi + gk, vk);
        cp_async16_zf(sb + 49152u + sw,  Klo + gk, vk);
    }
    asm volatile("cp.async.commit_group;" ::: "memory");
    asm volatile("cp.async.wait_group 0;" ::: "memory");
    __syncthreads();

    float acc[4][4][4];
#pragma unroll
    for (int i = 0; i < 4; i++)
#pragma unroll
        for (int j = 0; j < 4; j++)
#pragma unroll
            for (int c = 0; c < 4; c++) acc[i][j][c] = 0.f;

    const int lrow = lane & 15;
    const uint32_t lkoff = (uint32_t)((lane >> 4) << 4);

#pragma unroll
    for (int ks = 0; ks < 2; ks++) {
        uint32_t bh_[4][2], bl_[4][2];
#pragma unroll
        for (int p = 0; p < 2; p++) {
            uint32_t off = (uint32_t)((warp_n * 32 + p * 16 + lrow) * 128)
                         + (uint32_t)(ks * 32) + lkoff;
            uint32_t sw = off ^ ((off >> 3) & 0x70);
            uint32_t r0, r1, r2, r3;
            ldmat_x4(r0, r1, r2, r3, sb + 32768u + sw);
            bh_[p * 2 + 0][0] = r0; bh_[p * 2 + 1][0] = r1;
            bh_[p * 2 + 0][1] = r2; bh_[p * 2 + 1][1] = r3;
            ldmat_x4(r0, r1, r2, r3, sb + 49152u + sw);
            bl_[p * 2 + 0][0] = r0; bl_[p * 2 + 1][0] = r1;
            bl_[p * 2 + 0][1] = r2; bl_[p * 2 + 1][1] = r3;
        }
#pragma unroll
        for (int mt = 0; mt < 4; mt++) {
            uint32_t off = (uint32_t)((warp_m * 64 + mt * 16 + lrow) * 128)
                         + (uint32_t)(ks * 32) + lkoff;
            uint32_t sw = off ^ ((off >> 3) & 0x70);
            uint32_t a0, a1, a2, a3;
            ldmat_x4(a0, a1, a2, a3, sb + sw);
#pragma unroll
            for (int nt = 0; nt < 4; nt++)
                mma_bf16(acc[mt][nt][0], acc[mt][nt][1],
                         acc[mt][nt][2], acc[mt][nt][3],
                         a0, a1, a2, a3, bh_[nt][0], bh_[nt][1]);
#pragma unroll
            for (int nt = 0; nt < 4; nt++)
                mma_bf16(acc[mt][nt][0], acc[mt][nt][1],
                         acc[mt][nt][2], acc[mt][nt][3],
                         a0, a1, a2, a3, bl_[nt][0], bl_[nt][1]);
            ldmat_x4(a0, a1, a2, a3, sb + 16384u + sw);
#pragma unroll
            for (int nt = 0; nt < 4; nt++)
                mma_bf16(acc[mt][nt][0], acc[mt][nt][1],
                         acc[mt][nt][2], acc[mt][nt][3],
                         a0, a1, a2, a3, bh_[nt][0], bh_[nt][1]);
        }
    }

    // epilogue: scale + positional bias, write fp32 logits
    const int group = lane >> 2, tig = lane & 3;
    const float* abh = ab + h * 196;
    float* lbase = g_logits + (size_t)bh * 196 * 196;
#pragma unroll
    for (int mt = 0; mt < 4; mt++) {
        int nr0 = n0 + warp_m * 64 + mt * 16 + group;
        int nr1 = nr0 + 8;
#pragma unroll
        for (int nt = 0; nt < 4; nt++) {
            int m = m0c + warp_n * 32 + nt * 8 + tig * 2;
            if (m < 196) {
                if (nr0 < 196) {
                    const int* br = bidx + (size_t)nr0 * 196;
                    lbase[(size_t)nr0 * 196 + m]     = acc[mt][nt][0] * SCALEF + abh[br[m]];
                    lbase[(size_t)nr0 * 196 + m + 1] = acc[mt][nt][1] * SCALEF + abh[br[m + 1]];
                }
                if (nr1 < 196) {
                    const int* br = bidx + (size_t)nr1 * 196;
                    lbase[(size_t)nr1 * 196 + m]     = acc[mt][nt][2] * SCALEF + abh[br[m]];
                    lbase[(size_t)nr1 * 196 + m + 1] = acc[mt][nt][3] * SCALEF + abh[br[m + 1]];
                }
            }
        }
    }
}

// ------------------------------------------------------------------
// AV batched mma: D[e,n] = sum_m V[b,o*128+e,m] * P[bo,n,m], 3-term bf16.
// Fused epilogue: relu(D + v_local) -> bf16 hi/lo into g_pt (proj input).
__global__ void __launch_bounds__(256) av_mma_kernel()
{
    extern __shared__ __align__(1024) char smem[];
    const uint32_t sb = s2u(smem);
    const int tid = threadIdx.x;
    const int wid = tid >> 5, lane = tid & 31;
    const int warp_m = wid & 1;
    const int warp_n = wid >> 1;
    const int bo = blockIdx.y;
    const int b  = bo >> 3, o = bo & 7;
    const int j0 = blockIdx.x * 128;
    const int nk = 4;

    const __nv_bfloat16* Ahi = g_vhi + ((size_t)b * 1024 + o * 128) * KPAD;
    const __nv_bfloat16* Alo = g_vlo + ((size_t)b * 1024 + o * 128) * KPAD;
    const __nv_bfloat16* Bhi = g_phi + ((size_t)bo * 196) * KPAD;
    const __nv_bfloat16* Blo = g_plo + ((size_t)bo * 196) * KPAD;

    float acc[4][4][4];
#pragma unroll
    for (int i = 0; i < 4; i++)
#pragma unroll
        for (int j = 0; j < 4; j++)
#pragma unroll
            for (int c = 0; c < 4; c++) acc[i][j][c] = 0.f;

    const int lrow = lane & 15;
    const uint32_t lkoff = (uint32_t)((lane >> 4) << 4);

    auto issue = [&](int kb, uint32_t stage_off) {
#pragma unroll
        for (int i = 0; i < 4; i++) {
            int q = tid + (i << 8);
            int row = q >> 3, k8 = q & 7;
            uint32_t off = (uint32_t)(row * 128 + k8 * 16);
            uint32_t sw = off ^ ((off >> 3) & 0x70);
            size_t ga = (size_t)row * KPAD + kb + (k8 << 3);
            cp_async16(sb + stage_off + sw,          Ahi + ga);
            cp_async16(sb + stage_off + 16384u + sw, Alo + ga);
            int jrow = j0 + row;
            int valid = (jrow < 196);
            size_t gb = valid ? ((size_t)jrow * KPAD + kb + (k8 << 3)) : 0;
            cp_async16_zf(sb + stage_off + 32768u + sw, Bhi + gb, valid);
            cp_async16_zf(sb + stage_off + 49152u + sw, Blo + gb, valid);
        }
        asm volatile("cp.async.commit_group;" ::: "memory");
    };

    issue(0, 0u);
    issue(64, GEMM_STAGE_BYTES);

    for (int ch = 0; ch < nk; ch++) {
        if (ch + 1 < nk) asm volatile("cp.async.wait_group 1;" ::: "memory");
        else             asm volatile("cp.async.wait_group 0;" ::: "memory");
        __syncthreads();

        const uint32_t buf = (ch & 1) ? (uint32_t)GEMM_STAGE_BYTES : 0u;
#pragma unroll
        for (int ks = 0; ks < 4; ks++) {
            uint32_t bh[4][2], bl[4][2];
#pragma unroll
            for (int p = 0; p < 2; p++) {
                uint32_t off = (uint32_t)((warp_n * 32 + p * 16 + lrow) * 128)
                             + (uint32_t)(ks * 32) + lkoff;
                uint32_t sw = off ^ ((off >> 3) & 0x70);
                uint32_t r0, r1, r2, r3;
                ldmat_x4(r0, r1, r2, r3, sb + buf + 32768u + sw);
                bh[p * 2 + 0][0] = r0; bh[p * 2 + 1][0] = r1;
                bh[p * 2 + 0][1] = r2; bh[p * 2 + 1][1] = r3;
                ldmat_x4(r0, r1, r2, r3, sb + buf + 49152u + sw);
                bl[p * 2 + 0][0] = r0; bl[p * 2 + 1][0] = r1;
                bl[p * 2 + 0][1] = r2; bl[p * 2 + 1][1] = r3;
            }
#pragma unroll
            for (int mt = 0; mt < 4; mt++) {
                uint32_t off = (uint32_t)((warp_m * 64 + mt * 16 + lrow) * 128)
                             + (uint32_t)(ks * 32) + lkoff;
                uint32_t sw = off ^ ((off >> 3) & 0x70);
                uint32_t a0, a1, a2, a3;
                ldmat_x4(a0, a1, a2, a3, sb + buf + sw);
#pragma unroll
                for (int nt = 0; nt < 4; nt++)
                    mma_bf16(acc[mt][nt][0], acc[mt][nt][1],
                             acc[mt][nt][2], acc[mt][nt][3],
                             a0, a1, a2, a3, bh[nt][0], bh[nt][1]);
#pragma unroll
                for (int nt = 0; nt < 4; nt++)
                    mma_bf16(acc[mt][nt][0], acc[mt][nt][1],
                             acc[mt][nt][2], acc[mt][nt][3],
                             a0, a1, a2, a3, bl[nt][0], bl[nt][1]);
                ldmat_x4(a0, a1, a2, a3, sb + buf + 16384u + sw);
#pragma unroll
                for (int nt = 0; nt < 4; nt++)
                    mma_bf16(acc[mt][nt][0], acc[mt][nt][1],
                             acc[mt][nt][2], acc[mt][nt][3],
                             a0, a1, a2, a3, bh[nt][0], bh[nt][1]);
            }
        }

        if (ch + 2 < nk) {
            __syncthreads();
            issue((ch + 2) << 6, buf);
        }
    }

    // fused epilogue: relu(acc + v_local) -> bf16 hi/lo into g_pt
    const int group = lane >> 2, tig = lane & 3;
    const float* vlbase = g_vloc + ((size_t)b * 1024 + o * 128) * NPIX;
#pragma unroll
    for (int mt = 0; mt < 4; mt++) {
        int e0 = warp_m * 64 + mt * 16 + group;
        int e1 = e0 + 8;
#pragma unroll
        for (int nt = 0; nt < 4; nt++) {
            int j = j0 + warp_n * 32 + nt * 8 + tig * 2;
            if (j < 196) {
                float v00 = fmaxf(acc[mt][nt][0] + vlbase[(size_t)e0 * NPIX + j],     0.f);
                float v01 = fmaxf(acc[mt][nt][1] + vlbase[(size_t)e0 * NPIX + j + 1], 0.f);
                float v10 = fmaxf(acc[mt][nt][2] + vlbase[(size_t)e1 * NPIX + j],     0.f);
                float v11 = fmaxf(acc[mt][nt][3] + vlbase[(size_t)e1 * NPIX + j + 1], 0.f);
                size_t r00 = ((size_t)(b * 196 + j))     * 1024 + o * 128 + e0;
                size_t r01 = ((size_t)(b * 196 + j + 1)) * 1024 + o * 128 + e0;
                __nv_bfloat16 h;
                h = __float2bfloat16(v00); g_pt_hi[r00] = h;
                g_pt_lo[r00] = __float2bfloat16(v00 - __bfloat162float(h));
                h = __float2bfloat16(v01); g_pt_hi[r01] = h;
                g_pt_lo[r01] = __float2bfloat16(v01 - __bfloat162float(h));
                h = __float2bfloat16(v10); g_pt_hi[r00 + 8] = h;
                g_pt_lo[r00 + 8] = __float2bfloat16(v10 - __bfloat162float(h));
                h = __float2bfloat16(v11); g_pt_hi[r01 + 8] = h;
                g_pt_lo[r01 + 8] = __float2bfloat16(v11 - __bfloat162float(h));
            }
        }
    }
}

// ------------------------------------------------------------------
// Depthwise 3x3 'SAME' conv on v + BN -> g_vloc; also exports raw V as bf16 hi/lo.
__global__ void __launch_bounds__(256) dwconv_kernel(
    const float* __restrict__ wvl, const float* __restrict__ bvl,
    const float* __restrict__ bn)
{
    int c0 = blockIdx.x * 8, b = blockIdx.y;
    __shared__ float p[8 * 196];
    __shared__ float wsh[72];
    __shared__ float cs[8], ct[8];
    int tid = threadIdx.x;
    const float* src = g_qkv + (size_t)b * (QKVC * NPIX) + (size_t)(512 + c0) * NPIX;
    __nv_bfloat16* vhi = g_vhi + ((size_t)b * 1024 + c0) * KPAD;
    __nv_bfloat16* vlo = g_vlo + ((size_t)b * 1024 + c0) * KPAD;
    for (int i = tid; i < 1568; i += 256) {
        float v = src[i];
        p[i] = v;
        int c = i / 196, pix = i - c * 196;
        __nv_bfloat16 h = __float2bfloat16(v);
        vhi[(size_t)c * KPAD + pix] = h;
        vlo[(size_t)c * KPAD + pix] = __float2bfloat16(v - __bfloat162float(h));
    }
    if (tid < 72) wsh[tid] = wvl[c0 * 9 + tid];
    if (tid < 8) {
        int c = c0 + tid;
        float s = bn[c] * rsqrtf(bn[3072 + c] + EPSF);
        cs[tid] = s;
        ct[tid] = (bvl[c] - bn[2048 + c]) * s + bn[1024 + c];
    }
    __syncthreads();
    float* dst = g_vloc + (size_t)b * (DHC * NPIX) + (size_t)c0 * NPIX;
    for (int i = tid; i < 1568; i += 256) {
        int c = i / 196, pix = i - c * 196;
        int y = pix / 14, x = pix - y * 14;
        const float* pc = p + c * 196;
        const float* w = wsh + c * 9;
        float acc = 0.f;
#pragma unroll
        for (int dy = 0; dy < 3; dy++) {
            int yy = y + dy - 1;
            if (yy < 0 || yy > 13) continue;
#pragma unroll
            for (int dx = 0; dx < 3; dx++) {
                int xx = x + dx - 1;
                if (xx < 0 || xx > 13) continue;
                acc = fmaf(pc[yy * 14 + xx], w[dy * 3 + dx], acc);
            }
        }
        dst[i] = acc * cs[c] + ct[c];
    }
}

// ------------------------------------------------------------------
// Attention core v4: TH1 (reads g_logits) + softmax + TH2 + P export.
// smem (floats): L 21952 | th 144 = 22096 (88,384 B) -> 2 blocks/SM.
#define ATTN_SMEM_FLOATS (21952 + 144)

__global__ void __launch_bounds__(256, 2) attn_kernel(
    const float* __restrict__ th1w, const float* __restrict__ th1b,
    const float* __restrict__ th2w, const float* __restrict__ th2b)
{
    extern __shared__ float sm[];
    float* L  = sm;                 // [(h*14+nl)*196 + m]
    float* th = sm + 21952;         // th1w(64) th1b(8) th2w(64) th2b(8)

    int tid = threadIdx.x;
    int b = blockIdx.y;
    int n0 = blockIdx.x * 14;

    if (tid < 64)       th[tid] = th1w[tid];
    else if (tid < 72)  th[tid] = th1b[tid - 64];
    else if (tid < 136) th[tid] = th2w[tid - 72];
    else if (tid < 144) th[tid] = th2b[tid - 136];
    __syncthreads();

    // ---- talking-heads 1, fused with global logits load ----
    const float* lgbase = g_logits + (size_t)(b * 8) * 196 * 196;
    for (int idx = tid; idx < 2744; idx += 256) {
        int n_ = idx / 196, m = idx - n_ * 196;
        size_t rowoff = (size_t)(n0 + n_) * 196 + m;
        float v[8], o_[8];
#pragma unroll
        for (int hh = 0; hh < 8; hh++)
            v[hh] = lgbase[(size_t)hh * 196 * 196 + rowoff];
#pragma unroll
        for (int oo = 0; oo < 8; oo++) {
            float s = th[64 + oo];
#pragma unroll
            for (int hh = 0; hh < 8; hh++) s = fmaf(th[oo * 8 + hh], v[hh], s);
            o_[oo] = s;
        }
#pragma unroll
        for (int oo = 0; oo < 8; oo++) L[(oo * 14 + n_) * 196 + m] = o_[oo];
    }
    __syncthreads();

    // ---- softmax over m (warp w owns head o = w) ----
    {
        int w = tid >> 5, lane = tid & 31;
        for (int r = 0; r < 14; r++) {
            float* row = L + (w * 14 + r) * 196;
            float mx = -1e30f;
            for (int m = lane; m < 196; m += 32) mx = fmaxf(mx, row[m]);
#pragma unroll
            for (int off = 16; off > 0; off >>= 1)
                mx = fmaxf(mx, __shfl_xor_sync(0xffffffffu, mx, off));
            float sum = 0.f;
            for (int m = lane; m < 196; m += 32) {
                float e = __expf(row[m] - mx);
                row[m] = e; sum += e;
            }
#pragma unroll
            for (int off = 16; off > 0; off >>= 1)
                sum += __shfl_xor_sync(0xffffffffu, sum, off);
            float inv = 1.f / sum;
            for (int m = lane; m < 196; m += 32) row[m] *= inv;
        }
    }
    __syncthreads();

    // ---- talking-heads 2 ----
    for (int idx = tid; idx < 2744; idx += 256) {
        int n_ = idx / 196, m = idx - n_ * 196;
        float v[8], o_[8];
#pragma unroll
        for (int hh = 0; hh < 8; hh++) v[hh] = L[(hh * 14 + n_) * 196 + m];
#pragma unroll
        for (int oo = 0; oo < 8; oo++) {
            float s = th[136 + oo];
#pragma unroll
            for (int hh = 0; hh < 8; hh++) s = fmaf(th[72 + oo * 8 + hh], v[hh], s);
            o_[oo] = s;
        }
#pragma unroll
        for (int oo = 0; oo < 8; oo++) L[(oo * 14 + n_) * 196 + m] = o_[oo];
    }
    __syncthreads();

    // ---- export P as bf16 hi/lo ----
    for (int i = tid; i < 21952; i += 256) {
        int o = i / 2744;
        int rem = i - o * 2744;
        int n_ = rem / 196, m = rem - n_ * 196;
        float p = L[i];
        __nv_bfloat16 hh = __float2bfloat16(p);
        size_t row = (size_t)(b * 8 + o) * 196 + n0 + n_;
        g_phi[row * KPAD + m] = hh;
        g_plo[row * KPAD + m] = __float2bfloat16(p - __bfloat162float(hh));
    }
}

// ------------------------------------------------------------------
extern "C" void kernel_launch(void* const* d_in, const int* in_sizes, int n_in,
                              void* d_out, int out_size)
{
    const float* x    = (const float*)d_in[0];
    const float* wq   = (const float*)d_in[1];
    const float* bq   = (const float*)d_in[2];
    const float* bnq  = (const float*)d_in[3];
    const float* wk   = (const float*)d_in[4];
    const float* bk   = (const float*)d_in[5];
    const float* bnk  = (const float*)d_in[6];
    const float* wv   = (const float*)d_in[7];
    const float* bv   = (const float*)d_in[8];
    const float* bnv  = (const float*)d_in[9];
    const float* wvl  = (const float*)d_in[10];
    const float* bvl  = (const float*)d_in[11];
    const float* bnvl = (const float*)d_in[12];
    const float* th1w = (const float*)d_in[13];
    const float* th1b = (const float*)d_in[14];
    const float* th2w = (const float*)d_in[15];
    const float* th2b = (const float*)d_in[16];
    const float* wp   = (const float*)d_in[17];
    const float* bp   = (const float*)d_in[18];
    const float* bnp  = (const float*)d_in[19];
    const float* ab   = (const float*)d_in[20];
    const int*   bidx = (const int*)d_in[21];
    float* out = (float*)d_out;

    const int attn_smem = ATTN_SMEM_FLOATS * (int)sizeof(float);
    cudaFuncSetAttribute(attn_kernel,
                         cudaFuncAttributeMaxDynamicSharedMemorySize, attn_smem);
    cudaFuncSetAttribute(gemm_mma_kernel,
                         cudaFuncAttributeMaxDynamicSharedMemorySize, GEMM_SMEM_BYTES);
    cudaFuncSetAttribute(av_mma_kernel,
                         cudaFuncAttributeMaxDynamicSharedMemorySize, GEMM_SMEM_BYTES);
    cudaFuncSetAttribute(qk_mma_kernel,
                         cudaFuncAttributeMaxDynamicSharedMemorySize, QK_SMEM_BYTES);

    __nv_bfloat16 *wqkv_hi, *wqkv_lo, *xt_hi, *xt_lo, *wp_hi, *wp_lo, *pt_hi, *pt_lo;
    __nv_bfloat16 *qkh_hi, *qkh_lo;
    float *sv, *tv, *qkv_out;
    cudaGetSymbolAddress((void**)&wqkv_hi, g_wqkv_hi);
    cudaGetSymbolAddress((void**)&wqkv_lo, g_wqkv_lo);
    cudaGetSymbolAddress((void**)&xt_hi, g_xt_hi);
    cudaGetSymbolAddress((void**)&xt_lo, g_xt_lo);
    cudaGetSymbolAddress((void**)&wp_hi, g_wp_hi);
    cudaGetSymbolAddress((void**)&wp_lo, g_wp_lo);
    cudaGetSymbolAddress((void**)&pt_hi, g_pt_hi);
    cudaGetSymbolAddress((void**)&pt_lo, g_pt_lo);
    cudaGetSymbolAddress((void**)&qkh_hi, g_qkh_hi);
    cudaGetSymbolAddress((void**)&qkh_lo, g_qkh_lo);
    cudaGetSymbolAddress((void**)&sv, g_s);
    cudaGetSymbolAddress((void**)&tv, g_t);
    cudaGetSymbolAddress((void**)&qkv_out, g_qkv);

    // 1. fold BN + split weights + zero k-pads
    prep_kernel<<<2304, 256>>>(wq, wk, wv, wp, bq, bk, bv, bp, bnq, bnk, bnv, bnp);
    // 2. transpose+split x
    xt_cvt_kernel<<<dim3(7, 12, 64), 256>>>(x);
    // 3. fused qkv GEMM (M=1536, K=384) + q/k bf16 export
    gemm_mma_kernel<<<dim3(98, 12), 256, GEMM_SMEM_BYTES>>>(
        wqkv_hi, wqkv_lo, xt_hi, xt_lo, 384, sv, tv, qkv_out, 1536, qkh_hi, qkh_lo);
    // 4. depthwise conv + BN (+ V bf16 export)
    dwconv_kernel<<<dim3(128, 64), 256>>>(wvl, bvl, bnvl);
    // 5. QK logits on tensor cores (+ scale + positional bias)
    qk_mma_kernel<<<dim3(2, 2, 512), 256, QK_SMEM_BYTES>>>(ab, bidx);
    // 6. attention core (TH1, softmax, TH2, P export)
    attn_kernel<<<dim3(14, 64), 256, attn_smem>>>(th1w, th1b, th2w, th2b);
    // 7. AV on tensor cores (+ fused relu(att+v_local) -> proj input)
    av_mma_kernel<<<dim3(2, 512), 256, GEMM_SMEM_BYTES>>>();
    // 8. projection GEMM (M=384, K=1024)
    gemm_mma_kernel<<<dim3(98, 3), 256, GEMM_SMEM_BYTES>>>(
        wp_hi, wp_lo, pt_hi, pt_lo, 1024, sv + 1536, tv + 1536, out, 384,
        nullptr, nullptr);
}

// round 9
// speedup vs baseline: 3.4790x; 1.0805x over previous
#include <cuda_runtime.h>
#include <cuda_bf16.h>
#include <math.h>
#include <stdint.h>

#define EPSF 1e-5f
#define SCALEF 0.17677669529663687f

#define NB   64
#define NPIX 196
#define QKVC 1536
#define DHC  1024
#define NCOL 12544   // 64*196
#define KPAD 256     // padded k (m) dimension for AV mma

// ------------------------------------------------------------------
// scratch (no cudaMalloc allowed)
__device__ float g_qkv [NB * QKVC * NPIX];   // [b][1536][196]; q@0, k@256, v@512
__device__ float g_vloc[NB * DHC * NPIX];    // [b][1024][196]
__device__ float g_logits[512 * 196 * 196];  // [(b*8+h)][n][m] post-bias logits

__device__ __align__(16) __nv_bfloat16 g_xt_hi[NCOL * 384];   // [j][k]
__device__ __align__(16) __nv_bfloat16 g_xt_lo[NCOL * 384];
__device__ __align__(16) __nv_bfloat16 g_pt_hi[NCOL * 1024];  // [j][k]
__device__ __align__(16) __nv_bfloat16 g_pt_lo[NCOL * 1024];
__device__ __align__(16) __nv_bfloat16 g_wqkv_hi[1536 * 384]; // [m][k]
__device__ __align__(16) __nv_bfloat16 g_wqkv_lo[1536 * 384];
__device__ __align__(16) __nv_bfloat16 g_wp_hi[384 * 1024];
__device__ __align__(16) __nv_bfloat16 g_wp_lo[384 * 1024];
// q/k export: [(b*16 + hh)][n][d=32] bf16 hi/lo; hh 0-7 = q heads, 8-15 = k heads
__device__ __align__(16) __nv_bfloat16 g_qkh_hi[NB * 16 * 196 * 32];
__device__ __align__(16) __nv_bfloat16 g_qkh_lo[NB * 16 * 196 * 32];
// attention P (post-softmax/TH2) bf16 hi/lo: [(b*8+o)*196 + n][k=KPAD]
__device__ __align__(16) __nv_bfloat16 g_phi[512 * 196 * KPAD];
__device__ __align__(16) __nv_bfloat16 g_plo[512 * 196 * KPAD];
// raw V bf16 hi/lo: [b][c(1024)][k=KPAD]
__device__ __align__(16) __nv_bfloat16 g_vhi[NB * 1024 * KPAD];
__device__ __align__(16) __nv_bfloat16 g_vlo[NB * 1024 * KPAD];
__device__ float g_s[1920];   // folded BN scale: [0:1536) qkv, [1536:1920) proj
__device__ float g_t[1920];   // folded BN shift

// ------------------------------------------------------------------
static __device__ __forceinline__ uint32_t s2u(const void* p) {
    uint32_t a;
    asm("{ .reg .u64 t; cvta.to.shared.u64 t, %1; cvt.u32.u64 %0, t; }"
        : "=r"(a) : "l"(p));
    return a;
}

static __device__ __forceinline__ void cp_async16(uint32_t saddr, const void* gptr) {
    asm volatile("cp.async.cg.shared.global [%0], [%1], 16;"
                 :: "r"(saddr), "l"(gptr) : "memory");
}

static __device__ __forceinline__ void cp_async16_zf(uint32_t saddr, const void* gptr, int valid) {
    int sz = valid ? 16 : 0;
    asm volatile("cp.async.cg.shared.global [%0], [%1], 16, %2;"
                 :: "r"(saddr), "l"(gptr), "r"(sz) : "memory");
}

static __device__ __forceinline__ void ldmat_x4(
    uint32_t& r0, uint32_t& r1, uint32_t& r2, uint32_t& r3, uint32_t addr)
{
    asm volatile("ldmatrix.sync.aligned.m8n8.x4.shared.b16 {%0,%1,%2,%3}, [%4];"
                 : "=r"(r0), "=r"(r1), "=r"(r2), "=r"(r3) : "r"(addr));
}

static __device__ __forceinline__ void mma_bf16(
    float& d0, float& d1, float& d2, float& d3,
    uint32_t a0, uint32_t a1, uint32_t a2, uint32_t a3,
    uint32_t b0, uint32_t b1)
{
    asm volatile(
        "mma.sync.aligned.m16n8k16.row.col.f32.bf16.bf16.f32 "
        "{%0,%1,%2,%3}, {%4,%5,%6,%7}, {%8,%9}, {%0,%1,%2,%3};"
        : "+f"(d0), "+f"(d1), "+f"(d2), "+f"(d3)
        : "r"(a0), "r"(a1), "r"(a2), "r"(a3), "r"(b0), "r"(b1));
}

// ------------------------------------------------------------------
// Prep: fold BN; split weights into bf16 hi/lo; zero k-pads with u64 stores.
__global__ void __launch_bounds__(256) prep_kernel(
    const float* __restrict__ wq, const float* __restrict__ wk,
    const float* __restrict__ wv, const float* __restrict__ wp,
    const float* __restrict__ bq, const float* __restrict__ bk,
    const float* __restrict__ bv, const float* __restrict__ bp,
    const float* __restrict__ bnq, const float* __restrict__ bnk,
    const float* __restrict__ bnv, const float* __restrict__ bnp)
{
    int idx = blockIdx.x * 256 + threadIdx.x;
    int stride = gridDim.x * 256;

    for (int i = idx; i < 1536 * 384; i += stride) {
        int m = i / 384;
        float w = (m < 256) ? wq[i]
                : (m < 512) ? wk[i - 256 * 384]
                            : wv[i - 512 * 384];
        __nv_bfloat16 h = __float2bfloat16(w);
        g_wqkv_hi[i] = h;
        g_wqkv_lo[i] = __float2bfloat16(w - __bfloat162float(h));
    }
    for (int i = idx; i < 384 * 1024; i += stride) {
        float w = wp[i];
        __nv_bfloat16 h = __float2bfloat16(w);
        g_wp_hi[i] = h;
        g_wp_lo[i] = __float2bfloat16(w - __bfloat162float(h));
    }
    // zero P k-pad: rows 512*196, row stride 512B, pad = 120B at offset 392 (15 u64)
    for (long i = idx; i < (long)100352 * 15; i += stride) {
        long r = i / 15; int k = (int)(i % 15);
        *(unsigned long long*)((char*)g_phi + r * 512 + 392 + k * 8) = 0ull;
        *(unsigned long long*)((char*)g_plo + r * 512 + 392 + k * 8) = 0ull;
    }
    // zero V k-pad: rows 64*1024
    for (long i = idx; i < (long)65536 * 15; i += stride) {
        long r = i / 15; int k = (int)(i % 15);
        *(unsigned long long*)((char*)g_vhi + r * 512 + 392 + k * 8) = 0ull;
        *(unsigned long long*)((char*)g_vlo + r * 512 + 392 + k * 8) = 0ull;
    }
    if (idx < 1920) {
        const float* bn; const float* bias; int c; int C;
        if (idx < 256)       { bn = bnq; bias = bq; c = idx;        C = 256; }
        else if (idx < 512)  { bn = bnk; bias = bk; c = idx - 256;  C = 256; }
        else if (idx < 1536) { bn = bnv; bias = bv; c = idx - 512;  C = 1024; }
        else                 { bn = bnp; bias = bp; c = idx - 1536; C = 384; }
        float s = bn[c] * rsqrtf(bn[3 * C + c] + EPSF);
        g_s[idx] = s;
        g_t[idx] = (bias[c] - bn[2 * C + c]) * s + bn[C + c];
    }
}

// ------------------------------------------------------------------
// Transpose+split x: [b][384][196] -> Xt[j=b*196+n][k=c] bf16 hi/lo
__global__ void __launch_bounds__(256) xt_cvt_kernel(const float* __restrict__ X)
{
    __shared__ float t[32][29];
    int b = blockIdx.z, c0 = blockIdx.y * 32, n0 = blockIdx.x * 28;
    int tid = threadIdx.x;
    const float* src = X + ((size_t)b * 384 + c0) * 196 + n0;
    for (int i = tid; i < 32 * 28; i += 256) {
        int ci = i / 28, nj = i - ci * 28;
        t[ci][nj] = src[(size_t)ci * 196 + nj];
    }
    __syncthreads();
    for (int i = tid; i < 32 * 28; i += 256) {
        int nj = i >> 5, ci = i & 31;
        float v = t[ci][nj];
        __nv_bfloat16 h = __float2bfloat16(v);
        size_t o = ((size_t)(b * 196 + n0 + nj)) * 384 + c0 + ci;
        g_xt_hi[o] = h;
        g_xt_lo[o] = __float2bfloat16(v - __bfloat162float(h));
    }
}

// ------------------------------------------------------------------
// bf16 mma.sync GEMM, 3-term compensation fused per K-chunk (unchanged R8).
#define GEMM_STAGE_BYTES 65536
#define GEMM_SMEM_BYTES  (2 * GEMM_STAGE_BYTES)

__global__ void __launch_bounds__(256) gemm_mma_kernel(
    const __nv_bfloat16* __restrict__ Ahi, const __nv_bfloat16* __restrict__ Alo,
    const __nv_bfloat16* __restrict__ Bhi, const __nv_bfloat16* __restrict__ Blo,
    int K, const float* __restrict__ svec, const float* __restrict__ tvec,
    float* __restrict__ out, int Cout,
    __nv_bfloat16* __restrict__ qk_hi, __nv_bfloat16* __restrict__ qk_lo)
{
    extern __shared__ __align__(1024) char smem[];
    const uint32_t sb = s2u(smem);
    const int tid = threadIdx.x;
    const int wid = tid >> 5, lane = tid & 31;
    const int warp_m = wid & 1;
    const int warp_n = wid >> 1;
    const int m0 = blockIdx.y * 128;
    const int j0 = blockIdx.x * 128;
    const int nk = K >> 6;
    const bool doexp = (qk_hi != nullptr) && (m0 < 512);

    float acc[4][4][4];
#pragma unroll
    for (int i = 0; i < 4; i++)
#pragma unroll
        for (int j = 0; j < 4; j++)
#pragma unroll
            for (int c = 0; c < 4; c++) acc[i][j][c] = 0.f;

    const int lrow = lane & 15;
    const uint32_t lkoff = (uint32_t)((lane >> 4) << 4);

    auto issue = [&](int kb, uint32_t stage_off) {
#pragma unroll
        for (int i = 0; i < 4; i++) {
            int q = tid + (i << 8);
            int row = q >> 3, k8 = q & 7;
            uint32_t off = (uint32_t)(row * 128 + k8 * 16);
            uint32_t sw = off ^ ((off >> 3) & 0x70);
            size_t ga = (size_t)(m0 + row) * K + kb + (k8 << 3);
            size_t gb = (size_t)(j0 + row) * K + kb + (k8 << 3);
            cp_async16(sb + stage_off + sw,           Ahi + ga);
            cp_async16(sb + stage_off + 16384u + sw,  Alo + ga);
            cp_async16(sb + stage_off + 32768u + sw,  Bhi + gb);
            cp_async16(sb + stage_off + 49152u + sw,  Blo + gb);
        }
        asm volatile("cp.async.commit_group;" ::: "memory");
    };

    issue(0, 0u);
    if (nk > 1) issue(64, GEMM_STAGE_BYTES);

    for (int ch = 0; ch < nk; ch++) {
        if (ch + 1 < nk) asm volatile("cp.async.wait_group 1;" ::: "memory");
        else             asm volatile("cp.async.wait_group 0;" ::: "memory");
        __syncthreads();

        const uint32_t buf = (ch & 1) ? (uint32_t)GEMM_STAGE_BYTES : 0u;
#pragma unroll
        for (int ks = 0; ks < 4; ks++) {
            uint32_t bh[4][2], bl[4][2];
#pragma unroll
            for (int p = 0; p < 2; p++) {
                uint32_t off = (uint32_t)((warp_n * 32 + p * 16 + lrow) * 128)
                             + (uint32_t)(ks * 32) + lkoff;
                uint32_t sw = off ^ ((off >> 3) & 0x70);
                uint32_t r0, r1, r2, r3;
                ldmat_x4(r0, r1, r2, r3, sb + buf + 32768u + sw);
                bh[p * 2 + 0][0] = r0; bh[p * 2 + 1][0] = r1;
                bh[p * 2 + 0][1] = r2; bh[p * 2 + 1][1] = r3;
                ldmat_x4(r0, r1, r2, r3, sb + buf + 49152u + sw);
                bl[p * 2 + 0][0] = r0; bl[p * 2 + 1][0] = r1;
                bl[p * 2 + 0][1] = r2; bl[p * 2 + 1][1] = r3;
            }
#pragma unroll
            for (int mt = 0; mt < 4; mt++) {
                uint32_t off = (uint32_t)((warp_m * 64 + mt * 16 + lrow) * 128)
                             + (uint32_t)(ks * 32) + lkoff;
                uint32_t sw = off ^ ((off >> 3) & 0x70);
                uint32_t a0, a1, a2, a3;
                ldmat_x4(a0, a1, a2, a3, sb + buf + sw);
#pragma unroll
                for (int nt = 0; nt < 4; nt++)
                    mma_bf16(acc[mt][nt][0], acc[mt][nt][1],
                             acc[mt][nt][2], acc[mt][nt][3],
                             a0, a1, a2, a3, bh[nt][0], bh[nt][1]);
#pragma unroll
                for (int nt = 0; nt < 4; nt++)
                    mma_bf16(acc[mt][nt][0], acc[mt][nt][1],
                             acc[mt][nt][2], acc[mt][nt][3],
                             a0, a1, a2, a3, bl[nt][0], bl[nt][1]);
                ldmat_x4(a0, a1, a2, a3, sb + buf + 16384u + sw);
#pragma unroll
                for (int nt = 0; nt < 4; nt++)
                    mma_bf16(acc[mt][nt][0], acc[mt][nt][1],
                             acc[mt][nt][2], acc[mt][nt][3],
                             a0, a1, a2, a3, bh[nt][0], bh[nt][1]);
            }
        }

        if (ch + 2 < nk) {
            __syncthreads();
            issue((ch + 2) << 6, buf);
        }
    }

    const int group = lane >> 2, tig = lane & 3;
#pragma unroll
    for (int mt = 0; mt < 4; mt++) {
        int oc0 = m0 + warp_m * 64 + mt * 16 + group;
        int oc1 = oc0 + 8;
        float s0 = svec[oc0], t0 = tvec[oc0];
        float s1 = svec[oc1], t1 = tvec[oc1];
#pragma unroll
        for (int nt = 0; nt < 4; nt++) {
            int j = j0 + warp_n * 32 + nt * 8 + tig * 2;
            int b = j / 196, n = j - b * 196;
            float* p0 = out + ((size_t)b * Cout + oc0) * 196 + n;
            float* p1 = out + ((size_t)b * Cout + oc1) * 196 + n;
            float v00 = acc[mt][nt][0] * s0 + t0;
            float v01 = acc[mt][nt][1] * s0 + t0;
            float v10 = acc[mt][nt][2] * s1 + t1;
            float v11 = acc[mt][nt][3] * s1 + t1;
            p0[0] = v00; p0[1] = v01;
            p1[0] = v10; p1[1] = v11;
            if (doexp) {
                size_t r0 = (((size_t)(b * 16) + (oc0 >> 5)) * 196 + n) * 32 + (oc0 & 31);
                size_t r1 = (((size_t)(b * 16) + (oc1 >> 5)) * 196 + n) * 32 + (oc1 & 31);
                __nv_bfloat16 h;
                h = __float2bfloat16(v00); qk_hi[r0] = h;
                qk_lo[r0] = __float2bfloat16(v00 - __bfloat162float(h));
                h = __float2bfloat16(v01); qk_hi[r0 + 32] = h;
                qk_lo[r0 + 32] = __float2bfloat16(v01 - __bfloat162float(h));
                h = __float2bfloat16(v10); qk_hi[r1] = h;
                qk_lo[r1] = __float2bfloat16(v10 - __bfloat162float(h));
                h = __float2bfloat16(v11); qk_hi[r1 + 32] = h;
                qk_lo[r1 + 32] = __float2bfloat16(v11 - __bfloat162float(h));
            }
        }
    }
}

// ------------------------------------------------------------------
// QK logits mma (unchanged R8).
#define QK_SMEM_BYTES 65536

__global__ void __launch_bounds__(256) qk_mma_kernel(
    const float* __restrict__ ab, const int* __restrict__ bidx)
{
    extern __shared__ __align__(1024) char smem[];
    const uint32_t sb = s2u(smem);
    const int tid = threadIdx.x;
    const int wid = tid >> 5, lane = tid & 31;
    const int warp_m = wid & 1;
    const int warp_n = wid >> 1;
    const int bh = blockIdx.z;
    const int b = bh >> 3, h = bh & 7;
    const int n0 = blockIdx.x * 128;
    const int m0c = blockIdx.y * 128;

    const __nv_bfloat16* Qhi = g_qkh_hi + (size_t)(b * 16 + h) * 196 * 32;
    const __nv_bfloat16* Qlo = g_qkh_lo + (size_t)(b * 16 + h) * 196 * 32;
    const __nv_bfloat16* Khi = g_qkh_hi + (size_t)(b * 16 + 8 + h) * 196 * 32;
    const __nv_bfloat16* Klo = g_qkh_lo + (size_t)(b * 16 + 8 + h) * 196 * 32;

#pragma unroll
    for (int t = 0; t < 2; t++) {
        int q = tid + (t << 8);
        int row = q >> 2, k8 = q & 3;
        uint32_t off = (uint32_t)(row * 128 + k8 * 16);
        uint32_t sw = off ^ ((off >> 3) & 0x70);
        int nr = n0 + row;
        int vq = nr < 196;
        size_t gq = vq ? ((size_t)nr * 32 + (k8 << 3)) : 0;
        cp_async16_zf(sb + sw,           Qhi + gq, vq);
        cp_async16_zf(sb + 16384u + sw,  Qlo + gq, vq);
        int mr = m0c + row;
        int vk = mr < 196;
        size_t gk = vk ? ((size_t)mr * 32 + (k8 << 3)) : 0;
        cp_async16_zf(sb + 32768u + sw,  Khi + gk, vk);
        cp_async16_zf(sb + 49152u + sw,  Klo + gk, vk);
    }
    asm volatile("cp.async.commit_group;" ::: "memory");
    asm volatile("cp.async.wait_group 0;" ::: "memory");
    __syncthreads();

    float acc[4][4][4];
#pragma unroll
    for (int i = 0; i < 4; i++)
#pragma unroll
        for (int j = 0; j < 4; j++)
#pragma unroll
            for (int c = 0; c < 4; c++) acc[i][j][c] = 0.f;

    const int lrow = lane & 15;
    const uint32_t lkoff = (uint32_t)((lane >> 4) << 4);

#pragma unroll
    for (int ks = 0; ks < 2; ks++) {
        uint32_t bh_[4][2], bl_[4][2];
#pragma unroll
        for (int p = 0; p < 2; p++) {
            uint32_t off = (uint32_t)((warp_n * 32 + p * 16 + lrow) * 128)
                         + (uint32_t)(ks * 32) + lkoff;
            uint32_t sw = off ^ ((off >> 3) & 0x70);
            uint32_t r0, r1, r2, r3;
            ldmat_x4(r0, r1, r2, r3, sb + 32768u + sw);
            bh_[p * 2 + 0][0] = r0; bh_[p * 2 + 1][0] = r1;
            bh_[p * 2 + 0][1] = r2; bh_[p * 2 + 1][1] = r3;
            ldmat_x4(r0, r1, r2, r3, sb + 49152u + sw);
            bl_[p * 2 + 0][0] = r0; bl_[p * 2 + 1][0] = r1;
            bl_[p * 2 + 0][1] = r2; bl_[p * 2 + 1][1] = r3;
        }
#pragma unroll
        for (int mt = 0; mt < 4; mt++) {
            uint32_t off = (uint32_t)((warp_m * 64 + mt * 16 + lrow) * 128)
                         + (uint32_t)(ks * 32) + lkoff;
            uint32_t sw = off ^ ((off >> 3) & 0x70);
            uint32_t a0, a1, a2, a3;
            ldmat_x4(a0, a1, a2, a3, sb + sw);
#pragma unroll
            for (int nt = 0; nt < 4; nt++)
                mma_bf16(acc[mt][nt][0], acc[mt][nt][1],
                         acc[mt][nt][2], acc[mt][nt][3],
                         a0, a1, a2, a3, bh_[nt][0], bh_[nt][1]);
#pragma unroll
            for (int nt = 0; nt < 4; nt++)
                mma_bf16(acc[mt][nt][0], acc[mt][nt][1],
                         acc[mt][nt][2], acc[mt][nt][3],
                         a0, a1, a2, a3, bl_[nt][0], bl_[nt][1]);
            ldmat_x4(a0, a1, a2, a3, sb + 16384u + sw);
#pragma unroll
            for (int nt = 0; nt < 4; nt++)
                mma_bf16(acc[mt][nt][0], acc[mt][nt][1],
                         acc[mt][nt][2], acc[mt][nt][3],
                         a0, a1, a2, a3, bh_[nt][0], bh_[nt][1]);
        }
    }

    const int group = lane >> 2, tig = lane & 3;
    const float* abh = ab + h * 196;
    float* lbase = g_logits + (size_t)bh * 196 * 196;
#pragma unroll
    for (int mt = 0; mt < 4; mt++) {
        int nr0 = n0 + warp_m * 64 + mt * 16 + group;
        int nr1 = nr0 + 8;
#pragma unroll
        for (int nt = 0; nt < 4; nt++) {
            int m = m0c + warp_n * 32 + nt * 8 + tig * 2;
            if (m < 196) {
                if (nr0 < 196) {
                    const int* br = bidx + (size_t)nr0 * 196;
                    lbase[(size_t)nr0 * 196 + m]     = acc[mt][nt][0] * SCALEF + abh[br[m]];
                    lbase[(size_t)nr0 * 196 + m + 1] = acc[mt][nt][1] * SCALEF + abh[br[m + 1]];
                }
                if (nr1 < 196) {
                    const int* br = bidx + (size_t)nr1 * 196;
                    lbase[(size_t)nr1 * 196 + m]     = acc[mt][nt][2] * SCALEF + abh[br[m]];
                    lbase[(size_t)nr1 * 196 + m + 1] = acc[mt][nt][3] * SCALEF + abh[br[m + 1]];
                }
            }
        }
    }
}

// ------------------------------------------------------------------
// AV batched mma + fused relu(D+v_local) -> g_pt epilogue (unchanged R8).
__global__ void __launch_bounds__(256) av_mma_kernel()
{
    extern __shared__ __align__(1024) char smem[];
    const uint32_t sb = s2u(smem);
    const int tid = threadIdx.x;
    const int wid = tid >> 5, lane = tid & 31;
    const int warp_m = wid & 1;
    const int warp_n = wid >> 1;
    const int bo = blockIdx.y;
    const int b  = bo >> 3, o = bo & 7;
    const int j0 = blockIdx.x * 128;
    const int nk = 4;

    const __nv_bfloat16* Ahi = g_vhi + ((size_t)b * 1024 + o * 128) * KPAD;
    const __nv_bfloat16* Alo = g_vlo + ((size_t)b * 1024 + o * 128) * KPAD;
    const __nv_bfloat16* Bhi = g_phi + ((size_t)bo * 196) * KPAD;
    const __nv_bfloat16* Blo = g_plo + ((size_t)bo * 196) * KPAD;

    float acc[4][4][4];
#pragma unroll
    for (int i = 0; i < 4; i++)
#pragma unroll
        for (int j = 0; j < 4; j++)
#pragma unroll
            for (int c = 0; c < 4; c++) acc[i][j][c] = 0.f;

    const int lrow = lane & 15;
    const uint32_t lkoff = (uint32_t)((lane >> 4) << 4);

    auto issue = [&](int kb, uint32_t stage_off) {
#pragma unroll
        for (int i = 0; i < 4; i++) {
            int q = tid + (i << 8);
            int row = q >> 3, k8 = q & 7;
            uint32_t off = (uint32_t)(row * 128 + k8 * 16);
            uint32_t sw = off ^ ((off >> 3) & 0x70);
            size_t ga = (size_t)row * KPAD + kb + (k8 << 3);
            cp_async16(sb + stage_off + sw,          Ahi + ga);
            cp_async16(sb + stage_off + 16384u + sw, Alo + ga);
            int jrow = j0 + row;
            int valid = (jrow < 196);
            size_t gb = valid ? ((size_t)jrow * KPAD + kb + (k8 << 3)) : 0;
            cp_async16_zf(sb + stage_off + 32768u + sw, Bhi + gb, valid);
            cp_async16_zf(sb + stage_off + 49152u + sw, Blo + gb, valid);
        }
        asm volatile("cp.async.commit_group;" ::: "memory");
    };

    issue(0, 0u);
    issue(64, GEMM_STAGE_BYTES);

    for (int ch = 0; ch < nk; ch++) {
        if (ch + 1 < nk) asm volatile("cp.async.wait_group 1;" ::: "memory");
        else             asm volatile("cp.async.wait_group 0;" ::: "memory");
        __syncthreads();

        const uint32_t buf = (ch & 1) ? (uint32_t)GEMM_STAGE_BYTES : 0u;
#pragma unroll
        for (int ks = 0; ks < 4; ks++) {
            uint32_t bh[4][2], bl[4][2];
#pragma unroll
            for (int p = 0; p < 2; p++) {
                uint32_t off = (uint32_t)((warp_n * 32 + p * 16 + lrow) * 128)
                             + (uint32_t)(ks * 32) + lkoff;
                uint32_t sw = off ^ ((off >> 3) & 0x70);
                uint32_t r0, r1, r2, r3;
                ldmat_x4(r0, r1, r2, r3, sb + buf + 32768u + sw);
                bh[p * 2 + 0][0] = r0; bh[p * 2 + 1][0] = r1;
                bh[p * 2 + 0][1] = r2; bh[p * 2 + 1][1] = r3;
                ldmat_x4(r0, r1, r2, r3, sb + buf + 49152u + sw);
                bl[p * 2 + 0][0] = r0; bl[p * 2 + 1][0] = r1;
                bl[p * 2 + 0][1] = r2; bl[p * 2 + 1][1] = r3;
            }
#pragma unroll
            for (int mt = 0; mt < 4; mt++) {
                uint32_t off = (uint32_t)((warp_m * 64 + mt * 16 + lrow) * 128)
                             + (uint32_t)(ks * 32) + lkoff;
                uint32_t sw = off ^ ((off >> 3) & 0x70);
                uint32_t a0, a1, a2, a3;
                ldmat_x4(a0, a1, a2, a3, sb + buf + sw);
#pragma unroll
                for (int nt = 0; nt < 4; nt++)
                    mma_bf16(acc[mt][nt][0], acc[mt][nt][1],
                             acc[mt][nt][2], acc[mt][nt][3],
                             a0, a1, a2, a3, bh[nt][0], bh[nt][1]);
#pragma unroll
                for (int nt = 0; nt < 4; nt++)
                    mma_bf16(acc[mt][nt][0], acc[mt][nt][1],
                             acc[mt][nt][2], acc[mt][nt][3],
                             a0, a1, a2, a3, bl[nt][0], bl[nt][1]);
                ldmat_x4(a0, a1, a2, a3, sb + buf + 16384u + sw);
#pragma unroll
                for (int nt = 0; nt < 4; nt++)
                    mma_bf16(acc[mt][nt][0], acc[mt][nt][1],
                             acc[mt][nt][2], acc[mt][nt][3],
                             a0, a1, a2, a3, bh[nt][0], bh[nt][1]);
            }
        }

        if (ch + 2 < nk) {
            __syncthreads();
            issue((ch + 2) << 6, buf);
        }
    }

    const int group = lane >> 2, tig = lane & 3;
    const float* vlbase = g_vloc + ((size_t)b * 1024 + o * 128) * NPIX;
#pragma unroll
    for (int mt = 0; mt < 4; mt++) {
        int e0 = warp_m * 64 + mt * 16 + group;
        int e1 = e0 + 8;
#pragma unroll
        for (int nt = 0; nt < 4; nt++) {
            int j = j0 + warp_n * 32 + nt * 8 + tig * 2;
            if (j < 196) {
                float v00 = fmaxf(acc[mt][nt][0] + vlbase[(size_t)e0 * NPIX + j],     0.f);
                float v01 = fmaxf(acc[mt][nt][1] + vlbase[(size_t)e0 * NPIX + j + 1], 0.f);
                float v10 = fmaxf(acc[mt][nt][2] + vlbase[(size_t)e1 * NPIX + j],     0.f);
                float v11 = fmaxf(acc[mt][nt][3] + vlbase[(size_t)e1 * NPIX + j + 1], 0.f);
                size_t r00 = ((size_t)(b * 196 + j))     * 1024 + o * 128 + e0;
                size_t r01 = ((size_t)(b * 196 + j + 1)) * 1024 + o * 128 + e0;
                __nv_bfloat16 h;
                h = __float2bfloat16(v00); g_pt_hi[r00] = h;
                g_pt_lo[r00] = __float2bfloat16(v00 - __bfloat162float(h));
                h = __float2bfloat16(v01); g_pt_hi[r01] = h;
                g_pt_lo[r01] = __float2bfloat16(v01 - __bfloat162float(h));
                h = __float2bfloat16(v10); g_pt_hi[r00 + 8] = h;
                g_pt_lo[r00 + 8] = __float2bfloat16(v10 - __bfloat162float(h));
                h = __float2bfloat16(v11); g_pt_hi[r01 + 8] = h;
                g_pt_lo[r01 + 8] = __float2bfloat16(v11 - __bfloat162float(h));
            }
        }
    }
}

// ------------------------------------------------------------------
// Depthwise 3x3 conv v2: zero-halo padded 16x16 planes, branchless taps.
// warp = channel; lane = pixel (28 active lanes, 7 row-pairs).
__global__ void __launch_bounds__(256) dwconv_kernel(
    const float* __restrict__ wvl, const float* __restrict__ bvl,
    const float* __restrict__ bn)
{
    int c0 = blockIdx.x * 8, b = blockIdx.y;
    __shared__ float p[8 * 256];     // 8 channels x 16x16 zero-halo plane
    __shared__ float wsh[72];
    __shared__ float cs[8], ct[8];
    int tid = threadIdx.x;
    const float* src = g_qkv + (size_t)b * (QKVC * NPIX) + (size_t)(512 + c0) * NPIX;
    __nv_bfloat16* vhi = g_vhi + ((size_t)b * 1024 + c0) * KPAD;
    __nv_bfloat16* vlo = g_vlo + ((size_t)b * 1024 + c0) * KPAD;

    // load planes (halo = 0) + export raw V as bf16 hi/lo
    for (int i = tid; i < 2048; i += 256) {
        int c = i >> 8, idx = i & 255;
        int y = idx >> 4, x = idx & 15;
        float v = 0.f;
        if (y >= 1 && y <= 14 && x >= 1 && x <= 14) {
            int pix = (y - 1) * 14 + (x - 1);
            v = src[c * 196 + pix];
            __nv_bfloat16 h = __float2bfloat16(v);
            vhi[(size_t)c * KPAD + pix] = h;
            vlo[(size_t)c * KPAD + pix] = __float2bfloat16(v - __bfloat162float(h));
        }
        p[i] = v;
    }
    if (tid < 72) wsh[tid] = wvl[c0 * 9 + tid];
    if (tid < 8) {
        int c = c0 + tid;
        float s = bn[c] * rsqrtf(bn[3072 + c] + EPSF);
        cs[tid] = s;
        ct[tid] = (bvl[c] - bn[2048 + c]) * s + bn[1024 + c];
    }
    __syncthreads();

    int w = tid >> 5, lane = tid & 31;
    if (lane < 28) {
        const float* pc = p + w * 256;
        float w00 = wsh[w * 9 + 0], w01 = wsh[w * 9 + 1], w02 = wsh[w * 9 + 2];
        float w10 = wsh[w * 9 + 3], w11 = wsh[w * 9 + 4], w12 = wsh[w * 9 + 5];
        float w20 = wsh[w * 9 + 6], w21 = wsh[w * 9 + 7], w22 = wsh[w * 9 + 8];
        float s = cs[w], t = ct[w];
        float* dst = g_vloc + (size_t)b * (DHC * NPIX) + (size_t)(c0 + w) * NPIX;
        int xr = lane >= 14;
        int x = lane - xr * 14;          // 0..13
#pragma unroll
        for (int it = 0; it < 7; it++) {
            int y = it * 2 + xr;          // 0..13
            const float* q = pc + y * 16 + x;   // window top-left (plane coords y..y+2, x..x+2)
            float acc = w00 * q[0]  + w01 * q[1]  + w02 * q[2]
                      + w10 * q[16] + w11 * q[17] + w12 * q[18]
                      + w20 * q[32] + w21 * q[33] + w22 * q[34];
            dst[y * 14 + x] = acc * s + t;
        }
    }
}

// ------------------------------------------------------------------
// Attention core v5: TH1 (reads g_logits) + softmax + fused TH2+P-export.
// smem (floats): L 21952 | th 144 = 22096 (88,384 B) -> 2 blocks/SM.
#define ATTN_SMEM_FLOATS (21952 + 144)

__global__ void __launch_bounds__(256, 2) attn_kernel(
    const float* __restrict__ th1w, const float* __restrict__ th1b,
    const float* __restrict__ th2w, const float* __restrict__ th2b)
{
    extern __shared__ float sm[];
    float* L  = sm;                 // [(h*14+nl)*196 + m]
    float* th = sm + 21952;

    int tid = threadIdx.x;
    int b = blockIdx.y;
    int n0 = blockIdx.x * 14;

    if (tid < 64)       th[tid] = th1w[tid];
    else if (tid < 72)  th[tid] = th1b[tid - 64];
    else if (tid < 136) th[tid] = th2w[tid - 72];
    else if (tid < 144) th[tid] = th2b[tid - 136];
    __syncthreads();

    // ---- talking-heads 1, fused with global logits load ----
    const float* lgbase = g_logits + (size_t)(b * 8) * 196 * 196;
    for (int idx = tid; idx < 2744; idx += 256) {
        int n_ = idx / 196, m = idx - n_ * 196;
        size_t rowoff = (size_t)(n0 + n_) * 196 + m;
        float v[8], o_[8];
#pragma unroll
        for (int hh = 0; hh < 8; hh++)
            v[hh] = lgbase[(size_t)hh * 196 * 196 + rowoff];
#pragma unroll
        for (int oo = 0; oo < 8; oo++) {
            float s = th[64 + oo];
#pragma unroll
            for (int hh = 0; hh < 8; hh++) s = fmaf(th[oo * 8 + hh], v[hh], s);
            o_[oo] = s;
        }
#pragma unroll
        for (int oo = 0; oo < 8; oo++) L[(oo * 14 + n_) * 196 + m] = o_[oo];
    }
    __syncthreads();

    // ---- softmax over m (warp w owns head o = w) ----
    {
        int w = tid >> 5, lane = tid & 31;
        for (int r = 0; r < 14; r++) {
            float* row = L + (w * 14 + r) * 196;
            float mx = -1e30f;
            for (int m = lane; m < 196; m += 32) mx = fmaxf(mx, row[m]);
#pragma unroll
            for (int off = 16; off > 0; off >>= 1)
                mx = fmaxf(mx, __shfl_xor_sync(0xffffffffu, mx, off));
            float sum = 0.f;
            for (int m = lane; m < 196; m += 32) {
                float e = __expf(row[m] - mx);
                row[m] = e; sum += e;
            }
#pragma unroll
            for (int off = 16; off > 0; off >>= 1)
                sum += __shfl_xor_sync(0xffffffffu, sum, off);
            float inv = 1.f / sum;
            for (int m = lane; m < 196; m += 32) row[m] *= inv;
        }
    }
    __syncthreads();

    // ---- talking-heads 2 fused with P export (straight from registers) ----
    for (int idx = tid; idx < 2744; idx += 256) {
        int n_ = idx / 196, m = idx - n_ * 196;
        float v[8];
#pragma unroll
        for (int hh = 0; hh < 8; hh++) v[hh] = L[(hh * 14 + n_) * 196 + m];
        size_t rbase = (size_t)(b * 8) * 196 + n0 + n_;
#pragma unroll
        for (int oo = 0; oo < 8; oo++) {
            float s = th[136 + oo];
#pragma unroll
            for (int hh = 0; hh < 8; hh++) s = fmaf(th[72 + oo * 8 + hh], v[hh], s);
            __nv_bfloat16 hh2 = __float2bfloat16(s);
            size_t row = rbase + (size_t)oo * 196;
            g_phi[row * KPAD + m] = hh2;
            g_plo[row * KPAD + m] = __float2bfloat16(s - __bfloat162float(hh2));
        }
    }
}

// ------------------------------------------------------------------
extern "C" void kernel_launch(void* const* d_in, const int* in_sizes, int n_in,
                              void* d_out, int out_size)
{
    const float* x    = (const float*)d_in[0];
    const float* wq   = (const float*)d_in[1];
    const float* bq   = (const float*)d_in[2];
    const float* bnq  = (const float*)d_in[3];
    const float* wk   = (const float*)d_in[4];
    const float* bk   = (const float*)d_in[5];
    const float* bnk  = (const float*)d_in[6];
    const float* wv   = (const float*)d_in[7];
    const float* bv   = (const float*)d_in[8];
    const float* bnv  = (const float*)d_in[9];
    const float* wvl  = (const float*)d_in[10];
    const float* bvl  = (const float*)d_in[11];
    const float* bnvl = (const float*)d_in[12];
    const float* th1w = (const float*)d_in[13];
    const float* th1b = (const float*)d_in[14];
    const float* th2w = (const float*)d_in[15];
    const float* th2b = (const float*)d_in[16];
    const float* wp   = (const float*)d_in[17];
    const float* bp   = (const float*)d_in[18];
    const float* bnp  = (const float*)d_in[19];
    const float* ab   = (const float*)d_in[20];
    const int*   bidx = (const int*)d_in[21];
    float* out = (float*)d_out;

    const int attn_smem = ATTN_SMEM_FLOATS * (int)sizeof(float);
    cudaFuncSetAttribute(attn_kernel,
                         cudaFuncAttributeMaxDynamicSharedMemorySize, attn_smem);
    cudaFuncSetAttribute(gemm_mma_kernel,
                         cudaFuncAttributeMaxDynamicSharedMemorySize, GEMM_SMEM_BYTES);
    cudaFuncSetAttribute(av_mma_kernel,
                         cudaFuncAttributeMaxDynamicSharedMemorySize, GEMM_SMEM_BYTES);
    cudaFuncSetAttribute(qk_mma_kernel,
                         cudaFuncAttributeMaxDynamicSharedMemorySize, QK_SMEM_BYTES);

    __nv_bfloat16 *wqkv_hi, *wqkv_lo, *xt_hi, *xt_lo, *wp_hi, *wp_lo, *pt_hi, *pt_lo;
    __nv_bfloat16 *qkh_hi, *qkh_lo;
    float *sv, *tv, *qkv_out;
    cudaGetSymbolAddress((void**)&wqkv_hi, g_wqkv_hi);
    cudaGetSymbolAddress((void**)&wqkv_lo, g_wqkv_lo);
    cudaGetSymbolAddress((void**)&xt_hi, g_xt_hi);
    cudaGetSymbolAddress((void**)&xt_lo, g_xt_lo);
    cudaGetSymbolAddress((void**)&wp_hi, g_wp_hi);
    cudaGetSymbolAddress((void**)&wp_lo, g_wp_lo);
    cudaGetSymbolAddress((void**)&pt_hi, g_pt_hi);
    cudaGetSymbolAddress((void**)&pt_lo, g_pt_lo);
    cudaGetSymbolAddress((void**)&qkh_hi, g_qkh_hi);
    cudaGetSymbolAddress((void**)&qkh_lo, g_qkh_lo);
    cudaGetSymbolAddress((void**)&sv, g_s);
    cudaGetSymbolAddress((void**)&tv, g_t);
    cudaGetSymbolAddress((void**)&qkv_out, g_qkv);

    // 1. fold BN + split weights + zero k-pads (vectorized)
    prep_kernel<<<2304, 256>>>(wq, wk, wv, wp, bq, bk, bv, bp, bnq, bnk, bnv, bnp);
    // 2. transpose+split x
    xt_cvt_kernel<<<dim3(7, 12, 64), 256>>>(x);
    // 3. fused qkv GEMM (M=1536, K=384) + q/k bf16 export
    gemm_mma_kernel<<<dim3(98, 12), 256, GEMM_SMEM_BYTES>>>(
        wqkv_hi, wqkv_lo, xt_hi, xt_lo, 384, sv, tv, qkv_out, 1536, qkh_hi, qkh_lo);
    // 4. depthwise conv + BN (+ V bf16 export), branchless halo version
    dwconv_kernel<<<dim3(128, 64), 256>>>(wvl, bvl, bnvl);
    // 5. QK logits on tensor cores (+ scale + positional bias)
    qk_mma_kernel<<<dim3(2, 2, 512), 256, QK_SMEM_BYTES>>>(ab, bidx);
    // 6. attention core (TH1, softmax, fused TH2+P export)
    attn_kernel<<<dim3(14, 64), 256, attn_smem>>>(th1w, th1b, th2w, th2b);
    // 7. AV on tensor cores (+ fused relu(att+v_local) -> proj input)
    av_mma_kernel<<<dim3(2, 512), 256, GEMM_SMEM_BYTES>>>();
    // 8. projection GEMM (M=384, K=1024)
    gemm_mma_kernel<<<dim3(98, 3), 256, GEMM_SMEM_BYTES>>>(
        wp_hi, wp_lo, pt_hi, pt_lo, 1024, sv + 1536, tv + 1536, out, 384,
        nullptr, nullptr);
}

// round 10
// speedup vs baseline: 3.4797x; 1.0002x over previous
#include <cuda_runtime.h>
#include <cuda_bf16.h>
#include <math.h>
#include <stdint.h>

#define EPSF 1e-5f
#define SCALEF 0.17677669529663687f

#define NB   64
#define NPIX 196
#define DHC  1024
#define NCOL 12544   // 64*196
#define KPAD 256     // padded k (m) dimension for AV mma

// ------------------------------------------------------------------
// scratch (no cudaMalloc allowed)
__device__ float g_vloc[NB * DHC * NPIX];    // [b][1024][196]
__device__ float g_logits[512 * 196 * 196];  // [(b*8+h)][n][m] post-bias logits

__device__ __align__(16) __nv_bfloat16 g_xt_hi[NCOL * 384];   // [j][k]
__device__ __align__(16) __nv_bfloat16 g_xt_lo[NCOL * 384];
__device__ __align__(16) __nv_bfloat16 g_pt_hi[NCOL * 1024];  // [j][k]
__device__ __align__(16) __nv_bfloat16 g_pt_lo[NCOL * 1024];
__device__ __align__(16) __nv_bfloat16 g_wqkv_hi[1536 * 384]; // [m][k]
__device__ __align__(16) __nv_bfloat16 g_wqkv_lo[1536 * 384];
__device__ __align__(16) __nv_bfloat16 g_wp_hi[384 * 1024];
__device__ __align__(16) __nv_bfloat16 g_wp_lo[384 * 1024];
// q/k export: [(b*16 + hh)][n][d=32] bf16 hi/lo; hh 0-7 = q heads, 8-15 = k heads
__device__ __align__(16) __nv_bfloat16 g_qkh_hi[NB * 16 * 196 * 32];
__device__ __align__(16) __nv_bfloat16 g_qkh_lo[NB * 16 * 196 * 32];
// attention P (post-softmax/TH2) bf16 hi/lo: [(b*8+o)*196 + n][k=KPAD]
__device__ __align__(16) __nv_bfloat16 g_phi[512 * 196 * KPAD];
__device__ __align__(16) __nv_bfloat16 g_plo[512 * 196 * KPAD];
// BN'd V bf16 hi/lo: [b][c(1024)][k=KPAD] (written by qkv GEMM epilogue)
__device__ __align__(16) __nv_bfloat16 g_vhi[NB * 1024 * KPAD];
__device__ __align__(16) __nv_bfloat16 g_vlo[NB * 1024 * KPAD];
__device__ float g_s[1920];   // folded BN scale: [0:1536) qkv, [1536:1920) proj
__device__ float g_t[1920];   // folded BN shift

// ------------------------------------------------------------------
static __device__ __forceinline__ uint32_t s2u(const void* p) {
    uint32_t a;
    asm("{ .reg .u64 t; cvta.to.shared.u64 t, %1; cvt.u32.u64 %0, t; }"
        : "=r"(a) : "l"(p));
    return a;
}

static __device__ __forceinline__ void cp_async16(uint32_t saddr, const void* gptr) {
    asm volatile("cp.async.cg.shared.global [%0], [%1], 16;"
                 :: "r"(saddr), "l"(gptr) : "memory");
}

static __device__ __forceinline__ void cp_async16_zf(uint32_t saddr, const void* gptr, int valid) {
    int sz = valid ? 16 : 0;
    asm volatile("cp.async.cg.shared.global [%0], [%1], 16, %2;"
                 :: "r"(saddr), "l"(gptr), "r"(sz) : "memory");
}

static __device__ __forceinline__ void ldmat_x4(
    uint32_t& r0, uint32_t& r1, uint32_t& r2, uint32_t& r3, uint32_t addr)
{
    asm volatile("ldmatrix.sync.aligned.m8n8.x4.shared.b16 {%0,%1,%2,%3}, [%4];"
                 : "=r"(r0), "=r"(r1), "=r"(r2), "=r"(r3) : "r"(addr));
}

static __device__ __forceinline__ void mma_bf16(
    float& d0, float& d1, float& d2, float& d3,
    uint32_t a0, uint32_t a1, uint32_t a2, uint32_t a3,
    uint32_t b0, uint32_t b1)
{
    asm volatile(
        "mma.sync.aligned.m16n8k16.row.col.f32.bf16.bf16.f32 "
        "{%0,%1,%2,%3}, {%4,%5,%6,%7}, {%8,%9}, {%0,%1,%2,%3};"
        : "+f"(d0), "+f"(d1), "+f"(d2), "+f"(d3)
        : "r"(a0), "r"(a1), "r"(a2), "r"(a3), "r"(b0), "r"(b1));
}

// ------------------------------------------------------------------
// Prep: fold BN; split weights into bf16 hi/lo; zero k-pads with u64 stores.
__global__ void __launch_bounds__(256) prep_kernel(
    const float* __restrict__ wq, const float* __restrict__ wk,
    const float* __restrict__ wv, const float* __restrict__ wp,
    const float* __restrict__ bq, const float* __restrict__ bk,
    const float* __restrict__ bv, const float* __restrict__ bp,
    const float* __restrict__ bnq, const float* __restrict__ bnk,
    const float* __restrict__ bnv, const float* __restrict__ bnp)
{
    int idx = blockIdx.x * 256 + threadIdx.x;
    int stride = gridDim.x * 256;

    for (int i = idx; i < 1536 * 384; i += stride) {
        int m = i / 384;
        float w = (m < 256) ? wq[i]
                : (m < 512) ? wk[i - 256 * 384]
                            : wv[i - 512 * 384];
        __nv_bfloat16 h = __float2bfloat16(w);
        g_wqkv_hi[i] = h;
        g_wqkv_lo[i] = __float2bfloat16(w - __bfloat162float(h));
    }
    for (int i = idx; i < 384 * 1024; i += stride) {
        float w = wp[i];
        __nv_bfloat16 h = __float2bfloat16(w);
        g_wp_hi[i] = h;
        g_wp_lo[i] = __float2bfloat16(w - __bfloat162float(h));
    }
    // zero P k-pad: rows 512*196, row stride 512B, pad = 120B at offset 392 (15 u64)
    for (long i = idx; i < (long)100352 * 15; i += stride) {
        long r = i / 15; int k = (int)(i % 15);
        *(unsigned long long*)((char*)g_phi + r * 512 + 392 + k * 8) = 0ull;
        *(unsigned long long*)((char*)g_plo + r * 512 + 392 + k * 8) = 0ull;
    }
    // zero V k-pad: rows 64*1024
    for (long i = idx; i < (long)65536 * 15; i += stride) {
        long r = i / 15; int k = (int)(i % 15);
        *(unsigned long long*)((char*)g_vhi + r * 512 + 392 + k * 8) = 0ull;
        *(unsigned long long*)((char*)g_vlo + r * 512 + 392 + k * 8) = 0ull;
    }
    if (idx < 1920) {
        const float* bn; const float* bias; int c; int C;
        if (idx < 256)       { bn = bnq; bias = bq; c = idx;        C = 256; }
        else if (idx < 512)  { bn = bnk; bias = bk; c = idx - 256;  C = 256; }
        else if (idx < 1536) { bn = bnv; bias = bv; c = idx - 512;  C = 1024; }
        else                 { bn = bnp; bias = bp; c = idx - 1536; C = 384; }
        float s = bn[c] * rsqrtf(bn[3 * C + c] + EPSF);
        g_s[idx] = s;
        g_t[idx] = (bias[c] - bn[2 * C + c]) * s + bn[C + c];
    }
}

// ------------------------------------------------------------------
// Transpose+split x: [b][384][196] -> Xt[j=b*196+n][k=c] bf16 hi/lo
__global__ void __launch_bounds__(256) xt_cvt_kernel(const float* __restrict__ X)
{
    __shared__ float t[32][29];
    int b = blockIdx.z, c0 = blockIdx.y * 32, n0 = blockIdx.x * 28;
    int tid = threadIdx.x;
    const float* src = X + ((size_t)b * 384 + c0) * 196 + n0;
    for (int i = tid; i < 32 * 28; i += 256) {
        int ci = i / 28, nj = i - ci * 28;
        t[ci][nj] = src[(size_t)ci * 196 + nj];
    }
    __syncthreads();
    for (int i = tid; i < 32 * 28; i += 256) {
        int nj = i >> 5, ci = i & 31;
        float v = t[ci][nj];
        __nv_bfloat16 h = __float2bfloat16(v);
        size_t o = ((size_t)(b * 196 + n0 + nj)) * 384 + c0 + ci;
        g_xt_hi[o] = h;
        g_xt_lo[o] = __float2bfloat16(v - __bfloat162float(h));
    }
}

// ------------------------------------------------------------------
// bf16 mma.sync GEMM, 3-term compensation fused per K-chunk.
// Two epilogue modes:
//   qk_hi != nullptr (qkv launch): oc<512 -> q/k bf16 export; oc>=512 -> V bf16
//   export into g_vhi/g_vlo; NO fp32 output write.
//   qk_hi == nullptr (proj launch): fp32 BN output write to `out`.
#define GEMM_STAGE_BYTES 65536
#define GEMM_SMEM_BYTES  (2 * GEMM_STAGE_BYTES)

__global__ void __launch_bounds__(256) gemm_mma_kernel(
    const __nv_bfloat16* __restrict__ Ahi, const __nv_bfloat16* __restrict__ Alo,
    const __nv_bfloat16* __restrict__ Bhi, const __nv_bfloat16* __restrict__ Blo,
    int K, const float* __restrict__ svec, const float* __restrict__ tvec,
    float* __restrict__ out, int Cout,
    __nv_bfloat16* __restrict__ qk_hi, __nv_bfloat16* __restrict__ qk_lo)
{
    extern __shared__ __align__(1024) char smem[];
    const uint32_t sb = s2u(smem);
    const int tid = threadIdx.x;
    const int wid = tid >> 5, lane = tid & 31;
    const int warp_m = wid & 1;
    const int warp_n = wid >> 1;
    const int m0 = blockIdx.y * 128;
    const int j0 = blockIdx.x * 128;
    const int nk = K >> 6;
    const bool is_qkv = (qk_hi != nullptr);

    float acc[4][4][4];
#pragma unroll
    for (int i = 0; i < 4; i++)
#pragma unroll
        for (int j = 0; j < 4; j++)
#pragma unroll
            for (int c = 0; c < 4; c++) acc[i][j][c] = 0.f;

    const int lrow = lane & 15;
    const uint32_t lkoff = (uint32_t)((lane >> 4) << 4);

    auto issue = [&](int kb, uint32_t stage_off) {
#pragma unroll
        for (int i = 0; i < 4; i++) {
            int q = tid + (i << 8);
            int row = q >> 3, k8 = q & 7;
            uint32_t off = (uint32_t)(row * 128 + k8 * 16);
            uint32_t sw = off ^ ((off >> 3) & 0x70);
            size_t ga = (size_t)(m0 + row) * K + kb + (k8 << 3);
            size_t gb = (size_t)(j0 + row) * K + kb + (k8 << 3);
            cp_async16(sb + stage_off + sw,           Ahi + ga);
            cp_async16(sb + stage_off + 16384u + sw,  Alo + ga);
            cp_async16(sb + stage_off + 32768u + sw,  Bhi + gb);
            cp_async16(sb + stage_off + 49152u + sw,  Blo + gb);
        }
        asm volatile("cp.async.commit_group;" ::: "memory");
    };

    issue(0, 0u);
    if (nk > 1) issue(64, GEMM_STAGE_BYTES);

    for (int ch = 0; ch < nk; ch++) {
        if (ch + 1 < nk) asm volatile("cp.async.wait_group 1;" ::: "memory");
        else             asm volatile("cp.async.wait_group 0;" ::: "memory");
        __syncthreads();

        const uint32_t buf = (ch & 1) ? (uint32_t)GEMM_STAGE_BYTES : 0u;
#pragma unroll
        for (int ks = 0; ks < 4; ks++) {
            uint32_t bh[4][2], bl[4][2];
#pragma unroll
            for (int p = 0; p < 2; p++) {
                uint32_t off = (uint32_t)((warp_n * 32 + p * 16 + lrow) * 128)
                             + (uint32_t)(ks * 32) + lkoff;
                uint32_t sw = off ^ ((off >> 3) & 0x70);
                uint32_t r0, r1, r2, r3;
                ldmat_x4(r0, r1, r2, r3, sb + buf + 32768u + sw);
                bh[p * 2 + 0][0] = r0; bh[p * 2 + 1][0] = r1;
                bh[p * 2 + 0][1] = r2; bh[p * 2 + 1][1] = r3;
                ldmat_x4(r0, r1, r2, r3, sb + buf + 49152u + sw);
                bl[p * 2 + 0][0] = r0; bl[p * 2 + 1][0] = r1;
                bl[p * 2 + 0][1] = r2; bl[p * 2 + 1][1] = r3;
            }
#pragma unroll
            for (int mt = 0; mt < 4; mt++) {
                uint32_t off = (uint32_t)((warp_m * 64 + mt * 16 + lrow) * 128)
                             + (uint32_t)(ks * 32) + lkoff;
                uint32_t sw = off ^ ((off >> 3) & 0x70);
                uint32_t a0, a1, a2, a3;
                ldmat_x4(a0, a1, a2, a3, sb + buf + sw);
#pragma unroll
                for (int nt = 0; nt < 4; nt++)
                    mma_bf16(acc[mt][nt][0], acc[mt][nt][1],
                             acc[mt][nt][2], acc[mt][nt][3],
                             a0, a1, a2, a3, bh[nt][0], bh[nt][1]);
#pragma unroll
                for (int nt = 0; nt < 4; nt++)
                    mma_bf16(acc[mt][nt][0], acc[mt][nt][1],
                             acc[mt][nt][2], acc[mt][nt][3],
                             a0, a1, a2, a3, bl[nt][0], bl[nt][1]);
                ldmat_x4(a0, a1, a2, a3, sb + buf + 16384u + sw);
#pragma unroll
                for (int nt = 0; nt < 4; nt++)
                    mma_bf16(acc[mt][nt][0], acc[mt][nt][1],
                             acc[mt][nt][2], acc[mt][nt][3],
                             a0, a1, a2, a3, bh[nt][0], bh[nt][1]);
            }
        }

        if (ch + 2 < nk) {
            __syncthreads();
            issue((ch + 2) << 6, buf);
        }
    }

    const int group = lane >> 2, tig = lane & 3;
#pragma unroll
    for (int mt = 0; mt < 4; mt++) {
        int oc0 = m0 + warp_m * 64 + mt * 16 + group;
        int oc1 = oc0 + 8;
        float s0 = svec[oc0], t0 = tvec[oc0];
        float s1 = svec[oc1], t1 = tvec[oc1];
#pragma unroll
        for (int nt = 0; nt < 4; nt++) {
            int j = j0 + warp_n * 32 + nt * 8 + tig * 2;
            int b = j / 196, n = j - b * 196;
            float v00 = acc[mt][nt][0] * s0 + t0;
            float v01 = acc[mt][nt][1] * s0 + t0;
            float v10 = acc[mt][nt][2] * s1 + t1;
            float v11 = acc[mt][nt][3] * s1 + t1;
            if (!is_qkv) {
                float* p0 = out + ((size_t)b * Cout + oc0) * 196 + n;
                float* p1 = out + ((size_t)b * Cout + oc1) * 196 + n;
                p0[0] = v00; p0[1] = v01;
                p1[0] = v10; p1[1] = v11;
            } else if (m0 < 512) {
                // q/k export: [(b*16 + oc>>5)][n][oc&31]
                size_t r0 = (((size_t)(b * 16) + (oc0 >> 5)) * 196 + n) * 32 + (oc0 & 31);
                size_t r1 = (((size_t)(b * 16) + (oc1 >> 5)) * 196 + n) * 32 + (oc1 & 31);
                __nv_bfloat16 h;
                h = __float2bfloat16(v00); qk_hi[r0] = h;
                qk_lo[r0] = __float2bfloat16(v00 - __bfloat162float(h));
                h = __float2bfloat16(v01); qk_hi[r0 + 32] = h;
                qk_lo[r0 + 32] = __float2bfloat16(v01 - __bfloat162float(h));
                h = __float2bfloat16(v10); qk_hi[r1] = h;
                qk_lo[r1] = __float2bfloat16(v10 - __bfloat162float(h));
                h = __float2bfloat16(v11); qk_hi[r1 + 32] = h;
                qk_lo[r1 + 32] = __float2bfloat16(v11 - __bfloat162float(h));
            } else {
                // V export: [b][oc-512][n] in KPAD-strided rows
                size_t r0 = ((size_t)b * 1024 + (oc0 - 512)) * KPAD + n;
                size_t r1 = ((size_t)b * 1024 + (oc1 - 512)) * KPAD + n;
                __nv_bfloat16 h;
                h = __float2bfloat16(v00); g_vhi[r0] = h;
                g_vlo[r0] = __float2bfloat16(v00 - __bfloat162float(h));
                h = __float2bfloat16(v01); g_vhi[r0 + 1] = h;
                g_vlo[r0 + 1] = __float2bfloat16(v01 - __bfloat162float(h));
                h = __float2bfloat16(v10); g_vhi[r1] = h;
                g_vlo[r1] = __float2bfloat16(v10 - __bfloat162float(h));
                h = __float2bfloat16(v11); g_vhi[r1 + 1] = h;
                g_vlo[r1 + 1] = __float2bfloat16(v11 - __bfloat162float(h));
            }
        }
    }
}

// ------------------------------------------------------------------
// QK logits mma (unchanged R9).
#define QK_SMEM_BYTES 65536

__global__ void __launch_bounds__(256) qk_mma_kernel(
    const float* __restrict__ ab, const int* __restrict__ bidx)
{
    extern __shared__ __align__(1024) char smem[];
    const uint32_t sb = s2u(smem);
    const int tid = threadIdx.x;
    const int wid = tid >> 5, lane = tid & 31;
    const int warp_m = wid & 1;
    const int warp_n = wid >> 1;
    const int bh = blockIdx.z;
    const int b = bh >> 3, h = bh & 7;
    const int n0 = blockIdx.x * 128;
    const int m0c = blockIdx.y * 128;

    const __nv_bfloat16* Qhi = g_qkh_hi + (size_t)(b * 16 + h) * 196 * 32;
    const __nv_bfloat16* Qlo = g_qkh_lo + (size_t)(b * 16 + h) * 196 * 32;
    const __nv_bfloat16* Khi = g_qkh_hi + (size_t)(b * 16 + 8 + h) * 196 * 32;
    const __nv_bfloat16* Klo = g_qkh_lo + (size_t)(b * 16 + 8 + h) * 196 * 32;

#pragma unroll
    for (int t = 0; t < 2; t++) {
        int q = tid + (t << 8);
        int row = q >> 2, k8 = q & 3;
        uint32_t off = (uint32_t)(row * 128 + k8 * 16);
        uint32_t sw = off ^ ((off >> 3) & 0x70);
        int nr = n0 + row;
        int vq = nr < 196;
        size_t gq = vq ? ((size_t)nr * 32 + (k8 << 3)) : 0;
        cp_async16_zf(sb + sw,           Qhi + gq, vq);
        cp_async16_zf(sb + 16384u + sw,  Qlo + gq, vq);
        int mr = m0c + row;
        int vk = mr < 196;
        size_t gk = vk ? ((size_t)mr * 32 + (k8 << 3)) : 0;
        cp_async16_zf(sb + 32768u + sw,  Khi + gk, vk);
        cp_async16_zf(sb + 49152u + sw,  Klo + gk, vk);
    }
    asm volatile("cp.async.commit_group;" ::: "memory");
    asm volatile("cp.async.wait_group 0;" ::: "memory");
    __syncthreads();

    float acc[4][4][4];
#pragma unroll
    for (int i = 0; i < 4; i++)
#pragma unroll
        for (int j = 0; j < 4; j++)
#pragma unroll
            for (int c = 0; c < 4; c++) acc[i][j][c] = 0.f;

    const int lrow = lane & 15;
    const uint32_t lkoff = (uint32_t)((lane >> 4) << 4);

#pragma unroll
    for (int ks = 0; ks < 2; ks++) {
        uint32_t bh_[4][2], bl_[4][2];
#pragma unroll
        for (int p = 0; p < 2; p++) {
            uint32_t off = (uint32_t)((warp_n * 32 + p * 16 + lrow) * 128)
                         + (uint32_t)(ks * 32) + lkoff;
            uint32_t sw = off ^ ((off >> 3) & 0x70);
            uint32_t r0, r1, r2, r3;
            ldmat_x4(r0, r1, r2, r3, sb + 32768u + sw);
            bh_[p * 2 + 0][0] = r0; bh_[p * 2 + 1][0] = r1;
            bh_[p * 2 + 0][1] = r2; bh_[p * 2 + 1][1] = r3;
            ldmat_x4(r0, r1, r2, r3, sb + 49152u + sw);
            bl_[p * 2 + 0][0] = r0; bl_[p * 2 + 1][0] = r1;
            bl_[p * 2 + 0][1] = r2; bl_[p * 2 + 1][1] = r3;
        }
#pragma unroll
        for (int mt = 0; mt < 4; mt++) {
            uint32_t off = (uint32_t)((warp_m * 64 + mt * 16 + lrow) * 128)
                         + (uint32_t)(ks * 32) + lkoff;
            uint32_t sw = off ^ ((off >> 3) & 0x70);
            uint32_t a0, a1, a2, a3;
            ldmat_x4(a0, a1, a2, a3, sb + sw);
#pragma unroll
            for (int nt = 0; nt < 4; nt++)
                mma_bf16(acc[mt][nt][0], acc[mt][nt][1],
                         acc[mt][nt][2], acc[mt][nt][3],
                         a0, a1, a2, a3, bh_[nt][0], bh_[nt][1]);
#pragma unroll
            for (int nt = 0; nt < 4; nt++)
                mma_bf16(acc[mt][nt][0], acc[mt][nt][1],
                         acc[mt][nt][2], acc[mt][nt][3],
                         a0, a1, a2, a3, bl_[nt][0], bl_[nt][1]);
            ldmat_x4(a0, a1, a2, a3, sb + 16384u + sw);
#pragma unroll
            for (int nt = 0; nt < 4; nt++)
                mma_bf16(acc[mt][nt][0], acc[mt][nt][1],
                         acc[mt][nt][2], acc[mt][nt][3],
                         a0, a1, a2, a3, bh_[nt][0], bh_[nt][1]);
        }
    }

    const int group = lane >> 2, tig = lane & 3;
    const float* abh = ab + h * 196;
    float* lbase = g_logits + (size_t)bh * 196 * 196;
#pragma unroll
    for (int mt = 0; mt < 4; mt++) {
        int nr0 = n0 + warp_m * 64 + mt * 16 + group;
        int nr1 = nr0 + 8;
#pragma unroll
        for (int nt = 0; nt < 4; nt++) {
            int m = m0c + warp_n * 32 + nt * 8 + tig * 2;
            if (m < 196) {
                if (nr0 < 196) {
                    const int* br = bidx + (size_t)nr0 * 196;
                    lbase[(size_t)nr0 * 196 + m]     = acc[mt][nt][0] * SCALEF + abh[br[m]];
                    lbase[(size_t)nr0 * 196 + m + 1] = acc[mt][nt][1] * SCALEF + abh[br[m + 1]];
                }
                if (nr1 < 196) {
                    const int* br = bidx + (size_t)nr1 * 196;
                    lbase[(size_t)nr1 * 196 + m]     = acc[mt][nt][2] * SCALEF + abh[br[m]];
                    lbase[(size_t)nr1 * 196 + m + 1] = acc[mt][nt][3] * SCALEF + abh[br[m + 1]];
                }
            }
        }
    }
}

// ------------------------------------------------------------------
// AV batched mma + fused relu(D+v_local) -> g_pt epilogue (unchanged R9).
__global__ void __launch_bounds__(256) av_mma_kernel()
{
    extern __shared__ __align__(1024) char smem[];
    const uint32_t sb = s2u(smem);
    const int tid = threadIdx.x;
    const int wid = tid >> 5, lane = tid & 31;
    const int warp_m = wid & 1;
    const int warp_n = wid >> 1;
    const int bo = blockIdx.y;
    const int b  = bo >> 3, o = bo & 7;
    const int j0 = blockIdx.x * 128;
    const int nk = 4;

    const __nv_bfloat16* Ahi = g_vhi + ((size_t)b * 1024 + o * 128) * KPAD;
    const __nv_bfloat16* Alo = g_vlo + ((size_t)b * 1024 + o * 128) * KPAD;
    const __nv_bfloat16* Bhi = g_phi + ((size_t)bo * 196) * KPAD;
    const __nv_bfloat16* Blo = g_plo + ((size_t)bo * 196) * KPAD;

    float acc[4][4][4];
#pragma unroll
    for (int i = 0; i < 4; i++)
#pragma unroll
        for (int j = 0; j < 4; j++)
#pragma unroll
            for (int c = 0; c < 4; c++) acc[i][j][c] = 0.f;

    const int lrow = lane & 15;
    const uint32_t lkoff = (uint32_t)((lane >> 4) << 4);

    auto issue = [&](int kb, uint32_t stage_off) {
#pragma unroll
        for (int i = 0; i < 4; i++) {
            int q = tid + (i << 8);
            int row = q >> 3, k8 = q & 7;
            uint32_t off = (uint32_t)(row * 128 + k8 * 16);
            uint32_t sw = off ^ ((off >> 3) & 0x70);
            size_t ga = (size_t)row * KPAD + kb + (k8 << 3);
            cp_async16(sb + stage_off + sw,          Ahi + ga);
            cp_async16(sb + stage_off + 16384u + sw, Alo + ga);
            int jrow = j0 + row;
            int valid = (jrow < 196);
            size_t gb = valid ? ((size_t)jrow * KPAD + kb + (k8 << 3)) : 0;
            cp_async16_zf(sb + stage_off + 32768u + sw, Bhi + gb, valid);
            cp_async16_zf(sb + stage_off + 49152u + sw, Blo + gb, valid);
        }
        asm volatile("cp.async.commit_group;" ::: "memory");
    };

    issue(0, 0u);
    issue(64, GEMM_STAGE_BYTES);

    for (int ch = 0; ch < nk; ch++) {
        if (ch + 1 < nk) asm volatile("cp.async.wait_group 1;" ::: "memory");
        else             asm volatile("cp.async.wait_group 0;" ::: "memory");
        __syncthreads();

        const uint32_t buf = (ch & 1) ? (uint32_t)GEMM_STAGE_BYTES : 0u;
#pragma unroll
        for (int ks = 0; ks < 4; ks++) {
            uint32_t bh[4][2], bl[4][2];
#pragma unroll
            for (int p = 0; p < 2; p++) {
                uint32_t off = (uint32_t)((warp_n * 32 + p * 16 + lrow) * 128)
                             + (uint32_t)(ks * 32) + lkoff;
                uint32_t sw = off ^ ((off >> 3) & 0x70);
                uint32_t r0, r1, r2, r3;
                ldmat_x4(r0, r1, r2, r3, sb + buf + 32768u + sw);
                bh[p * 2 + 0][0] = r0; bh[p * 2 + 1][0] = r1;
                bh[p * 2 + 0][1] = r2; bh[p * 2 + 1][1] = r3;
                ldmat_x4(r0, r1, r2, r3, sb + buf + 49152u + sw);
                bl[p * 2 + 0][0] = r0; bl[p * 2 + 1][0] = r1;
                bl[p * 2 + 0][1] = r2; bl[p * 2 + 1][1] = r3;
            }
#pragma unroll
            for (int mt = 0; mt < 4; mt++) {
                uint32_t off = (uint32_t)((warp_m * 64 + mt * 16 + lrow) * 128)
                             + (uint32_t)(ks * 32) + lkoff;
                uint32_t sw = off ^ ((off >> 3) & 0x70);
                uint32_t a0, a1, a2, a3;
                ldmat_x4(a0, a1, a2, a3, sb + buf + sw);
#pragma unroll
                for (int nt = 0; nt < 4; nt++)
                    mma_bf16(acc[mt][nt][0], acc[mt][nt][1],
                             acc[mt][nt][2], acc[mt][nt][3],
                             a0, a1, a2, a3, bh[nt][0], bh[nt][1]);
#pragma unroll
                for (int nt = 0; nt < 4; nt++)
                    mma_bf16(acc[mt][nt][0], acc[mt][nt][1],
                             acc[mt][nt][2], acc[mt][nt][3],
                             a0, a1, a2, a3, bl[nt][0], bl[nt][1]);
                ldmat_x4(a0, a1, a2, a3, sb + buf + 16384u + sw);
#pragma unroll
                for (int nt = 0; nt < 4; nt++)
                    mma_bf16(acc[mt][nt][0], acc[mt][nt][1],
                             acc[mt][nt][2], acc[mt][nt][3],
                             a0, a1, a2, a3, bh[nt][0], bh[nt][1]);
            }
        }

        if (ch + 2 < nk) {
            __syncthreads();
            issue((ch + 2) << 6, buf);
        }
    }

    const int group = lane >> 2, tig = lane & 3;
    const float* vlbase = g_vloc + ((size_t)b * 1024 + o * 128) * NPIX;
#pragma unroll
    for (int mt = 0; mt < 4; mt++) {
        int e0 = warp_m * 64 + mt * 16 + group;
        int e1 = e0 + 8;
#pragma unroll
        for (int nt = 0; nt < 4; nt++) {
            int j = j0 + warp_n * 32 + nt * 8 + tig * 2;
            if (j < 196) {
                float v00 = fmaxf(acc[mt][nt][0] + vlbase[(size_t)e0 * NPIX + j],     0.f);
                float v01 = fmaxf(acc[mt][nt][1] + vlbase[(size_t)e0 * NPIX + j + 1], 0.f);
                float v10 = fmaxf(acc[mt][nt][2] + vlbase[(size_t)e1 * NPIX + j],     0.f);
                float v11 = fmaxf(acc[mt][nt][3] + vlbase[(size_t)e1 * NPIX + j + 1], 0.f);
                size_t r00 = ((size_t)(b * 196 + j))     * 1024 + o * 128 + e0;
                size_t r01 = ((size_t)(b * 196 + j + 1)) * 1024 + o * 128 + e0;
                __nv_bfloat16 h;
                h = __float2bfloat16(v00); g_pt_hi[r00] = h;
                g_pt_lo[r00] = __float2bfloat16(v00 - __bfloat162float(h));
                h = __float2bfloat16(v01); g_pt_hi[r01] = h;
                g_pt_lo[r01] = __float2bfloat16(v01 - __bfloat162float(h));
                h = __float2bfloat16(v10); g_pt_hi[r00 + 8] = h;
                g_pt_lo[r00 + 8] = __float2bfloat16(v10 - __bfloat162float(h));
                h = __float2bfloat16(v11); g_pt_hi[r01 + 8] = h;
                g_pt_lo[r01 + 8] = __float2bfloat16(v11 - __bfloat162float(h));
            }
        }
    }
}

// ------------------------------------------------------------------
// Depthwise 3x3 conv v3: input from bf16 hi/lo V export (no fp32 round-trip).
__global__ void __launch_bounds__(256) dwconv_kernel(
    const float* __restrict__ wvl, const float* __restrict__ bvl,
    const float* __restrict__ bn)
{
    int c0 = blockIdx.x * 8, b = blockIdx.y;
    __shared__ float p[8 * 256];     // 8 channels x 16x16 zero-halo plane
    __shared__ float wsh[72];
    __shared__ float cs[8], ct[8];
    int tid = threadIdx.x;
    const __nv_bfloat16* vhi = g_vhi + ((size_t)b * 1024 + c0) * KPAD;
    const __nv_bfloat16* vlo = g_vlo + ((size_t)b * 1024 + c0) * KPAD;

    for (int i = tid; i < 2048; i += 256) {
        int c = i >> 8, idx = i & 255;
        int y = idx >> 4, x = idx & 15;
        float v = 0.f;
        if (y >= 1 && y <= 14 && x >= 1 && x <= 14) {
            int pix = (y - 1) * 14 + (x - 1);
            size_t off = (size_t)c * KPAD + pix;
            v = __bfloat162float(vhi[off]) + __bfloat162float(vlo[off]);
        }
        p[i] = v;
    }
    if (tid < 72) wsh[tid] = wvl[c0 * 9 + tid];
    if (tid < 8) {
        int c = c0 + tid;
        float s = bn[c] * rsqrtf(bn[3072 + c] + EPSF);
        cs[tid] = s;
        ct[tid] = (bvl[c] - bn[2048 + c]) * s + bn[1024 + c];
    }
    __syncthreads();

    int w = tid >> 5, lane = tid & 31;
    if (lane < 28) {
        const float* pc = p + w * 256;
        float w00 = wsh[w * 9 + 0], w01 = wsh[w * 9 + 1], w02 = wsh[w * 9 + 2];
        float w10 = wsh[w * 9 + 3], w11 = wsh[w * 9 + 4], w12 = wsh[w * 9 + 5];
        float w20 = wsh[w * 9 + 6], w21 = wsh[w * 9 + 7], w22 = wsh[w * 9 + 8];
        float s = cs[w], t = ct[w];
        float* dst = g_vloc + (size_t)b * (DHC * NPIX) + (size_t)(c0 + w) * NPIX;
        int xr = lane >= 14;
        int x = lane - xr * 14;
#pragma unroll
        for (int it = 0; it < 7; it++) {
            int y = it * 2 + xr;
            const float* q = pc + y * 16 + x;
            float acc = w00 * q[0]  + w01 * q[1]  + w02 * q[2]
                      + w10 * q[16] + w11 * q[17] + w12 * q[18]
                      + w20 * q[32] + w21 * q[33] + w22 * q[34];
            dst[y * 14 + x] = acc * s + t;
        }
    }
}

// ------------------------------------------------------------------
// Attention core v5: TH1 (reads g_logits) + softmax + fused TH2+P-export.
#define ATTN_SMEM_FLOATS (21952 + 144)

__global__ void __launch_bounds__(256, 2) attn_kernel(
    const float* __restrict__ th1w, const float* __restrict__ th1b,
    const float* __restrict__ th2w, const float* __restrict__ th2b)
{
    extern __shared__ float sm[];
    float* L  = sm;
    float* th = sm + 21952;

    int tid = threadIdx.x;
    int b = blockIdx.y;
    int n0 = blockIdx.x * 14;

    if (tid < 64)       th[tid] = th1w[tid];
    else if (tid < 72)  th[tid] = th1b[tid - 64];
    else if (tid < 136) th[tid] = th2w[tid - 72];
    else if (tid < 144) th[tid] = th2b[tid - 136];
    __syncthreads();

    const float* lgbase = g_logits + (size_t)(b * 8) * 196 * 196;
    for (int idx = tid; idx < 2744; idx += 256) {
        int n_ = idx / 196, m = idx - n_ * 196;
        size_t rowoff = (size_t)(n0 + n_) * 196 + m;
        float v[8], o_[8];
#pragma unroll
        for (int hh = 0; hh < 8; hh++)
            v[hh] = lgbase[(size_t)hh * 196 * 196 + rowoff];
#pragma unroll
        for (int oo = 0; oo < 8; oo++) {
            float s = th[64 + oo];
#pragma unroll
            for (int hh = 0; hh < 8; hh++) s = fmaf(th[oo * 8 + hh], v[hh], s);
            o_[oo] = s;
        }
#pragma unroll
        for (int oo = 0; oo < 8; oo++) L[(oo * 14 + n_) * 196 + m] = o_[oo];
    }
    __syncthreads();

    {
        int w = tid >> 5, lane = tid & 31;
        for (int r = 0; r < 14; r++) {
            float* row = L + (w * 14 + r) * 196;
            float mx = -1e30f;
            for (int m = lane; m < 196; m += 32) mx = fmaxf(mx, row[m]);
#pragma unroll
            for (int off = 16; off > 0; off >>= 1)
                mx = fmaxf(mx, __shfl_xor_sync(0xffffffffu, mx, off));
            float sum = 0.f;
            for (int m = lane; m < 196; m += 32) {
                float e = __expf(row[m] - mx);
                row[m] = e; sum += e;
            }
#pragma unroll
            for (int off = 16; off > 0; off >>= 1)
                sum += __shfl_xor_sync(0xffffffffu, sum, off);
            float inv = 1.f / sum;
            for (int m = lane; m < 196; m += 32) row[m] *= inv;
        }
    }
    __syncthreads();

    for (int idx = tid; idx < 2744; idx += 256) {
        int n_ = idx / 196, m = idx - n_ * 196;
        float v[8];
#pragma unroll
        for (int hh = 0; hh < 8; hh++) v[hh] = L[(hh * 14 + n_) * 196 + m];
        size_t rbase = (size_t)(b * 8) * 196 + n0 + n_;
#pragma unroll
        for (int oo = 0; oo < 8; oo++) {
            float s = th[136 + oo];
#pragma unroll
            for (int hh = 0; hh < 8; hh++) s = fmaf(th[72 + oo * 8 + hh], v[hh], s);
            __nv_bfloat16 hh2 = __float2bfloat16(s);
            size_t row = rbase + (size_t)oo * 196;
            g_phi[row * KPAD + m] = hh2;
            g_plo[row * KPAD + m] = __float2bfloat16(s - __bfloat162float(hh2));
        }
    }
}

// ------------------------------------------------------------------
extern "C" void kernel_launch(void* const* d_in, const int* in_sizes, int n_in,
                              void* d_out, int out_size)
{
    const float* x    = (const float*)d_in[0];
    const float* wq   = (const float*)d_in[1];
    const float* bq   = (const float*)d_in[2];
    const float* bnq  = (const float*)d_in[3];
    const float* wk   = (const float*)d_in[4];
    const float* bk   = (const float*)d_in[5];
    const float* bnk  = (const float*)d_in[6];
    const float* wv   = (const float*)d_in[7];
    const float* bv   = (const float*)d_in[8];
    const float* bnv  = (const float*)d_in[9];
    const float* wvl  = (const float*)d_in[10];
    const float* bvl  = (const float*)d_in[11];
    const float* bnvl = (const float*)d_in[12];
    const float* th1w = (const float*)d_in[13];
    const float* th1b = (const float*)d_in[14];
    const float* th2w = (const float*)d_in[15];
    const float* th2b = (const float*)d_in[16];
    const float* wp   = (const float*)d_in[17];
    const float* bp   = (const float*)d_in[18];
    const float* bnp  = (const float*)d_in[19];
    const float* ab   = (const float*)d_in[20];
    const int*   bidx = (const int*)d_in[21];
    float* out = (float*)d_out;

    const int attn_smem = ATTN_SMEM_FLOATS * (int)sizeof(float);
    cudaFuncSetAttribute(attn_kernel,
                         cudaFuncAttributeMaxDynamicSharedMemorySize, attn_smem);
    cudaFuncSetAttribute(gemm_mma_kernel,
                         cudaFuncAttributeMaxDynamicSharedMemorySize, GEMM_SMEM_BYTES);
    cudaFuncSetAttribute(av_mma_kernel,
                         cudaFuncAttributeMaxDynamicSharedMemorySize, GEMM_SMEM_BYTES);
    cudaFuncSetAttribute(qk_mma_kernel,
                         cudaFuncAttributeMaxDynamicSharedMemorySize, QK_SMEM_BYTES);

    __nv_bfloat16 *wqkv_hi, *wqkv_lo, *xt_hi, *xt_lo, *wp_hi, *wp_lo, *pt_hi, *pt_lo;
    __nv_bfloat16 *qkh_hi, *qkh_lo;
    float *sv, *tv;
    cudaGetSymbolAddress((void**)&wqkv_hi, g_wqkv_hi);
    cudaGetSymbolAddress((void**)&wqkv_lo, g_wqkv_lo);
    cudaGetSymbolAddress((void**)&xt_hi, g_xt_hi);
    cudaGetSymbolAddress((void**)&xt_lo, g_xt_lo);
    cudaGetSymbolAddress((void**)&wp_hi, g_wp_hi);
    cudaGetSymbolAddress((void**)&wp_lo, g_wp_lo);
    cudaGetSymbolAddress((void**)&pt_hi, g_pt_hi);
    cudaGetSymbolAddress((void**)&pt_lo, g_pt_lo);
    cudaGetSymbolAddress((void**)&qkh_hi, g_qkh_hi);
    cudaGetSymbolAddress((void**)&qkh_lo, g_qkh_lo);
    cudaGetSymbolAddress((void**)&sv, g_s);
    cudaGetSymbolAddress((void**)&tv, g_t);

    // 1. fold BN + split weights + zero k-pads
    prep_kernel<<<2304, 256>>>(wq, wk, wv, wp, bq, bk, bv, bp, bnq, bnk, bnv, bnp);
    // 2. transpose+split x
    xt_cvt_kernel<<<dim3(7, 12, 64), 256>>>(x);
    // 3. fused qkv GEMM: exports q/k (g_qkh) and V (g_vhi/g_vlo); no fp32 out
    gemm_mma_kernel<<<dim3(98, 12), 256, GEMM_SMEM_BYTES>>>(
        wqkv_hi, wqkv_lo, xt_hi, xt_lo, 384, sv, tv, nullptr, 1536, qkh_hi, qkh_lo);
    // 4. depthwise conv + BN (reads bf16 V export)
    dwconv_kernel<<<dim3(128, 64), 256>>>(wvl, bvl, bnvl);
    // 5. QK logits on tensor cores (+ scale + positional bias)
    qk_mma_kernel<<<dim3(2, 2, 512), 256, QK_SMEM_BYTES>>>(ab, bidx);
    // 6. attention core (TH1, softmax, fused TH2+P export)
    attn_kernel<<<dim3(14, 64), 256, attn_smem>>>(th1w, th1b, th2w, th2b);
    // 7. AV on tensor cores (+ fused relu(att+v_local) -> proj input)
    av_mma_kernel<<<dim3(2, 512), 256, GEMM_SMEM_BYTES>>>();
    // 8. projection GEMM (M=384, K=1024)
    gemm_mma_kernel<<<dim3(98, 3), 256, GEMM_SMEM_BYTES>>>(
        wp_hi, wp_lo, pt_hi, pt_lo, 1024, sv + 1536, tv + 1536, out, 384,
        nullptr, nullptr);
}

// round 11
// speedup vs baseline: 3.5931x; 1.0326x over previous
#include <cuda_runtime.h>
#include <cuda_bf16.h>
#include <math.h>
#include <stdint.h>

#define EPSF 1e-5f
#define SCALEF 0.17677669529663687f

#define NB   64
#define NPIX 196
#define DHC  1024
#define NCOL 12544   // 64*196
#define KPAD 208     // padded k (m) dimension for AV mma (13*16)

// ------------------------------------------------------------------
// scratch (no cudaMalloc allowed)
__device__ float g_vloc[NB * DHC * NPIX];    // [b][1024][196]
__device__ float g_logits[512 * 196 * 196];  // [(b*8+h)][n][m] post-bias logits

__device__ __align__(16) __nv_bfloat16 g_xt_hi[NCOL * 384];   // [j][k]
__device__ __align__(16) __nv_bfloat16 g_xt_lo[NCOL * 384];
__device__ __align__(16) __nv_bfloat16 g_pt_hi[NCOL * 1024];  // [j][k]
__device__ __align__(16) __nv_bfloat16 g_pt_lo[NCOL * 1024];
__device__ __align__(16) __nv_bfloat16 g_wqkv_hi[1536 * 384]; // [m][k]
__device__ __align__(16) __nv_bfloat16 g_wqkv_lo[1536 * 384];
__device__ __align__(16) __nv_bfloat16 g_wp_hi[384 * 1024];
__device__ __align__(16) __nv_bfloat16 g_wp_lo[384 * 1024];
// q/k export: [(b*16 + hh)][n][d=32] bf16 hi/lo; hh 0-7 = q heads, 8-15 = k heads
__device__ __align__(16) __nv_bfloat16 g_qkh_hi[NB * 16 * 196 * 32];
__device__ __align__(16) __nv_bfloat16 g_qkh_lo[NB * 16 * 196 * 32];
// attention P (post-softmax/TH2) bf16 hi/lo: [(b*8+o)*196 + n][k=KPAD] (+ tail pad)
__device__ __align__(16) __nv_bfloat16 g_phi[512 * 196 * KPAD + 128];
__device__ __align__(16) __nv_bfloat16 g_plo[512 * 196 * KPAD + 128];
// BN'd V bf16 hi/lo: [b][c(1024)][k=KPAD] (written by qkv GEMM epilogue)
__device__ __align__(16) __nv_bfloat16 g_vhi[NB * 1024 * KPAD + 128];
__device__ __align__(16) __nv_bfloat16 g_vlo[NB * 1024 * KPAD + 128];
__device__ float g_s[1920];   // folded BN scale: [0:1536) qkv, [1536:1920) proj
__device__ float g_t[1920];   // folded BN shift

// ------------------------------------------------------------------
static __device__ __forceinline__ uint32_t s2u(const void* p) {
    uint32_t a;
    asm("{ .reg .u64 t; cvta.to.shared.u64 t, %1; cvt.u32.u64 %0, t; }"
        : "=r"(a) : "l"(p));
    return a;
}

static __device__ __forceinline__ void cp_async16(uint32_t saddr, const void* gptr) {
    asm volatile("cp.async.cg.shared.global [%0], [%1], 16;"
                 :: "r"(saddr), "l"(gptr) : "memory");
}

static __device__ __forceinline__ void cp_async16_zf(uint32_t saddr, const void* gptr, int valid) {
    int sz = valid ? 16 : 0;
    asm volatile("cp.async.cg.shared.global [%0], [%1], 16, %2;"
                 :: "r"(saddr), "l"(gptr), "r"(sz) : "memory");
}

static __device__ __forceinline__ void ldmat_x4(
    uint32_t& r0, uint32_t& r1, uint32_t& r2, uint32_t& r3, uint32_t addr)
{
    asm volatile("ldmatrix.sync.aligned.m8n8.x4.shared.b16 {%0,%1,%2,%3}, [%4];"
                 : "=r"(r0), "=r"(r1), "=r"(r2), "=r"(r3) : "r"(addr));
}

static __device__ __forceinline__ void mma_bf16(
    float& d0, float& d1, float& d2, float& d3,
    uint32_t a0, uint32_t a1, uint32_t a2, uint32_t a3,
    uint32_t b0, uint32_t b1)
{
    asm volatile(
        "mma.sync.aligned.m16n8k16.row.col.f32.bf16.bf16.f32 "
        "{%0,%1,%2,%3}, {%4,%5,%6,%7}, {%8,%9}, {%0,%1,%2,%3};"
        : "+f"(d0), "+f"(d1), "+f"(d2), "+f"(d3)
        : "r"(a0), "r"(a1), "r"(a2), "r"(a3), "r"(b0), "r"(b1));
}

// ------------------------------------------------------------------
// Prep: fold BN; split weights into bf16 hi/lo; zero k-pads (3 u64/row).
__global__ void __launch_bounds__(256) prep_kernel(
    const float* __restrict__ wq, const float* __restrict__ wk,
    const float* __restrict__ wv, const float* __restrict__ wp,
    const float* __restrict__ bq, const float* __restrict__ bk,
    const float* __restrict__ bv, const float* __restrict__ bp,
    const float* __restrict__ bnq, const float* __restrict__ bnk,
    const float* __restrict__ bnv, const float* __restrict__ bnp)
{
    int idx = blockIdx.x * 256 + threadIdx.x;
    int stride = gridDim.x * 256;

    for (int i = idx; i < 1536 * 384; i += stride) {
        int m = i / 384;
        float w = (m < 256) ? wq[i]
                : (m < 512) ? wk[i - 256 * 384]
                            : wv[i - 512 * 384];
        __nv_bfloat16 h = __float2bfloat16(w);
        g_wqkv_hi[i] = h;
        g_wqkv_lo[i] = __float2bfloat16(w - __bfloat162float(h));
    }
    for (int i = idx; i < 384 * 1024; i += stride) {
        float w = wp[i];
        __nv_bfloat16 h = __float2bfloat16(w);
        g_wp_hi[i] = h;
        g_wp_lo[i] = __float2bfloat16(w - __bfloat162float(h));
    }
    // zero P k-pad: rows 512*196, row stride 416B, pad = 24B at offset 392 (3 u64)
    for (long i = idx; i < (long)100352 * 3; i += stride) {
        long r = i / 3; int k = (int)(i % 3);
        *(unsigned long long*)((char*)g_phi + r * 416 + 392 + k * 8) = 0ull;
        *(unsigned long long*)((char*)g_plo + r * 416 + 392 + k * 8) = 0ull;
    }
    // zero V k-pad: rows 64*1024
    for (long i = idx; i < (long)65536 * 3; i += stride) {
        long r = i / 3; int k = (int)(i % 3);
        *(unsigned long long*)((char*)g_vhi + r * 416 + 392 + k * 8) = 0ull;
        *(unsigned long long*)((char*)g_vlo + r * 416 + 392 + k * 8) = 0ull;
    }
    // zero tail pads
    if (idx < 128) {
        g_phi[512 * 196 * KPAD + idx] = __float2bfloat16(0.f);
        g_plo[512 * 196 * KPAD + idx] = __float2bfloat16(0.f);
        g_vhi[NB * 1024 * KPAD + idx] = __float2bfloat16(0.f);
        g_vlo[NB * 1024 * KPAD + idx] = __float2bfloat16(0.f);
    }
    if (idx < 1920) {
        const float* bn; const float* bias; int c; int C;
        if (idx < 256)       { bn = bnq; bias = bq; c = idx;        C = 256; }
        else if (idx < 512)  { bn = bnk; bias = bk; c = idx - 256;  C = 256; }
        else if (idx < 1536) { bn = bnv; bias = bv; c = idx - 512;  C = 1024; }
        else                 { bn = bnp; bias = bp; c = idx - 1536; C = 384; }
        float s = bn[c] * rsqrtf(bn[3 * C + c] + EPSF);
        g_s[idx] = s;
        g_t[idx] = (bias[c] - bn[2 * C + c]) * s + bn[C + c];
    }
}

// ------------------------------------------------------------------
// Transpose+split x: [b][384][196] -> Xt[j=b*196+n][k=c] bf16 hi/lo
__global__ void __launch_bounds__(256) xt_cvt_kernel(const float* __restrict__ X)
{
    __shared__ float t[32][29];
    int b = blockIdx.z, c0 = blockIdx.y * 32, n0 = blockIdx.x * 28;
    int tid = threadIdx.x;
    const float* src = X + ((size_t)b * 384 + c0) * 196 + n0;
    for (int i = tid; i < 32 * 28; i += 256) {
        int ci = i / 28, nj = i - ci * 28;
        t[ci][nj] = src[(size_t)ci * 196 + nj];
    }
    __syncthreads();
    for (int i = tid; i < 32 * 28; i += 256) {
        int nj = i >> 5, ci = i & 31;
        float v = t[ci][nj];
        __nv_bfloat16 h = __float2bfloat16(v);
        size_t o = ((size_t)(b * 196 + n0 + nj)) * 384 + c0 + ci;
        g_xt_hi[o] = h;
        g_xt_lo[o] = __float2bfloat16(v - __bfloat162float(h));
    }
}

// ------------------------------------------------------------------
// bf16 mma.sync GEMM, 3-term compensation fused per K-chunk (epilogue modes as R10).
#define GEMM_STAGE_BYTES 65536
#define GEMM_SMEM_BYTES  (2 * GEMM_STAGE_BYTES)

__global__ void __launch_bounds__(256) gemm_mma_kernel(
    const __nv_bfloat16* __restrict__ Ahi, const __nv_bfloat16* __restrict__ Alo,
    const __nv_bfloat16* __restrict__ Bhi, const __nv_bfloat16* __restrict__ Blo,
    int K, const float* __restrict__ svec, const float* __restrict__ tvec,
    float* __restrict__ out, int Cout,
    __nv_bfloat16* __restrict__ qk_hi, __nv_bfloat16* __restrict__ qk_lo)
{
    extern __shared__ __align__(1024) char smem[];
    const uint32_t sb = s2u(smem);
    const int tid = threadIdx.x;
    const int wid = tid >> 5, lane = tid & 31;
    const int warp_m = wid & 1;
    const int warp_n = wid >> 1;
    const int m0 = blockIdx.y * 128;
    const int j0 = blockIdx.x * 128;
    const int nk = K >> 6;
    const bool is_qkv = (qk_hi != nullptr);

    float acc[4][4][4];
#pragma unroll
    for (int i = 0; i < 4; i++)
#pragma unroll
        for (int j = 0; j < 4; j++)
#pragma unroll
            for (int c = 0; c < 4; c++) acc[i][j][c] = 0.f;

    const int lrow = lane & 15;
    const uint32_t lkoff = (uint32_t)((lane >> 4) << 4);

    auto issue = [&](int kb, uint32_t stage_off) {
#pragma unroll
        for (int i = 0; i < 4; i++) {
            int q = tid + (i << 8);
            int row = q >> 3, k8 = q & 7;
            uint32_t off = (uint32_t)(row * 128 + k8 * 16);
            uint32_t sw = off ^ ((off >> 3) & 0x70);
            size_t ga = (size_t)(m0 + row) * K + kb + (k8 << 3);
            size_t gb = (size_t)(j0 + row) * K + kb + (k8 << 3);
            cp_async16(sb + stage_off + sw,           Ahi + ga);
            cp_async16(sb + stage_off + 16384u + sw,  Alo + ga);
            cp_async16(sb + stage_off + 32768u + sw,  Bhi + gb);
            cp_async16(sb + stage_off + 49152u + sw,  Blo + gb);
        }
        asm volatile("cp.async.commit_group;" ::: "memory");
    };

    issue(0, 0u);
    if (nk > 1) issue(64, GEMM_STAGE_BYTES);

    for (int ch = 0; ch < nk; ch++) {
        if (ch + 1 < nk) asm volatile("cp.async.wait_group 1;" ::: "memory");
        else             asm volatile("cp.async.wait_group 0;" ::: "memory");
        __syncthreads();

        const uint32_t buf = (ch & 1) ? (uint32_t)GEMM_STAGE_BYTES : 0u;
#pragma unroll
        for (int ks = 0; ks < 4; ks++) {
            uint32_t bh[4][2], bl[4][2];
#pragma unroll
            for (int p = 0; p < 2; p++) {
                uint32_t off = (uint32_t)((warp_n * 32 + p * 16 + lrow) * 128)
                             + (uint32_t)(ks * 32) + lkoff;
                uint32_t sw = off ^ ((off >> 3) & 0x70);
                uint32_t r0, r1, r2, r3;
                ldmat_x4(r0, r1, r2, r3, sb + buf + 32768u + sw);
                bh[p * 2 + 0][0] = r0; bh[p * 2 + 1][0] = r1;
                bh[p * 2 + 0][1] = r2; bh[p * 2 + 1][1] = r3;
                ldmat_x4(r0, r1, r2, r3, sb + buf + 49152u + sw);
                bl[p * 2 + 0][0] = r0; bl[p * 2 + 1][0] = r1;
                bl[p * 2 + 0][1] = r2; bl[p * 2 + 1][1] = r3;
            }
#pragma unroll
            for (int mt = 0; mt < 4; mt++) {
                uint32_t off = (uint32_t)((warp_m * 64 + mt * 16 + lrow) * 128)
                             + (uint32_t)(ks * 32) + lkoff;
                uint32_t sw = off ^ ((off >> 3) & 0x70);
                uint32_t a0, a1, a2, a3;
                ldmat_x4(a0, a1, a2, a3, sb + buf + sw);
#pragma unroll
                for (int nt = 0; nt < 4; nt++)
                    mma_bf16(acc[mt][nt][0], acc[mt][nt][1],
                             acc[mt][nt][2], acc[mt][nt][3],
                             a0, a1, a2, a3, bh[nt][0], bh[nt][1]);
#pragma unroll
                for (int nt = 0; nt < 4; nt++)
                    mma_bf16(acc[mt][nt][0], acc[mt][nt][1],
                             acc[mt][nt][2], acc[mt][nt][3],
                             a0, a1, a2, a3, bl[nt][0], bl[nt][1]);
                ldmat_x4(a0, a1, a2, a3, sb + buf + 16384u + sw);
#pragma unroll
                for (int nt = 0; nt < 4; nt++)
                    mma_bf16(acc[mt][nt][0], acc[mt][nt][1],
                             acc[mt][nt][2], acc[mt][nt][3],
                             a0, a1, a2, a3, bh[nt][0], bh[nt][1]);
            }
        }

        if (ch + 2 < nk) {
            __syncthreads();
            issue((ch + 2) << 6, buf);
        }
    }

    const int group = lane >> 2, tig = lane & 3;
#pragma unroll
    for (int mt = 0; mt < 4; mt++) {
        int oc0 = m0 + warp_m * 64 + mt * 16 + group;
        int oc1 = oc0 + 8;
        float s0 = svec[oc0], t0 = tvec[oc0];
        float s1 = svec[oc1], t1 = tvec[oc1];
#pragma unroll
        for (int nt = 0; nt < 4; nt++) {
            int j = j0 + warp_n * 32 + nt * 8 + tig * 2;
            int b = j / 196, n = j - b * 196;
            float v00 = acc[mt][nt][0] * s0 + t0;
            float v01 = acc[mt][nt][1] * s0 + t0;
            float v10 = acc[mt][nt][2] * s1 + t1;
            float v11 = acc[mt][nt][3] * s1 + t1;
            if (!is_qkv) {
                float* p0 = out + ((size_t)b * Cout + oc0) * 196 + n;
                float* p1 = out + ((size_t)b * Cout + oc1) * 196 + n;
                p0[0] = v00; p0[1] = v01;
                p1[0] = v10; p1[1] = v11;
            } else if (m0 < 512) {
                size_t r0 = (((size_t)(b * 16) + (oc0 >> 5)) * 196 + n) * 32 + (oc0 & 31);
                size_t r1 = (((size_t)(b * 16) + (oc1 >> 5)) * 196 + n) * 32 + (oc1 & 31);
                __nv_bfloat16 h;
                h = __float2bfloat16(v00); qk_hi[r0] = h;
                qk_lo[r0] = __float2bfloat16(v00 - __bfloat162float(h));
                h = __float2bfloat16(v01); qk_hi[r0 + 32] = h;
                qk_lo[r0 + 32] = __float2bfloat16(v01 - __bfloat162float(h));
                h = __float2bfloat16(v10); qk_hi[r1] = h;
                qk_lo[r1] = __float2bfloat16(v10 - __bfloat162float(h));
                h = __float2bfloat16(v11); qk_hi[r1 + 32] = h;
                qk_lo[r1 + 32] = __float2bfloat16(v11 - __bfloat162float(h));
            } else {
                size_t r0 = ((size_t)b * 1024 + (oc0 - 512)) * KPAD + n;
                size_t r1 = ((size_t)b * 1024 + (oc1 - 512)) * KPAD + n;
                __nv_bfloat16 h;
                h = __float2bfloat16(v00); g_vhi[r0] = h;
                g_vlo[r0] = __float2bfloat16(v00 - __bfloat162float(h));
                h = __float2bfloat16(v01); g_vhi[r0 + 1] = h;
                g_vlo[r0 + 1] = __float2bfloat16(v01 - __bfloat162float(h));
                h = __float2bfloat16(v10); g_vhi[r1] = h;
                g_vlo[r1] = __float2bfloat16(v10 - __bfloat162float(h));
                h = __float2bfloat16(v11); g_vhi[r1 + 1] = h;
                g_vlo[r1 + 1] = __float2bfloat16(v11 - __bfloat162float(h));
            }
        }
    }
}

// ------------------------------------------------------------------
// QK logits mma (unchanged).
#define QK_SMEM_BYTES 65536

__global__ void __launch_bounds__(256) qk_mma_kernel(
    const float* __restrict__ ab, const int* __restrict__ bidx)
{
    extern __shared__ __align__(1024) char smem[];
    const uint32_t sb = s2u(smem);
    const int tid = threadIdx.x;
    const int wid = tid >> 5, lane = tid & 31;
    const int warp_m = wid & 1;
    const int warp_n = wid >> 1;
    const int bh = blockIdx.z;
    const int b = bh >> 3, h = bh & 7;
    const int n0 = blockIdx.x * 128;
    const int m0c = blockIdx.y * 128;

    const __nv_bfloat16* Qhi = g_qkh_hi + (size_t)(b * 16 + h) * 196 * 32;
    const __nv_bfloat16* Qlo = g_qkh_lo + (size_t)(b * 16 + h) * 196 * 32;
    const __nv_bfloat16* Khi = g_qkh_hi + (size_t)(b * 16 + 8 + h) * 196 * 32;
    const __nv_bfloat16* Klo = g_qkh_lo + (size_t)(b * 16 + 8 + h) * 196 * 32;

#pragma unroll
    for (int t = 0; t < 2; t++) {
        int q = tid + (t << 8);
        int row = q >> 2, k8 = q & 3;
        uint32_t off = (uint32_t)(row * 128 + k8 * 16);
        uint32_t sw = off ^ ((off >> 3) & 0x70);
        int nr = n0 + row;
        int vq = nr < 196;
        size_t gq = vq ? ((size_t)nr * 32 + (k8 << 3)) : 0;
        cp_async16_zf(sb + sw,           Qhi + gq, vq);
        cp_async16_zf(sb + 16384u + sw,  Qlo + gq, vq);
        int mr = m0c + row;
        int vk = mr < 196;
        size_t gk = vk ? ((size_t)mr * 32 + (k8 << 3)) : 0;
        cp_async16_zf(sb + 32768u + sw,  Khi + gk, vk);
        cp_async16_zf(sb + 49152u + sw,  Klo + gk, vk);
    }
    asm volatile("cp.async.commit_group;" ::: "memory");
    asm volatile("cp.async.wait_group 0;" ::: "memory");
    __syncthreads();

    float acc[4][4][4];
#pragma unroll
    for (int i = 0; i < 4; i++)
#pragma unroll
        for (int j = 0; j < 4; j++)
#pragma unroll
            for (int c = 0; c < 4; c++) acc[i][j][c] = 0.f;

    const int lrow = lane & 15;
    const uint32_t lkoff = (uint32_t)((lane >> 4) << 4);

#pragma unroll
    for (int ks = 0; ks < 2; ks++) {
        uint32_t bh_[4][2], bl_[4][2];
#pragma unroll
        for (int p = 0; p < 2; p++) {
            uint32_t off = (uint32_t)((warp_n * 32 + p * 16 + lrow) * 128)
                         + (uint32_t)(ks * 32) + lkoff;
            uint32_t sw = off ^ ((off >> 3) & 0x70);
            uint32_t r0, r1, r2, r3;
            ldmat_x4(r0, r1, r2, r3, sb + 32768u + sw);
            bh_[p * 2 + 0][0] = r0; bh_[p * 2 + 1][0] = r1;
            bh_[p * 2 + 0][1] = r2; bh_[p * 2 + 1][1] = r3;
            ldmat_x4(r0, r1, r2, r3, sb + 49152u + sw);
            bl_[p * 2 + 0][0] = r0; bl_[p * 2 + 1][0] = r1;
            bl_[p * 2 + 0][1] = r2; bl_[p * 2 + 1][1] = r3;
        }
#pragma unroll
        for (int mt = 0; mt < 4; mt++) {
            uint32_t off = (uint32_t)((warp_m * 64 + mt * 16 + lrow) * 128)
                         + (uint32_t)(ks * 32) + lkoff;
            uint32_t sw = off ^ ((off >> 3) & 0x70);
            uint32_t a0, a1, a2, a3;
            ldmat_x4(a0, a1, a2, a3, sb + sw);
#pragma unroll
            for (int nt = 0; nt < 4; nt++)
                mma_bf16(acc[mt][nt][0], acc[mt][nt][1],
                         acc[mt][nt][2], acc[mt][nt][3],
                         a0, a1, a2, a3, bh_[nt][0], bh_[nt][1]);
#pragma unroll
            for (int nt = 0; nt < 4; nt++)
                mma_bf16(acc[mt][nt][0], acc[mt][nt][1],
                         acc[mt][nt][2], acc[mt][nt][3],
                         a0, a1, a2, a3, bl_[nt][0], bl_[nt][1]);
            ldmat_x4(a0, a1, a2, a3, sb + 16384u + sw);
#pragma unroll
            for (int nt = 0; nt < 4; nt++)
                mma_bf16(acc[mt][nt][0], acc[mt][nt][1],
                         acc[mt][nt][2], acc[mt][nt][3],
                         a0, a1, a2, a3, bh_[nt][0], bh_[nt][1]);
        }
    }

    const int group = lane >> 2, tig = lane & 3;
    const float* abh = ab + h * 196;
    float* lbase = g_logits + (size_t)bh * 196 * 196;
#pragma unroll
    for (int mt = 0; mt < 4; mt++) {
        int nr0 = n0 + warp_m * 64 + mt * 16 + group;
        int nr1 = nr0 + 8;
#pragma unroll
        for (int nt = 0; nt < 4; nt++) {
            int m = m0c + warp_n * 32 + nt * 8 + tig * 2;
            if (m < 196) {
                if (nr0 < 196) {
                    const int* br = bidx + (size_t)nr0 * 196;
                    lbase[(size_t)nr0 * 196 + m]     = acc[mt][nt][0] * SCALEF + abh[br[m]];
                    lbase[(size_t)nr0 * 196 + m + 1] = acc[mt][nt][1] * SCALEF + abh[br[m + 1]];
                }
                if (nr1 < 196) {
                    const int* br = bidx + (size_t)nr1 * 196;
                    lbase[(size_t)nr1 * 196 + m]     = acc[mt][nt][2] * SCALEF + abh[br[m]];
                    lbase[(size_t)nr1 * 196 + m + 1] = acc[mt][nt][3] * SCALEF + abh[br[m + 1]];
                }
            }
        }
    }
}

// ------------------------------------------------------------------
// AV batched mma v2: ONE block per bo covers all 196 n-cols (two n-tiles
// resident in registers); V chunks loaded once. K = 208 (chunks 64,64,64,16).
// smem/stage: Ahi 16K | Alo 16K | B0hi 16K | B0lo 16K | B1hi 16K | B1lo 16K = 96K.
#define AV_STAGE_BYTES 98304
#define AV_SMEM_BYTES  (2 * AV_STAGE_BYTES)

__global__ void __launch_bounds__(256) av_mma_kernel()
{
    extern __shared__ __align__(1024) char smem[];
    const uint32_t sb = s2u(smem);
    const int tid = threadIdx.x;
    const int wid = tid >> 5, lane = tid & 31;
    const int warp_m = wid & 1;
    const int warp_n = wid >> 1;
    const int bo = blockIdx.x;
    const int b  = bo >> 3, o = bo & 7;

    const __nv_bfloat16* Ahi = g_vhi + ((size_t)b * 1024 + o * 128) * KPAD;
    const __nv_bfloat16* Alo = g_vlo + ((size_t)b * 1024 + o * 128) * KPAD;
    const __nv_bfloat16* Bhi = g_phi + ((size_t)bo * 196) * KPAD;
    const __nv_bfloat16* Blo = g_plo + ((size_t)bo * 196) * KPAD;

    float acc0[4][4][4], acc1[4][4][4];
#pragma unroll
    for (int i = 0; i < 4; i++)
#pragma unroll
        for (int j = 0; j < 4; j++)
#pragma unroll
            for (int c = 0; c < 4; c++) { acc0[i][j][c] = 0.f; acc1[i][j][c] = 0.f; }

    const int lrow = lane & 15;
    const uint32_t lkoff = (uint32_t)((lane >> 4) << 4);

    auto issue = [&](int kb, uint32_t stage_off) {
#pragma unroll
        for (int i = 0; i < 4; i++) {
            int q = tid + (i << 8);
            int row = q >> 3, k8 = q & 7;
            uint32_t off = (uint32_t)(row * 128 + k8 * 16);
            uint32_t sw = off ^ ((off >> 3) & 0x70);
            size_t ga = (size_t)row * KPAD + kb + (k8 << 3);
            cp_async16(sb + stage_off + sw,          Ahi + ga);
            cp_async16(sb + stage_off + 16384u + sw, Alo + ga);
            // B tile 0: P rows 0..127 (all valid)
            size_t gb0 = (size_t)row * KPAD + kb + (k8 << 3);
            cp_async16(sb + stage_off + 32768u + sw, Bhi + gb0);
            cp_async16(sb + stage_off + 49152u + sw, Blo + gb0);
            // B tile 1: P rows 128..255 (valid < 196)
            int jr = 128 + row;
            int valid = jr < 196;
            size_t gb1 = valid ? ((size_t)jr * KPAD + kb + (k8 << 3)) : 0;
            cp_async16_zf(sb + stage_off + 65536u + sw, Bhi + gb1, valid);
            cp_async16_zf(sb + stage_off + 81920u + sw, Blo + gb1, valid);
        }
        asm volatile("cp.async.commit_group;" ::: "memory");
    };

    issue(0, 0u);
    issue(64, AV_STAGE_BYTES);

    for (int ch = 0; ch < 4; ch++) {
        if (ch + 1 < 4) asm volatile("cp.async.wait_group 1;" ::: "memory");
        else            asm volatile("cp.async.wait_group 0;" ::: "memory");
        __syncthreads();

        const uint32_t buf = (ch & 1) ? (uint32_t)AV_STAGE_BYTES : 0u;
        const int nks = (ch == 3) ? 1 : 4;
        for (int ks = 0; ks < nks; ks++) {
            uint32_t b0h[4][2], b0l[4][2], b1h[4][2], b1l[4][2];
#pragma unroll
            for (int p = 0; p < 2; p++) {
                uint32_t off = (uint32_t)((warp_n * 32 + p * 16 + lrow) * 128)
                             + (uint32_t)(ks * 32) + lkoff;
                uint32_t sw = off ^ ((off >> 3) & 0x70);
                uint32_t r0, r1, r2, r3;
                ldmat_x4(r0, r1, r2, r3, sb + buf + 32768u + sw);
                b0h[p * 2 + 0][0] = r0; b0h[p * 2 + 1][0] = r1;
                b0h[p * 2 + 0][1] = r2; b0h[p * 2 + 1][1] = r3;
                ldmat_x4(r0, r1, r2, r3, sb + buf + 49152u + sw);
                b0l[p * 2 + 0][0] = r0; b0l[p * 2 + 1][0] = r1;
                b0l[p * 2 + 0][1] = r2; b0l[p * 2 + 1][1] = r3;
                ldmat_x4(r0, r1, r2, r3, sb + buf + 65536u + sw);
                b1h[p * 2 + 0][0] = r0; b1h[p * 2 + 1][0] = r1;
                b1h[p * 2 + 0][1] = r2; b1h[p * 2 + 1][1] = r3;
                ldmat_x4(r0, r1, r2, r3, sb + buf + 81920u + sw);
                b1l[p * 2 + 0][0] = r0; b1l[p * 2 + 1][0] = r1;
                b1l[p * 2 + 0][1] = r2; b1l[p * 2 + 1][1] = r3;
            }
#pragma unroll
            for (int mt = 0; mt < 4; mt++) {
                uint32_t off = (uint32_t)((warp_m * 64 + mt * 16 + lrow) * 128)
                             + (uint32_t)(ks * 32) + lkoff;
                uint32_t sw = off ^ ((off >> 3) & 0x70);
                uint32_t a0, a1, a2, a3;
                ldmat_x4(a0, a1, a2, a3, sb + buf + sw);
#pragma unroll
                for (int nt = 0; nt < 4; nt++) {
                    mma_bf16(acc0[mt][nt][0], acc0[mt][nt][1],
                             acc0[mt][nt][2], acc0[mt][nt][3],
                             a0, a1, a2, a3, b0h[nt][0], b0h[nt][1]);
                    mma_bf16(acc0[mt][nt][0], acc0[mt][nt][1],
                             acc0[mt][nt][2], acc0[mt][nt][3],
                             a0, a1, a2, a3, b0l[nt][0], b0l[nt][1]);
                    mma_bf16(acc1[mt][nt][0], acc1[mt][nt][1],
                             acc1[mt][nt][2], acc1[mt][nt][3],
                             a0, a1, a2, a3, b1h[nt][0], b1h[nt][1]);
                    mma_bf16(acc1[mt][nt][0], acc1[mt][nt][1],
                             acc1[mt][nt][2], acc1[mt][nt][3],
                             a0, a1, a2, a3, b1l[nt][0], b1l[nt][1]);
                }
                ldmat_x4(a0, a1, a2, a3, sb + buf + 16384u + sw);
#pragma unroll
                for (int nt = 0; nt < 4; nt++) {
                    mma_bf16(acc0[mt][nt][0], acc0[mt][nt][1],
                             acc0[mt][nt][2], acc0[mt][nt][3],
                             a0, a1, a2, a3, b0h[nt][0], b0h[nt][1]);
                    mma_bf16(acc1[mt][nt][0], acc1[mt][nt][1],
                             acc1[mt][nt][2], acc1[mt][nt][3],
                             a0, a1, a2, a3, b1h[nt][0], b1h[nt][1]);
                }
            }
        }

        if (ch + 2 < 4) {
            __syncthreads();
            issue((ch + 2) << 6, buf);
        }
    }

    // fused epilogue: relu(acc + v_local) -> bf16 hi/lo into g_pt (both tiles)
    const int group = lane >> 2, tig = lane & 3;
    const float* vlbase = g_vloc + ((size_t)b * 1024 + o * 128) * NPIX;
#pragma unroll
    for (int mt = 0; mt < 4; mt++) {
        int e0 = warp_m * 64 + mt * 16 + group;
        int e1 = e0 + 8;
#pragma unroll
        for (int nt = 0; nt < 4; nt++) {
            int jb = warp_n * 32 + nt * 8 + tig * 2;
#pragma unroll
            for (int tile = 0; tile < 2; tile++) {
                int j = jb + tile * 128;
                if (j < 196) {
                    float a0v = tile ? acc1[mt][nt][0] : acc0[mt][nt][0];
                    float a1v = tile ? acc1[mt][nt][1] : acc0[mt][nt][1];
                    float a2v = tile ? acc1[mt][nt][2] : acc0[mt][nt][2];
                    float a3v = tile ? acc1[mt][nt][3] : acc0[mt][nt][3];
                    float v00 = fmaxf(a0v + vlbase[(size_t)e0 * NPIX + j],     0.f);
                    float v01 = fmaxf(a1v + vlbase[(size_t)e0 * NPIX + j + 1], 0.f);
                    float v10 = fmaxf(a2v + vlbase[(size_t)e1 * NPIX + j],     0.f);
                    float v11 = fmaxf(a3v + vlbase[(size_t)e1 * NPIX + j + 1], 0.f);
                    size_t r00 = ((size_t)(b * 196 + j))     * 1024 + o * 128 + e0;
                    size_t r01 = ((size_t)(b * 196 + j + 1)) * 1024 + o * 128 + e0;
                    __nv_bfloat16 h;
                    h = __float2bfloat16(v00); g_pt_hi[r00] = h;
                    g_pt_lo[r00] = __float2bfloat16(v00 - __bfloat162float(h));
                    h = __float2bfloat16(v01); g_pt_hi[r01] = h;
                    g_pt_lo[r01] = __float2bfloat16(v01 - __bfloat162float(h));
                    h = __float2bfloat16(v10); g_pt_hi[r00 + 8] = h;
                    g_pt_lo[r00 + 8] = __float2bfloat16(v10 - __bfloat162float(h));
                    h = __float2bfloat16(v11); g_pt_hi[r01 + 8] = h;
                    g_pt_lo[r01 + 8] = __float2bfloat16(v11 - __bfloat162float(h));
                }
            }
        }
    }
}

// ------------------------------------------------------------------
// Depthwise 3x3 conv v4: vectorized uint2 (4x bf16) loads of the V export.
__global__ void __launch_bounds__(256) dwconv_kernel(
    const float* __restrict__ wvl, const float* __restrict__ bvl,
    const float* __restrict__ bn)
{
    int c0 = blockIdx.x * 8, b = blockIdx.y;
    __shared__ float p[8 * 256];     // 8 channels x 16x16 zero-halo plane
    __shared__ float wsh[72];
    __shared__ float cs[8], ct[8];
    int tid = threadIdx.x;
    const __nv_bfloat16* vhi = g_vhi + ((size_t)b * 1024 + c0) * KPAD;
    const __nv_bfloat16* vlo = g_vlo + ((size_t)b * 1024 + c0) * KPAD;

    for (int i = tid; i < 2048; i += 256) p[i] = 0.f;
    if (tid < 72) wsh[tid] = wvl[c0 * 9 + tid];
    if (tid < 8) {
        int c = c0 + tid;
        float s = bn[c] * rsqrtf(bn[3072 + c] + EPSF);
        cs[tid] = s;
        ct[tid] = (bvl[c] - bn[2048 + c]) * s + bn[1024 + c];
    }
    __syncthreads();

    // fill interior: 392 uint2 chunks (8 ch x 49 x 4 pix)
    for (int i = tid; i < 392; i += 256) {
        int c = i / 49, q = i - c * 49;
        int pix = q * 4;
        uint2 vh = *(const uint2*)(vhi + (size_t)c * KPAD + pix);
        uint2 vl = *(const uint2*)(vlo + (size_t)c * KPAD + pix);
        const __nv_bfloat162* hp = (const __nv_bfloat162*)&vh;
        const __nv_bfloat162* lp = (const __nv_bfloat162*)&vl;
        float2 h0 = __bfloat1622float2(hp[0]), h1 = __bfloat1622float2(hp[1]);
        float2 l0 = __bfloat1622float2(lp[0]), l1 = __bfloat1622float2(lp[1]);
        float vals[4] = { h0.x + l0.x, h0.y + l0.y, h1.x + l1.x, h1.y + l1.y };
        int y = pix / 14, x = pix - y * 14;
#pragma unroll
        for (int e = 0; e < 4; e++) {
            p[c * 256 + (y + 1) * 16 + (x + 1)] = vals[e];
            if (++x == 14) { x = 0; ++y; }
        }
    }
    __syncthreads();

    int w = tid >> 5, lane = tid & 31;
    if (lane < 28) {
        const float* pc = p + w * 256;
        float w00 = wsh[w * 9 + 0], w01 = wsh[w * 9 + 1], w02 = wsh[w * 9 + 2];
        float w10 = wsh[w * 9 + 3], w11 = wsh[w * 9 + 4], w12 = wsh[w * 9 + 5];
        float w20 = wsh[w * 9 + 6], w21 = wsh[w * 9 + 7], w22 = wsh[w * 9 + 8];
        float s = cs[w], t = ct[w];
        float* dst = g_vloc + (size_t)b * (DHC * NPIX) + (size_t)(c0 + w) * NPIX;
        int xr = lane >= 14;
        int x = lane - xr * 14;
#pragma unroll
        for (int it = 0; it < 7; it++) {
            int y = it * 2 + xr;
            const float* q = pc + y * 16 + x;
            float acc = w00 * q[0]  + w01 * q[1]  + w02 * q[2]
                      + w10 * q[16] + w11 * q[17] + w12 * q[18]
                      + w20 * q[32] + w21 * q[33] + w22 * q[34];
            dst[y * 14 + x] = acc * s + t;
        }
    }
}

// ------------------------------------------------------------------
// Attention core v5: TH1 (reads g_logits) + softmax + fused TH2+P-export.
#define ATTN_SMEM_FLOATS (21952 + 144)

__global__ void __launch_bounds__(256, 2) attn_kernel(
    const float* __restrict__ th1w, const float* __restrict__ th1b,
    const float* __restrict__ th2w, const float* __restrict__ th2b)
{
    extern __shared__ float sm[];
    float* L  = sm;
    float* th = sm + 21952;

    int tid = threadIdx.x;
    int b = blockIdx.y;
    int n0 = blockIdx.x * 14;

    if (tid < 64)       th[tid] = th1w[tid];
    else if (tid < 72)  th[tid] = th1b[tid - 64];
    else if (tid < 136) th[tid] = th2w[tid - 72];
    else if (tid < 144) th[tid] = th2b[tid - 136];
    __syncthreads();

    const float* lgbase = g_logits + (size_t)(b * 8) * 196 * 196;
    for (int idx = tid; idx < 2744; idx += 256) {
        int n_ = idx / 196, m = idx - n_ * 196;
        size_t rowoff = (size_t)(n0 + n_) * 196 + m;
        float v[8], o_[8];
#pragma unroll
        for (int hh = 0; hh < 8; hh++)
            v[hh] = lgbase[(size_t)hh * 196 * 196 + rowoff];
#pragma unroll
        for (int oo = 0; oo < 8; oo++) {
            float s = th[64 + oo];
#pragma unroll
            for (int hh = 0; hh < 8; hh++) s = fmaf(th[oo * 8 + hh], v[hh], s);
            o_[oo] = s;
        }
#pragma unroll
        for (int oo = 0; oo < 8; oo++) L[(oo * 14 + n_) * 196 + m] = o_[oo];
    }
    __syncthreads();

    {
        int w = tid >> 5, lane = tid & 31;
        for (int r = 0; r < 14; r++) {
            float* row = L + (w * 14 + r) * 196;
            float mx = -1e30f;
            for (int m = lane; m < 196; m += 32) mx = fmaxf(mx, row[m]);
#pragma unroll
            for (int off = 16; off > 0; off >>= 1)
                mx = fmaxf(mx, __shfl_xor_sync(0xffffffffu, mx, off));
            float sum = 0.f;
            for (int m = lane; m < 196; m += 32) {
                float e = __expf(row[m] - mx);
                row[m] = e; sum += e;
            }
#pragma unroll
            for (int off = 16; off > 0; off >>= 1)
                sum += __shfl_xor_sync(0xffffffffu, sum, off);
            float inv = 1.f / sum;
            for (int m = lane; m < 196; m += 32) row[m] *= inv;
        }
    }
    __syncthreads();

    for (int idx = tid; idx < 2744; idx += 256) {
        int n_ = idx / 196, m = idx - n_ * 196;
        float v[8];
#pragma unroll
        for (int hh = 0; hh < 8; hh++) v[hh] = L[(hh * 14 + n_) * 196 + m];
        size_t rbase = (size_t)(b * 8) * 196 + n0 + n_;
#pragma unroll
        for (int oo = 0; oo < 8; oo++) {
            float s = th[136 + oo];
#pragma unroll
            for (int hh = 0; hh < 8; hh++) s = fmaf(th[72 + oo * 8 + hh], v[hh], s);
            __nv_bfloat16 hh2 = __float2bfloat16(s);
            size_t row = rbase + (size_t)oo * 196;
            g_phi[row * KPAD + m] = hh2;
            g_plo[row * KPAD + m] = __float2bfloat16(s - __bfloat162float(hh2));
        }
    }
}

// ------------------------------------------------------------------
extern "C" void kernel_launch(void* const* d_in, const int* in_sizes, int n_in,
                              void* d_out, int out_size)
{
    const float* x    = (const float*)d_in[0];
    const float* wq   = (const float*)d_in[1];
    const float* bq   = (const float*)d_in[2];
    const float* bnq  = (const float*)d_in[3];
    const float* wk   = (const float*)d_in[4];
    const float* bk   = (const float*)d_in[5];
    const float* bnk  = (const float*)d_in[6];
    const float* wv   = (const float*)d_in[7];
    const float* bv   = (const float*)d_in[8];
    const float* bnv  = (const float*)d_in[9];
    const float* wvl  = (const float*)d_in[10];
    const float* bvl  = (const float*)d_in[11];
    const float* bnvl = (const float*)d_in[12];
    const float* th1w = (const float*)d_in[13];
    const float* th1b = (const float*)d_in[14];
    const float* th2w = (const float*)d_in[15];
    const float* th2b = (const float*)d_in[16];
    const float* wp   = (const float*)d_in[17];
    const float* bp   = (const float*)d_in[18];
    const float* bnp  = (const float*)d_in[19];
    const float* ab   = (const float*)d_in[20];
    const int*   bidx = (const int*)d_in[21];
    float* out = (float*)d_out;

    const int attn_smem = ATTN_SMEM_FLOATS * (int)sizeof(float);
    cudaFuncSetAttribute(attn_kernel,
                         cudaFuncAttributeMaxDynamicSharedMemorySize, attn_smem);
    cudaFuncSetAttribute(gemm_mma_kernel,
                         cudaFuncAttributeMaxDynamicSharedMemorySize, GEMM_SMEM_BYTES);
    cudaFuncSetAttribute(av_mma_kernel,
                         cudaFuncAttributeMaxDynamicSharedMemorySize, AV_SMEM_BYTES);
    cudaFuncSetAttribute(qk_mma_kernel,
                         cudaFuncAttributeMaxDynamicSharedMemorySize, QK_SMEM_BYTES);

    __nv_bfloat16 *wqkv_hi, *wqkv_lo, *xt_hi, *xt_lo, *wp_hi, *wp_lo, *pt_hi, *pt_lo;
    __nv_bfloat16 *qkh_hi, *qkh_lo;
    float *sv, *tv;
    cudaGetSymbolAddress((void**)&wqkv_hi, g_wqkv_hi);
    cudaGetSymbolAddress((void**)&wqkv_lo, g_wqkv_lo);
    cudaGetSymbolAddress((void**)&xt_hi, g_xt_hi);
    cudaGetSymbolAddress((void**)&xt_lo, g_xt_lo);
    cudaGetSymbolAddress((void**)&wp_hi, g_wp_hi);
    cudaGetSymbolAddress((void**)&wp_lo, g_wp_lo);
    cudaGetSymbolAddress((void**)&pt_hi, g_pt_hi);
    cudaGetSymbolAddress((void**)&pt_lo, g_pt_lo);
    cudaGetSymbolAddress((void**)&qkh_hi, g_qkh_hi);
    cudaGetSymbolAddress((void**)&qkh_lo, g_qkh_lo);
    cudaGetSymbolAddress((void**)&sv, g_s);
    cudaGetSymbolAddress((void**)&tv, g_t);

    // 1. fold BN + split weights + zero k-pads
    prep_kernel<<<2304, 256>>>(wq, wk, wv, wp, bq, bk, bv, bp, bnq, bnk, bnv, bnp);
    // 2. transpose+split x
    xt_cvt_kernel<<<dim3(7, 12, 64), 256>>>(x);
    // 3. fused qkv GEMM: exports q/k (g_qkh) and V (g_vhi/g_vlo)
    gemm_mma_kernel<<<dim3(98, 12), 256, GEMM_SMEM_BYTES>>>(
        wqkv_hi, wqkv_lo, xt_hi, xt_lo, 384, sv, tv, nullptr, 1536, qkh_hi, qkh_lo);
    // 4. depthwise conv + BN (vectorized bf16 V reads)
    dwconv_kernel<<<dim3(128, 64), 256>>>(wvl, bvl, bnvl);
    // 5. QK logits on tensor cores (+ scale + positional bias)
    qk_mma_kernel<<<dim3(2, 2, 512), 256, QK_SMEM_BYTES>>>(ab, bidx);
    // 6. attention core (TH1, softmax, fused TH2+P export)
    attn_kernel<<<dim3(14, 64), 256, attn_smem>>>(th1w, th1b, th2w, th2b);
    // 7. AV on tensor cores, single V pass (+ fused relu(att+v_local) epilogue)
    av_mma_kernel<<<512, 256, AV_SMEM_BYTES>>>();
    // 8. projection GEMM (M=384, K=1024)
    gemm_mma_kernel<<<dim3(98, 3), 256, GEMM_SMEM_BYTES>>>(
        wp_hi, wp_lo, pt_hi, pt_lo, 1024, sv + 1536, tv + 1536, out, 384,
        nullptr, nullptr);
}

// round 12
// speedup vs baseline: 3.6885x; 1.0266x over previous
#include <cuda_runtime.h>
#include <cuda_bf16.h>
#include <math.h>
#include <stdint.h>

#define EPSF 1e-5f
#define SCALEF 0.17677669529663687f

#define NB   64
#define NPIX 196
#define DHC  1024
#define NCOL 12544   // 64*196
#define KPAD 208     // padded k (m) dimension for AV mma (13*16)

// ------------------------------------------------------------------
// scratch (no cudaMalloc allowed)
__device__ float g_vloc[NB * DHC * NPIX];    // [b][1024][196]
__device__ float g_logits[512 * 196 * 196];  // [(b*8+h)][n][m] post-bias logits

__device__ __align__(16) __nv_bfloat16 g_xt_hi[NCOL * 384];   // [j][k]
__device__ __align__(16) __nv_bfloat16 g_xt_lo[NCOL * 384];
__device__ __align__(16) __nv_bfloat16 g_pt_hi[NCOL * 1024];  // [j][k]
__device__ __align__(16) __nv_bfloat16 g_pt_lo[NCOL * 1024];
__device__ __align__(16) __nv_bfloat16 g_wqkv_hi[1536 * 384]; // [m][k]
__device__ __align__(16) __nv_bfloat16 g_wqkv_lo[1536 * 384];
__device__ __align__(16) __nv_bfloat16 g_wp_hi[384 * 1024];
__device__ __align__(16) __nv_bfloat16 g_wp_lo[384 * 1024];
// q/k export: [(b*16 + hh)][n][d=32] bf16 hi/lo; hh 0-7 = q heads, 8-15 = k heads
__device__ __align__(16) __nv_bfloat16 g_qkh_hi[NB * 16 * 196 * 32];
__device__ __align__(16) __nv_bfloat16 g_qkh_lo[NB * 16 * 196 * 32];
// attention P (post-softmax/TH2) bf16 hi/lo: [(b*8+o)*196 + n][k=KPAD] (+ tail pad)
__device__ __align__(16) __nv_bfloat16 g_phi[512 * 196 * KPAD + 128];
__device__ __align__(16) __nv_bfloat16 g_plo[512 * 196 * KPAD + 128];
// BN'd V bf16 hi/lo: [b][c(1024)][k=KPAD] (written by qkv GEMM epilogue)
__device__ __align__(16) __nv_bfloat16 g_vhi[NB * 1024 * KPAD + 128];
__device__ __align__(16) __nv_bfloat16 g_vlo[NB * 1024 * KPAD + 128];
__device__ float g_s[1920];   // folded BN scale: [0:1536) qkv, [1536:1920) proj
__device__ float g_t[1920];   // folded BN shift

// ------------------------------------------------------------------
static __device__ __forceinline__ uint32_t s2u(const void* p) {
    uint32_t a;
    asm("{ .reg .u64 t; cvta.to.shared.u64 t, %1; cvt.u32.u64 %0, t; }"
        : "=r"(a) : "l"(p));
    return a;
}

static __device__ __forceinline__ void cp_async16(uint32_t saddr, const void* gptr) {
    asm volatile("cp.async.cg.shared.global [%0], [%1], 16;"
                 :: "r"(saddr), "l"(gptr) : "memory");
}

static __device__ __forceinline__ void cp_async16_zf(uint32_t saddr, const void* gptr, int valid) {
    int sz = valid ? 16 : 0;
    asm volatile("cp.async.cg.shared.global [%0], [%1], 16, %2;"
                 :: "r"(saddr), "l"(gptr), "r"(sz) : "memory");
}

static __device__ __forceinline__ void ldmat_x4(
    uint32_t& r0, uint32_t& r1, uint32_t& r2, uint32_t& r3, uint32_t addr)
{
    asm volatile("ldmatrix.sync.aligned.m8n8.x4.shared.b16 {%0,%1,%2,%3}, [%4];"
                 : "=r"(r0), "=r"(r1), "=r"(r2), "=r"(r3) : "r"(addr));
}

static __device__ __forceinline__ void mma_bf16(
    float& d0, float& d1, float& d2, float& d3,
    uint32_t a0, uint32_t a1, uint32_t a2, uint32_t a3,
    uint32_t b0, uint32_t b1)
{
    asm volatile(
        "mma.sync.aligned.m16n8k16.row.col.f32.bf16.bf16.f32 "
        "{%0,%1,%2,%3}, {%4,%5,%6,%7}, {%8,%9}, {%0,%1,%2,%3};"
        : "+f"(d0), "+f"(d1), "+f"(d2), "+f"(d3)
        : "r"(a0), "r"(a1), "r"(a2), "r"(a3), "r"(b0), "r"(b1));
}

// ------------------------------------------------------------------
// Prep: fold BN; split weights into bf16 hi/lo; zero k-pads (3 u64/row).
__global__ void __launch_bounds__(256) prep_kernel(
    const float* __restrict__ wq, const float* __restrict__ wk,
    const float* __restrict__ wv, const float* __restrict__ wp,
    const float* __restrict__ bq, const float* __restrict__ bk,
    const float* __restrict__ bv, const float* __restrict__ bp,
    const float* __restrict__ bnq, const float* __restrict__ bnk,
    const float* __restrict__ bnv, const float* __restrict__ bnp)
{
    int idx = blockIdx.x * 256 + threadIdx.x;
    int stride = gridDim.x * 256;

    for (int i = idx; i < 1536 * 384; i += stride) {
        int m = i / 384;
        float w = (m < 256) ? wq[i]
                : (m < 512) ? wk[i - 256 * 384]
                            : wv[i - 512 * 384];
        __nv_bfloat16 h = __float2bfloat16(w);
        g_wqkv_hi[i] = h;
        g_wqkv_lo[i] = __float2bfloat16(w - __bfloat162float(h));
    }
    for (int i = idx; i < 384 * 1024; i += stride) {
        float w = wp[i];
        __nv_bfloat16 h = __float2bfloat16(w);
        g_wp_hi[i] = h;
        g_wp_lo[i] = __float2bfloat16(w - __bfloat162float(h));
    }
    // zero P k-pad: rows 512*196, row stride 416B, pad = 24B at offset 392 (3 u64)
    for (long i = idx; i < (long)100352 * 3; i += stride) {
        long r = i / 3; int k = (int)(i % 3);
        *(unsigned long long*)((char*)g_phi + r * 416 + 392 + k * 8) = 0ull;
        *(unsigned long long*)((char*)g_plo + r * 416 + 392 + k * 8) = 0ull;
    }
    // zero V k-pad: rows 64*1024
    for (long i = idx; i < (long)65536 * 3; i += stride) {
        long r = i / 3; int k = (int)(i % 3);
        *(unsigned long long*)((char*)g_vhi + r * 416 + 392 + k * 8) = 0ull;
        *(unsigned long long*)((char*)g_vlo + r * 416 + 392 + k * 8) = 0ull;
    }
    // zero tail pads
    if (idx < 128) {
        g_phi[512 * 196 * KPAD + idx] = __float2bfloat16(0.f);
        g_plo[512 * 196 * KPAD + idx] = __float2bfloat16(0.f);
        g_vhi[NB * 1024 * KPAD + idx] = __float2bfloat16(0.f);
        g_vlo[NB * 1024 * KPAD + idx] = __float2bfloat16(0.f);
    }
    if (idx < 1920) {
        const float* bn; const float* bias; int c; int C;
        if (idx < 256)       { bn = bnq; bias = bq; c = idx;        C = 256; }
        else if (idx < 512)  { bn = bnk; bias = bk; c = idx - 256;  C = 256; }
        else if (idx < 1536) { bn = bnv; bias = bv; c = idx - 512;  C = 1024; }
        else                 { bn = bnp; bias = bp; c = idx - 1536; C = 384; }
        float s = bn[c] * rsqrtf(bn[3 * C + c] + EPSF);
        g_s[idx] = s;
        g_t[idx] = (bias[c] - bn[2 * C + c]) * s + bn[C + c];
    }
}

// ------------------------------------------------------------------
// Transpose+split x: [b][384][196] -> Xt[j=b*196+n][k=c] bf16 hi/lo
__global__ void __launch_bounds__(256) xt_cvt_kernel(const float* __restrict__ X)
{
    __shared__ float t[32][29];
    int b = blockIdx.z, c0 = blockIdx.y * 32, n0 = blockIdx.x * 28;
    int tid = threadIdx.x;
    const float* src = X + ((size_t)b * 384 + c0) * 196 + n0;
    for (int i = tid; i < 32 * 28; i += 256) {
        int ci = i / 28, nj = i - ci * 28;
        t[ci][nj] = src[(size_t)ci * 196 + nj];
    }
    __syncthreads();
    for (int i = tid; i < 32 * 28; i += 256) {
        int nj = i >> 5, ci = i & 31;
        float v = t[ci][nj];
        __nv_bfloat16 h = __float2bfloat16(v);
        size_t o = ((size_t)(b * 196 + n0 + nj)) * 384 + c0 + ci;
        g_xt_hi[o] = h;
        g_xt_lo[o] = __float2bfloat16(v - __bfloat162float(h));
    }
}

// ------------------------------------------------------------------
// bf16 mma.sync GEMM, 3-term compensation fused per K-chunk (epilogue modes as R10).
#define GEMM_STAGE_BYTES 65536
#define GEMM_SMEM_BYTES  (2 * GEMM_STAGE_BYTES)

__global__ void __launch_bounds__(256) gemm_mma_kernel(
    const __nv_bfloat16* __restrict__ Ahi, const __nv_bfloat16* __restrict__ Alo,
    const __nv_bfloat16* __restrict__ Bhi, const __nv_bfloat16* __restrict__ Blo,
    int K, const float* __restrict__ svec, const float* __restrict__ tvec,
    float* __restrict__ out, int Cout,
    __nv_bfloat16* __restrict__ qk_hi, __nv_bfloat16* __restrict__ qk_lo)
{
    extern __shared__ __align__(1024) char smem[];
    const uint32_t sb = s2u(smem);
    const int tid = threadIdx.x;
    const int wid = tid >> 5, lane = tid & 31;
    const int warp_m = wid & 1;
    const int warp_n = wid >> 1;
    const int m0 = blockIdx.y * 128;
    const int j0 = blockIdx.x * 128;
    const int nk = K >> 6;
    const bool is_qkv = (qk_hi != nullptr);

    float acc[4][4][4];
#pragma unroll
    for (int i = 0; i < 4; i++)
#pragma unroll
        for (int j = 0; j < 4; j++)
#pragma unroll
            for (int c = 0; c < 4; c++) acc[i][j][c] = 0.f;

    const int lrow = lane & 15;
    const uint32_t lkoff = (uint32_t)((lane >> 4) << 4);

    auto issue = [&](int kb, uint32_t stage_off) {
#pragma unroll
        for (int i = 0; i < 4; i++) {
            int q = tid + (i << 8);
            int row = q >> 3, k8 = q & 7;
            uint32_t off = (uint32_t)(row * 128 + k8 * 16);
            uint32_t sw = off ^ ((off >> 3) & 0x70);
            size_t ga = (size_t)(m0 + row) * K + kb + (k8 << 3);
            size_t gb = (size_t)(j0 + row) * K + kb + (k8 << 3);
            cp_async16(sb + stage_off + sw,           Ahi + ga);
            cp_async16(sb + stage_off + 16384u + sw,  Alo + ga);
            cp_async16(sb + stage_off + 32768u + sw,  Bhi + gb);
            cp_async16(sb + stage_off + 49152u + sw,  Blo + gb);
        }
        asm volatile("cp.async.commit_group;" ::: "memory");
    };

    issue(0, 0u);
    if (nk > 1) issue(64, GEMM_STAGE_BYTES);

    for (int ch = 0; ch < nk; ch++) {
        if (ch + 1 < nk) asm volatile("cp.async.wait_group 1;" ::: "memory");
        else             asm volatile("cp.async.wait_group 0;" ::: "memory");
        __syncthreads();

        const uint32_t buf = (ch & 1) ? (uint32_t)GEMM_STAGE_BYTES : 0u;
#pragma unroll
        for (int ks = 0; ks < 4; ks++) {
            uint32_t bh[4][2], bl[4][2];
#pragma unroll
            for (int p = 0; p < 2; p++) {
                uint32_t off = (uint32_t)((warp_n * 32 + p * 16 + lrow) * 128)
                             + (uint32_t)(ks * 32) + lkoff;
                uint32_t sw = off ^ ((off >> 3) & 0x70);
                uint32_t r0, r1, r2, r3;
                ldmat_x4(r0, r1, r2, r3, sb + buf + 32768u + sw);
                bh[p * 2 + 0][0] = r0; bh[p * 2 + 1][0] = r1;
                bh[p * 2 + 0][1] = r2; bh[p * 2 + 1][1] = r3;
                ldmat_x4(r0, r1, r2, r3, sb + buf + 49152u + sw);
                bl[p * 2 + 0][0] = r0; bl[p * 2 + 1][0] = r1;
                bl[p * 2 + 0][1] = r2; bl[p * 2 + 1][1] = r3;
            }
#pragma unroll
            for (int mt = 0; mt < 4; mt++) {
                uint32_t off = (uint32_t)((warp_m * 64 + mt * 16 + lrow) * 128)
                             + (uint32_t)(ks * 32) + lkoff;
                uint32_t sw = off ^ ((off >> 3) & 0x70);
                uint32_t a0, a1, a2, a3;
                ldmat_x4(a0, a1, a2, a3, sb + buf + sw);
#pragma unroll
                for (int nt = 0; nt < 4; nt++)
                    mma_bf16(acc[mt][nt][0], acc[mt][nt][1],
                             acc[mt][nt][2], acc[mt][nt][3],
                             a0, a1, a2, a3, bh[nt][0], bh[nt][1]);
#pragma unroll
                for (int nt = 0; nt < 4; nt++)
                    mma_bf16(acc[mt][nt][0], acc[mt][nt][1],
                             acc[mt][nt][2], acc[mt][nt][3],
                             a0, a1, a2, a3, bl[nt][0], bl[nt][1]);
                ldmat_x4(a0, a1, a2, a3, sb + buf + 16384u + sw);
#pragma unroll
                for (int nt = 0; nt < 4; nt++)
                    mma_bf16(acc[mt][nt][0], acc[mt][nt][1],
                             acc[mt][nt][2], acc[mt][nt][3],
                             a0, a1, a2, a3, bh[nt][0], bh[nt][1]);
            }
        }

        if (ch + 2 < nk) {
            __syncthreads();
            issue((ch + 2) << 6, buf);
        }
    }

    const int group = lane >> 2, tig = lane & 3;
#pragma unroll
    for (int mt = 0; mt < 4; mt++) {
        int oc0 = m0 + warp_m * 64 + mt * 16 + group;
        int oc1 = oc0 + 8;
        float s0 = svec[oc0], t0 = tvec[oc0];
        float s1 = svec[oc1], t1 = tvec[oc1];
#pragma unroll
        for (int nt = 0; nt < 4; nt++) {
            int j = j0 + warp_n * 32 + nt * 8 + tig * 2;
            int b = j / 196, n = j - b * 196;
            float v00 = acc[mt][nt][0] * s0 + t0;
            float v01 = acc[mt][nt][1] * s0 + t0;
            float v10 = acc[mt][nt][2] * s1 + t1;
            float v11 = acc[mt][nt][3] * s1 + t1;
            if (!is_qkv) {
                float* p0 = out + ((size_t)b * Cout + oc0) * 196 + n;
                float* p1 = out + ((size_t)b * Cout + oc1) * 196 + n;
                p0[0] = v00; p0[1] = v01;
                p1[0] = v10; p1[1] = v11;
            } else if (m0 < 512) {
                size_t r0 = (((size_t)(b * 16) + (oc0 >> 5)) * 196 + n) * 32 + (oc0 & 31);
                size_t r1 = (((size_t)(b * 16) + (oc1 >> 5)) * 196 + n) * 32 + (oc1 & 31);
                __nv_bfloat16 h;
                h = __float2bfloat16(v00); qk_hi[r0] = h;
                qk_lo[r0] = __float2bfloat16(v00 - __bfloat162float(h));
                h = __float2bfloat16(v01); qk_hi[r0 + 32] = h;
                qk_lo[r0 + 32] = __float2bfloat16(v01 - __bfloat162float(h));
                h = __float2bfloat16(v10); qk_hi[r1] = h;
                qk_lo[r1] = __float2bfloat16(v10 - __bfloat162float(h));
                h = __float2bfloat16(v11); qk_hi[r1 + 32] = h;
                qk_lo[r1 + 32] = __float2bfloat16(v11 - __bfloat162float(h));
            } else {
                size_t r0 = ((size_t)b * 1024 + (oc0 - 512)) * KPAD + n;
                size_t r1 = ((size_t)b * 1024 + (oc1 - 512)) * KPAD + n;
                __nv_bfloat16 h;
                h = __float2bfloat16(v00); g_vhi[r0] = h;
                g_vlo[r0] = __float2bfloat16(v00 - __bfloat162float(h));
                h = __float2bfloat16(v01); g_vhi[r0 + 1] = h;
                g_vlo[r0 + 1] = __float2bfloat16(v01 - __bfloat162float(h));
                h = __float2bfloat16(v10); g_vhi[r1] = h;
                g_vlo[r1] = __float2bfloat16(v10 - __bfloat162float(h));
                h = __float2bfloat16(v11); g_vhi[r1 + 1] = h;
                g_vlo[r1 + 1] = __float2bfloat16(v11 - __bfloat162float(h));
            }
        }
    }
}

// ------------------------------------------------------------------
// QK logits mma (unchanged).
#define QK_SMEM_BYTES 65536

__global__ void __launch_bounds__(256) qk_mma_kernel(
    const float* __restrict__ ab, const int* __restrict__ bidx)
{
    extern __shared__ __align__(1024) char smem[];
    const uint32_t sb = s2u(smem);
    const int tid = threadIdx.x;
    const int wid = tid >> 5, lane = tid & 31;
    const int warp_m = wid & 1;
    const int warp_n = wid >> 1;
    const int bh = blockIdx.z;
    const int b = bh >> 3, h = bh & 7;
    const int n0 = blockIdx.x * 128;
    const int m0c = blockIdx.y * 128;

    const __nv_bfloat16* Qhi = g_qkh_hi + (size_t)(b * 16 + h) * 196 * 32;
    const __nv_bfloat16* Qlo = g_qkh_lo + (size_t)(b * 16 + h) * 196 * 32;
    const __nv_bfloat16* Khi = g_qkh_hi + (size_t)(b * 16 + 8 + h) * 196 * 32;
    const __nv_bfloat16* Klo = g_qkh_lo + (size_t)(b * 16 + 8 + h) * 196 * 32;

#pragma unroll
    for (int t = 0; t < 2; t++) {
        int q = tid + (t << 8);
        int row = q >> 2, k8 = q & 3;
        uint32_t off = (uint32_t)(row * 128 + k8 * 16);
        uint32_t sw = off ^ ((off >> 3) & 0x70);
        int nr = n0 + row;
        int vq = nr < 196;
        size_t gq = vq ? ((size_t)nr * 32 + (k8 << 3)) : 0;
        cp_async16_zf(sb + sw,           Qhi + gq, vq);
        cp_async16_zf(sb + 16384u + sw,  Qlo + gq, vq);
        int mr = m0c + row;
        int vk = mr < 196;
        size_t gk = vk ? ((size_t)mr * 32 + (k8 << 3)) : 0;
        cp_async16_zf(sb + 32768u + sw,  Khi + gk, vk);
        cp_async16_zf(sb + 49152u + sw,  Klo + gk, vk);
    }
    asm volatile("cp.async.commit_group;" ::: "memory");
    asm volatile("cp.async.wait_group 0;" ::: "memory");
    __syncthreads();

    float acc[4][4][4];
#pragma unroll
    for (int i = 0; i < 4; i++)
#pragma unroll
        for (int j = 0; j < 4; j++)
#pragma unroll
            for (int c = 0; c < 4; c++) acc[i][j][c] = 0.f;

    const int lrow = lane & 15;
    const uint32_t lkoff = (uint32_t)((lane >> 4) << 4);

#pragma unroll
    for (int ks = 0; ks < 2; ks++) {
        uint32_t bh_[4][2], bl_[4][2];
#pragma unroll
        for (int p = 0; p < 2; p++) {
            uint32_t off = (uint32_t)((warp_n * 32 + p * 16 + lrow) * 128)
                         + (uint32_t)(ks * 32) + lkoff;
            uint32_t sw = off ^ ((off >> 3) & 0x70);
            uint32_t r0, r1, r2, r3;
            ldmat_x4(r0, r1, r2, r3, sb + 32768u + sw);
            bh_[p * 2 + 0][0] = r0; bh_[p * 2 + 1][0] = r1;
            bh_[p * 2 + 0][1] = r2; bh_[p * 2 + 1][1] = r3;
            ldmat_x4(r0, r1, r2, r3, sb + 49152u + sw);
            bl_[p * 2 + 0][0] = r0; bl_[p * 2 + 1][0] = r1;
            bl_[p * 2 + 0][1] = r2; bl_[p * 2 + 1][1] = r3;
        }
#pragma unroll
        for (int mt = 0; mt < 4; mt++) {
            uint32_t off = (uint32_t)((warp_m * 64 + mt * 16 + lrow) * 128)
                         + (uint32_t)(ks * 32) + lkoff;
            uint32_t sw = off ^ ((off >> 3) & 0x70);
            uint32_t a0, a1, a2, a3;
            ldmat_x4(a0, a1, a2, a3, sb + sw);
#pragma unroll
            for (int nt = 0; nt < 4; nt++)
                mma_bf16(acc[mt][nt][0], acc[mt][nt][1],
                         acc[mt][nt][2], acc[mt][nt][3],
                         a0, a1, a2, a3, bh_[nt][0], bh_[nt][1]);
#pragma unroll
            for (int nt = 0; nt < 4; nt++)
                mma_bf16(acc[mt][nt][0], acc[mt][nt][1],
                         acc[mt][nt][2], acc[mt][nt][3],
                         a0, a1, a2, a3, bl_[nt][0], bl_[nt][1]);
            ldmat_x4(a0, a1, a2, a3, sb + 16384u + sw);
#pragma unroll
            for (int nt = 0; nt < 4; nt++)
                mma_bf16(acc[mt][nt][0], acc[mt][nt][1],
                         acc[mt][nt][2], acc[mt][nt][3],
                         a0, a1, a2, a3, bh_[nt][0], bh_[nt][1]);
        }
    }

    const int group = lane >> 2, tig = lane & 3;
    const float* abh = ab + h * 196;
    float* lbase = g_logits + (size_t)bh * 196 * 196;
#pragma unroll
    for (int mt = 0; mt < 4; mt++) {
        int nr0 = n0 + warp_m * 64 + mt * 16 + group;
        int nr1 = nr0 + 8;
#pragma unroll
        for (int nt = 0; nt < 4; nt++) {
            int m = m0c + warp_n * 32 + nt * 8 + tig * 2;
            if (m < 196) {
                if (nr0 < 196) {
                    const int* br = bidx + (size_t)nr0 * 196;
                    lbase[(size_t)nr0 * 196 + m]     = acc[mt][nt][0] * SCALEF + abh[br[m]];
                    lbase[(size_t)nr0 * 196 + m + 1] = acc[mt][nt][1] * SCALEF + abh[br[m + 1]];
                }
                if (nr1 < 196) {
                    const int* br = bidx + (size_t)nr1 * 196;
                    lbase[(size_t)nr1 * 196 + m]     = acc[mt][nt][2] * SCALEF + abh[br[m]];
                    lbase[(size_t)nr1 * 196 + m + 1] = acc[mt][nt][3] * SCALEF + abh[br[m + 1]];
                }
            }
        }
    }
}

// ------------------------------------------------------------------
// AV batched mma v2 (unchanged R11): one block per bo, single V pass.
#define AV_STAGE_BYTES 98304
#define AV_SMEM_BYTES  (2 * AV_STAGE_BYTES)

__global__ void __launch_bounds__(256) av_mma_kernel()
{
    extern __shared__ __align__(1024) char smem[];
    const uint32_t sb = s2u(smem);
    const int tid = threadIdx.x;
    const int wid = tid >> 5, lane = tid & 31;
    const int warp_m = wid & 1;
    const int warp_n = wid >> 1;
    const int bo = blockIdx.x;
    const int b  = bo >> 3, o = bo & 7;

    const __nv_bfloat16* Ahi = g_vhi + ((size_t)b * 1024 + o * 128) * KPAD;
    const __nv_bfloat16* Alo = g_vlo + ((size_t)b * 1024 + o * 128) * KPAD;
    const __nv_bfloat16* Bhi = g_phi + ((size_t)bo * 196) * KPAD;
    const __nv_bfloat16* Blo = g_plo + ((size_t)bo * 196) * KPAD;

    float acc0[4][4][4], acc1[4][4][4];
#pragma unroll
    for (int i = 0; i < 4; i++)
#pragma unroll
        for (int j = 0; j < 4; j++)
#pragma unroll
            for (int c = 0; c < 4; c++) { acc0[i][j][c] = 0.f; acc1[i][j][c] = 0.f; }

    const int lrow = lane & 15;
    const uint32_t lkoff = (uint32_t)((lane >> 4) << 4);

    auto issue = [&](int kb, uint32_t stage_off) {
#pragma unroll
        for (int i = 0; i < 4; i++) {
            int q = tid + (i << 8);
            int row = q >> 3, k8 = q & 7;
            uint32_t off = (uint32_t)(row * 128 + k8 * 16);
            uint32_t sw = off ^ ((off >> 3) & 0x70);
            size_t ga = (size_t)row * KPAD + kb + (k8 << 3);
            cp_async16(sb + stage_off + sw,          Ahi + ga);
            cp_async16(sb + stage_off + 16384u + sw, Alo + ga);
            size_t gb0 = (size_t)row * KPAD + kb + (k8 << 3);
            cp_async16(sb + stage_off + 32768u + sw, Bhi + gb0);
            cp_async16(sb + stage_off + 49152u + sw, Blo + gb0);
            int jr = 128 + row;
            int valid = jr < 196;
            size_t gb1 = valid ? ((size_t)jr * KPAD + kb + (k8 << 3)) : 0;
            cp_async16_zf(sb + stage_off + 65536u + sw, Bhi + gb1, valid);
            cp_async16_zf(sb + stage_off + 81920u + sw, Blo + gb1, valid);
        }
        asm volatile("cp.async.commit_group;" ::: "memory");
    };

    issue(0, 0u);
    issue(64, AV_STAGE_BYTES);

    for (int ch = 0; ch < 4; ch++) {
        if (ch + 1 < 4) asm volatile("cp.async.wait_group 1;" ::: "memory");
        else            asm volatile("cp.async.wait_group 0;" ::: "memory");
        __syncthreads();

        const uint32_t buf = (ch & 1) ? (uint32_t)AV_STAGE_BYTES : 0u;
        const int nks = (ch == 3) ? 1 : 4;
        for (int ks = 0; ks < nks; ks++) {
            uint32_t b0h[4][2], b0l[4][2], b1h[4][2], b1l[4][2];
#pragma unroll
            for (int p = 0; p < 2; p++) {
                uint32_t off = (uint32_t)((warp_n * 32 + p * 16 + lrow) * 128)
                             + (uint32_t)(ks * 32) + lkoff;
                uint32_t sw = off ^ ((off >> 3) & 0x70);
                uint32_t r0, r1, r2, r3;
                ldmat_x4(r0, r1, r2, r3, sb + buf + 32768u + sw);
                b0h[p * 2 + 0][0] = r0; b0h[p * 2 + 1][0] = r1;
                b0h[p * 2 + 0][1] = r2; b0h[p * 2 + 1][1] = r3;
                ldmat_x4(r0, r1, r2, r3, sb + buf + 49152u + sw);
                b0l[p * 2 + 0][0] = r0; b0l[p * 2 + 1][0] = r1;
                b0l[p * 2 + 0][1] = r2; b0l[p * 2 + 1][1] = r3;
                ldmat_x4(r0, r1, r2, r3, sb + buf + 65536u + sw);
                b1h[p * 2 + 0][0] = r0; b1h[p * 2 + 1][0] = r1;
                b1h[p * 2 + 0][1] = r2; b1h[p * 2 + 1][1] = r3;
                ldmat_x4(r0, r1, r2, r3, sb + buf + 81920u + sw);
                b1l[p * 2 + 0][0] = r0; b1l[p * 2 + 1][0] = r1;
                b1l[p * 2 + 0][1] = r2; b1l[p * 2 + 1][1] = r3;
            }
#pragma unroll
            for (int mt = 0; mt < 4; mt++) {
                uint32_t off = (uint32_t)((warp_m * 64 + mt * 16 + lrow) * 128)
                             + (uint32_t)(ks * 32) + lkoff;
                uint32_t sw = off ^ ((off >> 3) & 0x70);
                uint32_t a0, a1, a2, a3;
                ldmat_x4(a0, a1, a2, a3, sb + buf + sw);
#pragma unroll
                for (int nt = 0; nt < 4; nt++) {
                    mma_bf16(acc0[mt][nt][0], acc0[mt][nt][1],
                             acc0[mt][nt][2], acc0[mt][nt][3],
                             a0, a1, a2, a3, b0h[nt][0], b0h[nt][1]);
                    mma_bf16(acc0[mt][nt][0], acc0[mt][nt][1],
                             acc0[mt][nt][2], acc0[mt][nt][3],
                             a0, a1, a2, a3, b0l[nt][0], b0l[nt][1]);
                    mma_bf16(acc1[mt][nt][0], acc1[mt][nt][1],
                             acc1[mt][nt][2], acc1[mt][nt][3],
                             a0, a1, a2, a3, b1h[nt][0], b1h[nt][1]);
                    mma_bf16(acc1[mt][nt][0], acc1[mt][nt][1],
                             acc1[mt][nt][2], acc1[mt][nt][3],
                             a0, a1, a2, a3, b1l[nt][0], b1l[nt][1]);
                }
                ldmat_x4(a0, a1, a2, a3, sb + buf + 16384u + sw);
#pragma unroll
                for (int nt = 0; nt < 4; nt++) {
                    mma_bf16(acc0[mt][nt][0], acc0[mt][nt][1],
                             acc0[mt][nt][2], acc0[mt][nt][3],
                             a0, a1, a2, a3, b0h[nt][0], b0h[nt][1]);
                    mma_bf16(acc1[mt][nt][0], acc1[mt][nt][1],
                             acc1[mt][nt][2], acc1[mt][nt][3],
                             a0, a1, a2, a3, b1h[nt][0], b1h[nt][1]);
                }
            }
        }

        if (ch + 2 < 4) {
            __syncthreads();
            issue((ch + 2) << 6, buf);
        }
    }

    const int group = lane >> 2, tig = lane & 3;
    const float* vlbase = g_vloc + ((size_t)b * 1024 + o * 128) * NPIX;
#pragma unroll
    for (int mt = 0; mt < 4; mt++) {
        int e0 = warp_m * 64 + mt * 16 + group;
        int e1 = e0 + 8;
#pragma unroll
        for (int nt = 0; nt < 4; nt++) {
            int jb = warp_n * 32 + nt * 8 + tig * 2;
#pragma unroll
            for (int tile = 0; tile < 2; tile++) {
                int j = jb + tile * 128;
                if (j < 196) {
                    float a0v = tile ? acc1[mt][nt][0] : acc0[mt][nt][0];
                    float a1v = tile ? acc1[mt][nt][1] : acc0[mt][nt][1];
                    float a2v = tile ? acc1[mt][nt][2] : acc0[mt][nt][2];
                    float a3v = tile ? acc1[mt][nt][3] : acc0[mt][nt][3];
                    float v00 = fmaxf(a0v + vlbase[(size_t)e0 * NPIX + j],     0.f);
                    float v01 = fmaxf(a1v + vlbase[(size_t)e0 * NPIX + j + 1], 0.f);
                    float v10 = fmaxf(a2v + vlbase[(size_t)e1 * NPIX + j],     0.f);
                    float v11 = fmaxf(a3v + vlbase[(size_t)e1 * NPIX + j + 1], 0.f);
                    size_t r00 = ((size_t)(b * 196 + j))     * 1024 + o * 128 + e0;
                    size_t r01 = ((size_t)(b * 196 + j + 1)) * 1024 + o * 128 + e0;
                    __nv_bfloat16 h;
                    h = __float2bfloat16(v00); g_pt_hi[r00] = h;
                    g_pt_lo[r00] = __float2bfloat16(v00 - __bfloat162float(h));
                    h = __float2bfloat16(v01); g_pt_hi[r01] = h;
                    g_pt_lo[r01] = __float2bfloat16(v01 - __bfloat162float(h));
                    h = __float2bfloat16(v10); g_pt_hi[r00 + 8] = h;
                    g_pt_lo[r00 + 8] = __float2bfloat16(v10 - __bfloat162float(h));
                    h = __float2bfloat16(v11); g_pt_hi[r01 + 8] = h;
                    g_pt_lo[r01 + 8] = __float2bfloat16(v11 - __bfloat162float(h));
                }
            }
        }
    }
}

// ------------------------------------------------------------------
// Depthwise 3x3 conv v4 (unchanged R11).
__global__ void __launch_bounds__(256) dwconv_kernel(
    const float* __restrict__ wvl, const float* __restrict__ bvl,
    const float* __restrict__ bn)
{
    int c0 = blockIdx.x * 8, b = blockIdx.y;
    __shared__ float p[8 * 256];
    __shared__ float wsh[72];
    __shared__ float cs[8], ct[8];
    int tid = threadIdx.x;
    const __nv_bfloat16* vhi = g_vhi + ((size_t)b * 1024 + c0) * KPAD;
    const __nv_bfloat16* vlo = g_vlo + ((size_t)b * 1024 + c0) * KPAD;

    for (int i = tid; i < 2048; i += 256) p[i] = 0.f;
    if (tid < 72) wsh[tid] = wvl[c0 * 9 + tid];
    if (tid < 8) {
        int c = c0 + tid;
        float s = bn[c] * rsqrtf(bn[3072 + c] + EPSF);
        cs[tid] = s;
        ct[tid] = (bvl[c] - bn[2048 + c]) * s + bn[1024 + c];
    }
    __syncthreads();

    for (int i = tid; i < 392; i += 256) {
        int c = i / 49, q = i - c * 49;
        int pix = q * 4;
        uint2 vh = *(const uint2*)(vhi + (size_t)c * KPAD + pix);
        uint2 vl = *(const uint2*)(vlo + (size_t)c * KPAD + pix);
        const __nv_bfloat162* hp = (const __nv_bfloat162*)&vh;
        const __nv_bfloat162* lp = (const __nv_bfloat162*)&vl;
        float2 h0 = __bfloat1622float2(hp[0]), h1 = __bfloat1622float2(hp[1]);
        float2 l0 = __bfloat1622float2(lp[0]), l1 = __bfloat1622float2(lp[1]);
        float vals[4] = { h0.x + l0.x, h0.y + l0.y, h1.x + l1.x, h1.y + l1.y };
        int y = pix / 14, x = pix - y * 14;
#pragma unroll
        for (int e = 0; e < 4; e++) {
            p[c * 256 + (y + 1) * 16 + (x + 1)] = vals[e];
            if (++x == 14) { x = 0; ++y; }
        }
    }
    __syncthreads();

    int w = tid >> 5, lane = tid & 31;
    if (lane < 28) {
        const float* pc = p + w * 256;
        float w00 = wsh[w * 9 + 0], w01 = wsh[w * 9 + 1], w02 = wsh[w * 9 + 2];
        float w10 = wsh[w * 9 + 3], w11 = wsh[w * 9 + 4], w12 = wsh[w * 9 + 5];
        float w20 = wsh[w * 9 + 6], w21 = wsh[w * 9 + 7], w22 = wsh[w * 9 + 8];
        float s = cs[w], t = ct[w];
        float* dst = g_vloc + (size_t)b * (DHC * NPIX) + (size_t)(c0 + w) * NPIX;
        int xr = lane >= 14;
        int x = lane - xr * 14;
#pragma unroll
        for (int it = 0; it < 7; it++) {
            int y = it * 2 + xr;
            const float* q = pc + y * 16 + x;
            float acc = w00 * q[0]  + w01 * q[1]  + w02 * q[2]
                      + w10 * q[16] + w11 * q[17] + w12 * q[18]
                      + w20 * q[32] + w21 * q[33] + w22 * q[34];
            dst[y * 14 + x] = acc * s + t;
        }
    }
}

// ------------------------------------------------------------------
// Attention core v6: paired-m vectorized TH1 / TH2+export.
#define ATTN_SMEM_FLOATS (21952 + 144)

__global__ void __launch_bounds__(256, 2) attn_kernel(
    const float* __restrict__ th1w, const float* __restrict__ th1b,
    const float* __restrict__ th2w, const float* __restrict__ th2b)
{
    extern __shared__ float sm[];
    float* L  = sm;
    float* th = sm + 21952;

    int tid = threadIdx.x;
    int b = blockIdx.y;
    int n0 = blockIdx.x * 14;

    if (tid < 64)       th[tid] = th1w[tid];
    else if (tid < 72)  th[tid] = th1b[tid - 64];
    else if (tid < 136) th[tid] = th2w[tid - 72];
    else if (tid < 144) th[tid] = th2b[tid - 136];
    __syncthreads();

    // ---- TH1, paired-m (float2 global loads, float2 smem stores) ----
    const float* lgbase = g_logits + (size_t)(b * 8) * 196 * 196;
    for (int idx = tid; idx < 1372; idx += 256) {
        int n_ = idx / 98, m = (idx - n_ * 98) * 2;
        size_t rowoff = (size_t)(n0 + n_) * 196 + m;
        float2 v[8];
#pragma unroll
        for (int hh = 0; hh < 8; hh++)
            v[hh] = *(const float2*)(lgbase + (size_t)hh * 196 * 196 + rowoff);
#pragma unroll
        for (int oo = 0; oo < 8; oo++) {
            float s0 = th[64 + oo], s1 = th[64 + oo];
#pragma unroll
            for (int hh = 0; hh < 8; hh++) {
                float w = th[oo * 8 + hh];
                s0 = fmaf(w, v[hh].x, s0);
                s1 = fmaf(w, v[hh].y, s1);
            }
            *(float2*)(L + (oo * 14 + n_) * 196 + m) = make_float2(s0, s1);
        }
    }
    __syncthreads();

    // ---- softmax over m (warp w owns head o = w) ----
    {
        int w = tid >> 5, lane = tid & 31;
        for (int r = 0; r < 14; r++) {
            float* row = L + (w * 14 + r) * 196;
            float mx = -1e30f;
            for (int m = lane; m < 196; m += 32) mx = fmaxf(mx, row[m]);
#pragma unroll
            for (int off = 16; off > 0; off >>= 1)
                mx = fmaxf(mx, __shfl_xor_sync(0xffffffffu, mx, off));
            float sum = 0.f;
            for (int m = lane; m < 196; m += 32) {
                float e = __expf(row[m] - mx);
                row[m] = e; sum += e;
            }
#pragma unroll
            for (int off = 16; off > 0; off >>= 1)
                sum += __shfl_xor_sync(0xffffffffu, sum, off);
            float inv = 1.f / sum;
            for (int m = lane; m < 196; m += 32) row[m] *= inv;
        }
    }
    __syncthreads();

    // ---- TH2 + P export, paired-m (bf16x2 packed stores) ----
    for (int idx = tid; idx < 1372; idx += 256) {
        int n_ = idx / 98, m = (idx - n_ * 98) * 2;
        float2 v[8];
#pragma unroll
        for (int hh = 0; hh < 8; hh++)
            v[hh] = *(const float2*)(L + (hh * 14 + n_) * 196 + m);
        size_t rbase = (size_t)(b * 8) * 196 + n0 + n_;
#pragma unroll
        for (int oo = 0; oo < 8; oo++) {
            float s0 = th[136 + oo], s1 = th[136 + oo];
#pragma unroll
            for (int hh = 0; hh < 8; hh++) {
                float w = th[72 + oo * 8 + hh];
                s0 = fmaf(w, v[hh].x, s0);
                s1 = fmaf(w, v[hh].y, s1);
            }
            __nv_bfloat162 hi2 = __floats2bfloat162_rn(s0, s1);
            float r0 = s0 - __bfloat162float(__low2bfloat16(hi2));
            float r1 = s1 - __bfloat162float(__high2bfloat16(hi2));
            __nv_bfloat162 lo2 = __floats2bfloat162_rn(r0, r1);
            size_t row = rbase + (size_t)oo * 196;
            *(__nv_bfloat162*)(g_phi + row * KPAD + m) = hi2;
            *(__nv_bfloat162*)(g_plo + row * KPAD + m) = lo2;
        }
    }
}

// ------------------------------------------------------------------
extern "C" void kernel_launch(void* const* d_in, const int* in_sizes, int n_in,
                              void* d_out, int out_size)
{
    const float* x    = (const float*)d_in[0];
    const float* wq   = (const float*)d_in[1];
    const float* bq   = (const float*)d_in[2];
    const float* bnq  = (const float*)d_in[3];
    const float* wk   = (const float*)d_in[4];
    const float* bk   = (const float*)d_in[5];
    const float* bnk  = (const float*)d_in[6];
    const float* wv   = (const float*)d_in[7];
    const float* bv   = (const float*)d_in[8];
    const float* bnv  = (const float*)d_in[9];
    const float* wvl  = (const float*)d_in[10];
    const float* bvl  = (const float*)d_in[11];
    const float* bnvl = (const float*)d_in[12];
    const float* th1w = (const float*)d_in[13];
    const float* th1b = (const float*)d_in[14];
    const float* th2w = (const float*)d_in[15];
    const float* th2b = (const float*)d_in[16];
    const float* wp   = (const float*)d_in[17];
    const float* bp   = (const float*)d_in[18];
    const float* bnp  = (const float*)d_in[19];
    const float* ab   = (const float*)d_in[20];
    const int*   bidx = (const int*)d_in[21];
    float* out = (float*)d_out;

    const int attn_smem = ATTN_SMEM_FLOATS * (int)sizeof(float);
    cudaFuncSetAttribute(attn_kernel,
                         cudaFuncAttributeMaxDynamicSharedMemorySize, attn_smem);
    cudaFuncSetAttribute(gemm_mma_kernel,
                         cudaFuncAttributeMaxDynamicSharedMemorySize, GEMM_SMEM_BYTES);
    cudaFuncSetAttribute(av_mma_kernel,
                         cudaFuncAttributeMaxDynamicSharedMemorySize, AV_SMEM_BYTES);
    cudaFuncSetAttribute(qk_mma_kernel,
                         cudaFuncAttributeMaxDynamicSharedMemorySize, QK_SMEM_BYTES);

    __nv_bfloat16 *wqkv_hi, *wqkv_lo, *xt_hi, *xt_lo, *wp_hi, *wp_lo, *pt_hi, *pt_lo;
    __nv_bfloat16 *qkh_hi, *qkh_lo;
    float *sv, *tv;
    cudaGetSymbolAddress((void**)&wqkv_hi, g_wqkv_hi);
    cudaGetSymbolAddress((void**)&wqkv_lo, g_wqkv_lo);
    cudaGetSymbolAddress((void**)&xt_hi, g_xt_hi);
    cudaGetSymbolAddress((void**)&xt_lo, g_xt_lo);
    cudaGetSymbolAddress((void**)&wp_hi, g_wp_hi);
    cudaGetSymbolAddress((void**)&wp_lo, g_wp_lo);
    cudaGetSymbolAddress((void**)&pt_hi, g_pt_hi);
    cudaGetSymbolAddress((void**)&pt_lo, g_pt_lo);
    cudaGetSymbolAddress((void**)&qkh_hi, g_qkh_hi);
    cudaGetSymbolAddress((void**)&qkh_lo, g_qkh_lo);
    cudaGetSymbolAddress((void**)&sv, g_s);
    cudaGetSymbolAddress((void**)&tv, g_t);

    // streams/events created once, outside any capture (first call is the
    // un-captured correctness run); reused on the capture call.
    static cudaStream_t s2 = nullptr;
    static cudaEvent_t evA, evB, evC, evD;
    if (s2 == nullptr) {
        cudaStreamCreateWithFlags(&s2, cudaStreamNonBlocking);
        cudaEventCreateWithFlags(&evA, cudaEventDisableTiming);
        cudaEventCreateWithFlags(&evB, cudaEventDisableTiming);
        cudaEventCreateWithFlags(&evC, cudaEventDisableTiming);
        cudaEventCreateWithFlags(&evD, cudaEventDisableTiming);
    }

    // fork: xt_cvt on s2 || prep on main
    cudaEventRecord(evA, 0);
    cudaStreamWaitEvent(s2, evA, 0);
    xt_cvt_kernel<<<dim3(7, 12, 64), 256, 0, s2>>>(x);
    prep_kernel<<<2304, 256>>>(wq, wk, wv, wp, bq, bk, bv, bp, bnq, bnk, bnv, bnp);
    cudaEventRecord(evB, s2);
    cudaStreamWaitEvent(0, evB, 0);

    // qkv GEMM: exports q/k (g_qkh) and V (g_vhi/g_vlo)
    gemm_mma_kernel<<<dim3(98, 12), 256, GEMM_SMEM_BYTES>>>(
        wqkv_hi, wqkv_lo, xt_hi, xt_lo, 384, sv, tv, nullptr, 1536, qkh_hi, qkh_lo);

    // fork: dwconv on s2 || (qk -> attn) on main
    cudaEventRecord(evC, 0);
    cudaStreamWaitEvent(s2, evC, 0);
    dwconv_kernel<<<dim3(128, 64), 256, 0, s2>>>(wvl, bvl, bnvl);
    qk_mma_kernel<<<dim3(2, 2, 512), 256, QK_SMEM_BYTES>>>(ab, bidx);
    attn_kernel<<<dim3(14, 64), 256, attn_smem>>>(th1w, th1b, th2w, th2b);
    cudaEventRecord(evD, s2);
    cudaStreamWaitEvent(0, evD, 0);

    // AV (needs attn P + dwconv vloc), then projection
    av_mma_kernel<<<512, 256, AV_SMEM_BYTES>>>();
    gemm_mma_kernel<<<dim3(98, 3), 256, GEMM_SMEM_BYTES>>>(
        wp_hi, wp_lo, pt_hi, pt_lo, 1024, sv + 1536, tv + 1536, out, 384,
        nullptr, nullptr);
}

// round 13
// speedup vs baseline: 3.7378x; 1.0134x over previous
#include <cuda_runtime.h>
#include <cuda_bf16.h>
#include <math.h>
#include <stdint.h>

#define EPSF 1e-5f
#define SCALEF 0.17677669529663687f

#define NB   64
#define NPIX 196
#define DHC  1024
#define NCOL 12544   // 64*196
#define KPAD 208     // padded k (m) dimension for AV mma (13*16)

// ------------------------------------------------------------------
// scratch (no cudaMalloc allowed)
__device__ float g_vloc[NB * DHC * NPIX];    // [b][1024][196]
__device__ float g_logits[512 * 196 * 196];  // [(b*8+h)][n][m] post-bias logits

__device__ __align__(16) __nv_bfloat16 g_xt_hi[NCOL * 384];   // [j][k]
__device__ __align__(16) __nv_bfloat16 g_xt_lo[NCOL * 384];
__device__ __align__(16) __nv_bfloat16 g_pt_hi[NCOL * 1024];  // [j][k]
__device__ __align__(16) __nv_bfloat16 g_pt_lo[NCOL * 1024];
__device__ __align__(16) __nv_bfloat16 g_wqkv_hi[1536 * 384]; // [m][k]
__device__ __align__(16) __nv_bfloat16 g_wqkv_lo[1536 * 384];
__device__ __align__(16) __nv_bfloat16 g_wp_hi[384 * 1024];
__device__ __align__(16) __nv_bfloat16 g_wp_lo[384 * 1024];
// q/k export: [(b*16 + hh)][n][d=32] bf16 hi/lo; hh 0-7 = q heads, 8-15 = k heads
__device__ __align__(16) __nv_bfloat16 g_qkh_hi[NB * 16 * 196 * 32];
__device__ __align__(16) __nv_bfloat16 g_qkh_lo[NB * 16 * 196 * 32];
// attention P (post-softmax/TH2) bf16 hi/lo: [(b*8+o)*196 + n][k=KPAD] (+ tail pad)
__device__ __align__(16) __nv_bfloat16 g_phi[512 * 196 * KPAD + 128];
__device__ __align__(16) __nv_bfloat16 g_plo[512 * 196 * KPAD + 128];
// BN'd V bf16 hi/lo: [b][c(1024)][k=KPAD] (written by qkv GEMM epilogue)
__device__ __align__(16) __nv_bfloat16 g_vhi[NB * 1024 * KPAD + 128];
__device__ __align__(16) __nv_bfloat16 g_vlo[NB * 1024 * KPAD + 128];
__device__ float g_s[1920];   // folded BN scale: [0:1536) qkv, [1536:1920) proj
__device__ float g_t[1920];   // folded BN shift

// ------------------------------------------------------------------
static __device__ __forceinline__ uint32_t s2u(const void* p) {
    uint32_t a;
    asm("{ .reg .u64 t; cvta.to.shared.u64 t, %1; cvt.u32.u64 %0, t; }"
        : "=r"(a) : "l"(p));
    return a;
}

static __device__ __forceinline__ void cp_async16(uint32_t saddr, const void* gptr) {
    asm volatile("cp.async.cg.shared.global [%0], [%1], 16;"
                 :: "r"(saddr), "l"(gptr) : "memory");
}

static __device__ __forceinline__ void cp_async16_zf(uint32_t saddr, const void* gptr, int valid) {
    int sz = valid ? 16 : 0;
    asm volatile("cp.async.cg.shared.global [%0], [%1], 16, %2;"
                 :: "r"(saddr), "l"(gptr), "r"(sz) : "memory");
}

static __device__ __forceinline__ void ldmat_x4(
    uint32_t& r0, uint32_t& r1, uint32_t& r2, uint32_t& r3, uint32_t addr)
{
    asm volatile("ldmatrix.sync.aligned.m8n8.x4.shared.b16 {%0,%1,%2,%3}, [%4];"
                 : "=r"(r0), "=r"(r1), "=r"(r2), "=r"(r3) : "r"(addr));
}

static __device__ __forceinline__ void mma_bf16(
    float& d0, float& d1, float& d2, float& d3,
    uint32_t a0, uint32_t a1, uint32_t a2, uint32_t a3,
    uint32_t b0, uint32_t b1)
{
    asm volatile(
        "mma.sync.aligned.m16n8k16.row.col.f32.bf16.bf16.f32 "
        "{%0,%1,%2,%3}, {%4,%5,%6,%7}, {%8,%9}, {%0,%1,%2,%3};"
        : "+f"(d0), "+f"(d1), "+f"(d2), "+f"(d3)
        : "r"(a0), "r"(a1), "r"(a2), "r"(a3), "r"(b0), "r"(b1));
}

// ------------------------------------------------------------------
// Prep 1 (critical path): fold BN scale/shift; split qkv weights bf16 hi/lo.
__global__ void __launch_bounds__(256) prep_kernel(
    const float* __restrict__ wq, const float* __restrict__ wk,
    const float* __restrict__ wv,
    const float* __restrict__ bq, const float* __restrict__ bk,
    const float* __restrict__ bv, const float* __restrict__ bp,
    const float* __restrict__ bnq, const float* __restrict__ bnk,
    const float* __restrict__ bnv, const float* __restrict__ bnp)
{
    int idx = blockIdx.x * 256 + threadIdx.x;
    int stride = gridDim.x * 256;

    for (int i = idx; i < 1536 * 384; i += stride) {
        int m = i / 384;
        float w = (m < 256) ? wq[i]
                : (m < 512) ? wk[i - 256 * 384]
                            : wv[i - 512 * 384];
        __nv_bfloat16 h = __float2bfloat16(w);
        g_wqkv_hi[i] = h;
        g_wqkv_lo[i] = __float2bfloat16(w - __bfloat162float(h));
    }
    if (idx < 1920) {
        const float* bn; const float* bias; int c; int C;
        if (idx < 256)       { bn = bnq; bias = bq; c = idx;        C = 256; }
        else if (idx < 512)  { bn = bnk; bias = bk; c = idx - 256;  C = 256; }
        else if (idx < 1536) { bn = bnv; bias = bv; c = idx - 512;  C = 1024; }
        else                 { bn = bnp; bias = bp; c = idx - 1536; C = 384; }
        float s = bn[c] * rsqrtf(bn[3 * C + c] + EPSF);
        g_s[idx] = s;
        g_t[idx] = (bias[c] - bn[2 * C + c]) * s + bn[C + c];
    }
}

// Prep 2 (off critical path; overlaps qkv GEMM): wp split + all pad zeroing.
__global__ void __launch_bounds__(256) prep2_kernel(const float* __restrict__ wp)
{
    int idx = blockIdx.x * 256 + threadIdx.x;
    int stride = gridDim.x * 256;

    for (int i = idx; i < 384 * 1024; i += stride) {
        float w = wp[i];
        __nv_bfloat16 h = __float2bfloat16(w);
        g_wp_hi[i] = h;
        g_wp_lo[i] = __float2bfloat16(w - __bfloat162float(h));
    }
    // zero P k-pad: rows 512*196, row stride 416B, pad = 24B at offset 392 (3 u64)
    for (long i = idx; i < (long)100352 * 3; i += stride) {
        long r = i / 3; int k = (int)(i % 3);
        *(unsigned long long*)((char*)g_phi + r * 416 + 392 + k * 8) = 0ull;
        *(unsigned long long*)((char*)g_plo + r * 416 + 392 + k * 8) = 0ull;
    }
    // zero V k-pad: rows 64*1024
    for (long i = idx; i < (long)65536 * 3; i += stride) {
        long r = i / 3; int k = (int)(i % 3);
        *(unsigned long long*)((char*)g_vhi + r * 416 + 392 + k * 8) = 0ull;
        *(unsigned long long*)((char*)g_vlo + r * 416 + 392 + k * 8) = 0ull;
    }
    if (idx < 128) {
        g_phi[512 * 196 * KPAD + idx] = __float2bfloat16(0.f);
        g_plo[512 * 196 * KPAD + idx] = __float2bfloat16(0.f);
        g_vhi[NB * 1024 * KPAD + idx] = __float2bfloat16(0.f);
        g_vlo[NB * 1024 * KPAD + idx] = __float2bfloat16(0.f);
    }
}

// ------------------------------------------------------------------
// Transpose+split x: [b][384][196] -> Xt[j=b*196+n][k=c] bf16 hi/lo
__global__ void __launch_bounds__(256) xt_cvt_kernel(const float* __restrict__ X)
{
    __shared__ float t[32][29];
    int b = blockIdx.z, c0 = blockIdx.y * 32, n0 = blockIdx.x * 28;
    int tid = threadIdx.x;
    const float* src = X + ((size_t)b * 384 + c0) * 196 + n0;
    for (int i = tid; i < 32 * 28; i += 256) {
        int ci = i / 28, nj = i - ci * 28;
        t[ci][nj] = src[(size_t)ci * 196 + nj];
    }
    __syncthreads();
    for (int i = tid; i < 32 * 28; i += 256) {
        int nj = i >> 5, ci = i & 31;
        float v = t[ci][nj];
        __nv_bfloat16 h = __float2bfloat16(v);
        size_t o = ((size_t)(b * 196 + n0 + nj)) * 384 + c0 + ci;
        g_xt_hi[o] = h;
        g_xt_lo[o] = __float2bfloat16(v - __bfloat162float(h));
    }
}

// ------------------------------------------------------------------
// bf16 mma.sync GEMM v2: 128(M) x 256(J) tiles, dual accumulators;
// A fragments reused across two B tiles (halves B L2 traffic).
// J grid = 49 (12544 = 49*256, no bounds checks).
// smem/stage: Ahi|Alo|B0hi|B0lo|B1hi|B1lo x16K = 96K; 2 stages = 192K.
#define GEMM_STAGE_BYTES 98304
#define GEMM_SMEM_BYTES  (2 * GEMM_STAGE_BYTES)

__global__ void __launch_bounds__(256) gemm_mma_kernel(
    const __nv_bfloat16* __restrict__ Ahi, const __nv_bfloat16* __restrict__ Alo,
    const __nv_bfloat16* __restrict__ Bhi, const __nv_bfloat16* __restrict__ Blo,
    int K, const float* __restrict__ svec, const float* __restrict__ tvec,
    float* __restrict__ out, int Cout,
    __nv_bfloat16* __restrict__ qk_hi, __nv_bfloat16* __restrict__ qk_lo)
{
    extern __shared__ __align__(1024) char smem[];
    const uint32_t sb = s2u(smem);
    const int tid = threadIdx.x;
    const int wid = tid >> 5, lane = tid & 31;
    const int warp_m = wid & 1;
    const int warp_n = wid >> 1;
    const int m0 = blockIdx.y * 128;
    const int j0 = blockIdx.x * 256;
    const int nk = K >> 6;
    const bool is_qkv = (qk_hi != nullptr);

    float acc0[4][4][4], acc1[4][4][4];
#pragma unroll
    for (int i = 0; i < 4; i++)
#pragma unroll
        for (int j = 0; j < 4; j++)
#pragma unroll
            for (int c = 0; c < 4; c++) { acc0[i][j][c] = 0.f; acc1[i][j][c] = 0.f; }

    const int lrow = lane & 15;
    const uint32_t lkoff = (uint32_t)((lane >> 4) << 4);

    auto issue = [&](int kb, uint32_t stage_off) {
#pragma unroll
        for (int i = 0; i < 4; i++) {
            int q = tid + (i << 8);
            int row = q >> 3, k8 = q & 7;
            uint32_t off = (uint32_t)(row * 128 + k8 * 16);
            uint32_t sw = off ^ ((off >> 3) & 0x70);
            size_t ga  = (size_t)(m0 + row) * K + kb + (k8 << 3);
            size_t gb0 = (size_t)(j0 + row) * K + kb + (k8 << 3);
            size_t gb1 = (size_t)(j0 + 128 + row) * K + kb + (k8 << 3);
            cp_async16(sb + stage_off + sw,           Ahi + ga);
            cp_async16(sb + stage_off + 16384u + sw,  Alo + ga);
            cp_async16(sb + stage_off + 32768u + sw,  Bhi + gb0);
            cp_async16(sb + stage_off + 49152u + sw,  Blo + gb0);
            cp_async16(sb + stage_off + 65536u + sw,  Bhi + gb1);
            cp_async16(sb + stage_off + 81920u + sw,  Blo + gb1);
        }
        asm volatile("cp.async.commit_group;" ::: "memory");
    };

    issue(0, 0u);
    if (nk > 1) issue(64, GEMM_STAGE_BYTES);

    for (int ch = 0; ch < nk; ch++) {
        if (ch + 1 < nk) asm volatile("cp.async.wait_group 1;" ::: "memory");
        else             asm volatile("cp.async.wait_group 0;" ::: "memory");
        __syncthreads();

        const uint32_t buf = (ch & 1) ? (uint32_t)GEMM_STAGE_BYTES : 0u;
#pragma unroll
        for (int ks = 0; ks < 4; ks++) {
            uint32_t b0h[4][2], b0l[4][2], b1h[4][2], b1l[4][2];
#pragma unroll
            for (int p = 0; p < 2; p++) {
                uint32_t off = (uint32_t)((warp_n * 32 + p * 16 + lrow) * 128)
                             + (uint32_t)(ks * 32) + lkoff;
                uint32_t sw = off ^ ((off >> 3) & 0x70);
                uint32_t r0, r1, r2, r3;
                ldmat_x4(r0, r1, r2, r3, sb + buf + 32768u + sw);
                b0h[p * 2 + 0][0] = r0; b0h[p * 2 + 1][0] = r1;
                b0h[p * 2 + 0][1] = r2; b0h[p * 2 + 1][1] = r3;
                ldmat_x4(r0, r1, r2, r3, sb + buf + 49152u + sw);
                b0l[p * 2 + 0][0] = r0; b0l[p * 2 + 1][0] = r1;
                b0l[p * 2 + 0][1] = r2; b0l[p * 2 + 1][1] = r3;
                ldmat_x4(r0, r1, r2, r3, sb + buf + 65536u + sw);
                b1h[p * 2 + 0][0] = r0; b1h[p * 2 + 1][0] = r1;
                b1h[p * 2 + 0][1] = r2; b1h[p * 2 + 1][1] = r3;
                ldmat_x4(r0, r1, r2, r3, sb + buf + 81920u + sw);
                b1l[p * 2 + 0][0] = r0; b1l[p * 2 + 1][0] = r1;
                b1l[p * 2 + 0][1] = r2; b1l[p * 2 + 1][1] = r3;
            }
#pragma unroll
            for (int mt = 0; mt < 4; mt++) {
                uint32_t off = (uint32_t)((warp_m * 64 + mt * 16 + lrow) * 128)
                             + (uint32_t)(ks * 32) + lkoff;
                uint32_t sw = off ^ ((off >> 3) & 0x70);
                uint32_t a0, a1, a2, a3;
                ldmat_x4(a0, a1, a2, a3, sb + buf + sw);
#pragma unroll
                for (int nt = 0; nt < 4; nt++) {
                    mma_bf16(acc0[mt][nt][0], acc0[mt][nt][1],
                             acc0[mt][nt][2], acc0[mt][nt][3],
                             a0, a1, a2, a3, b0h[nt][0], b0h[nt][1]);
                    mma_bf16(acc0[mt][nt][0], acc0[mt][nt][1],
                             acc0[mt][nt][2], acc0[mt][nt][3],
                             a0, a1, a2, a3, b0l[nt][0], b0l[nt][1]);
                    mma_bf16(acc1[mt][nt][0], acc1[mt][nt][1],
                             acc1[mt][nt][2], acc1[mt][nt][3],
                             a0, a1, a2, a3, b1h[nt][0], b1h[nt][1]);
                    mma_bf16(acc1[mt][nt][0], acc1[mt][nt][1],
                             acc1[mt][nt][2], acc1[mt][nt][3],
                             a0, a1, a2, a3, b1l[nt][0], b1l[nt][1]);
                }
                ldmat_x4(a0, a1, a2, a3, sb + buf + 16384u + sw);
#pragma unroll
                for (int nt = 0; nt < 4; nt++) {
                    mma_bf16(acc0[mt][nt][0], acc0[mt][nt][1],
                             acc0[mt][nt][2], acc0[mt][nt][3],
                             a0, a1, a2, a3, b0h[nt][0], b0h[nt][1]);
                    mma_bf16(acc1[mt][nt][0], acc1[mt][nt][1],
                             acc1[mt][nt][2], acc1[mt][nt][3],
                             a0, a1, a2, a3, b1h[nt][0], b1h[nt][1]);
                }
            }
        }

        if (ch + 2 < nk) {
            __syncthreads();
            issue((ch + 2) << 6, buf);
        }
    }

    const int group = lane >> 2, tig = lane & 3;
#pragma unroll
    for (int mt = 0; mt < 4; mt++) {
        int oc0 = m0 + warp_m * 64 + mt * 16 + group;
        int oc1 = oc0 + 8;
        float s0 = svec[oc0], t0 = tvec[oc0];
        float s1 = svec[oc1], t1 = tvec[oc1];
#pragma unroll
        for (int nt = 0; nt < 4; nt++) {
#pragma unroll
            for (int tile = 0; tile < 2; tile++) {
                int j = j0 + tile * 128 + warp_n * 32 + nt * 8 + tig * 2;
                float (*ac)[4][4] = tile ? acc1 : acc0;
                float v00 = ac[mt][nt][0] * s0 + t0;
                float v01 = ac[mt][nt][1] * s0 + t0;
                float v10 = ac[mt][nt][2] * s1 + t1;
                float v11 = ac[mt][nt][3] * s1 + t1;
                int b = j / 196, n = j - b * 196;
                if (!is_qkv) {
                    float* p0 = out + ((size_t)b * Cout + oc0) * 196 + n;
                    float* p1 = out + ((size_t)b * Cout + oc1) * 196 + n;
                    p0[0] = v00; p0[1] = v01;
                    p1[0] = v10; p1[1] = v11;
                } else if (m0 < 512) {
                    size_t r0 = (((size_t)(b * 16) + (oc0 >> 5)) * 196 + n) * 32 + (oc0 & 31);
                    size_t r1 = (((size_t)(b * 16) + (oc1 >> 5)) * 196 + n) * 32 + (oc1 & 31);
                    __nv_bfloat16 h;
                    h = __float2bfloat16(v00); qk_hi[r0] = h;
                    qk_lo[r0] = __float2bfloat16(v00 - __bfloat162float(h));
                    h = __float2bfloat16(v01); qk_hi[r0 + 32] = h;
                    qk_lo[r0 + 32] = __float2bfloat16(v01 - __bfloat162float(h));
                    h = __float2bfloat16(v10); qk_hi[r1] = h;
                    qk_lo[r1] = __float2bfloat16(v10 - __bfloat162float(h));
                    h = __float2bfloat16(v11); qk_hi[r1 + 32] = h;
                    qk_lo[r1 + 32] = __float2bfloat16(v11 - __bfloat162float(h));
                } else {
                    size_t r0 = ((size_t)b * 1024 + (oc0 - 512)) * KPAD + n;
                    size_t r1 = ((size_t)b * 1024 + (oc1 - 512)) * KPAD + n;
                    __nv_bfloat16 h;
                    h = __float2bfloat16(v00); g_vhi[r0] = h;
                    g_vlo[r0] = __float2bfloat16(v00 - __bfloat162float(h));
                    h = __float2bfloat16(v01); g_vhi[r0 + 1] = h;
                    g_vlo[r0 + 1] = __float2bfloat16(v01 - __bfloat162float(h));
                    h = __float2bfloat16(v10); g_vhi[r1] = h;
                    g_vlo[r1] = __float2bfloat16(v10 - __bfloat162float(h));
                    h = __float2bfloat16(v11); g_vhi[r1 + 1] = h;
                    g_vlo[r1 + 1] = __float2bfloat16(v11 - __bfloat162float(h));
                }
            }
        }
    }
}

// ------------------------------------------------------------------
// QK logits mma (unchanged).
#define QK_SMEM_BYTES 65536

__global__ void __launch_bounds__(256) qk_mma_kernel(
    const float* __restrict__ ab, const int* __restrict__ bidx)
{
    extern __shared__ __align__(1024) char smem[];
    const uint32_t sb = s2u(smem);
    const int tid = threadIdx.x;
    const int wid = tid >> 5, lane = tid & 31;
    const int warp_m = wid & 1;
    const int warp_n = wid >> 1;
    const int bh = blockIdx.z;
    const int b = bh >> 3, h = bh & 7;
    const int n0 = blockIdx.x * 128;
    const int m0c = blockIdx.y * 128;

    const __nv_bfloat16* Qhi = g_qkh_hi + (size_t)(b * 16 + h) * 196 * 32;
    const __nv_bfloat16* Qlo = g_qkh_lo + (size_t)(b * 16 + h) * 196 * 32;
    const __nv_bfloat16* Khi = g_qkh_hi + (size_t)(b * 16 + 8 + h) * 196 * 32;
    const __nv_bfloat16* Klo = g_qkh_lo + (size_t)(b * 16 + 8 + h) * 196 * 32;

#pragma unroll
    for (int t = 0; t < 2; t++) {
        int q = tid + (t << 8);
        int row = q >> 2, k8 = q & 3;
        uint32_t off = (uint32_t)(row * 128 + k8 * 16);
        uint32_t sw = off ^ ((off >> 3) & 0x70);
        int nr = n0 + row;
        int vq = nr < 196;
        size_t gq = vq ? ((size_t)nr * 32 + (k8 << 3)) : 0;
        cp_async16_zf(sb + sw,           Qhi + gq, vq);
        cp_async16_zf(sb + 16384u + sw,  Qlo + gq, vq);
        int mr = m0c + row;
        int vk = mr < 196;
        size_t gk = vk ? ((size_t)mr * 32 + (k8 << 3)) : 0;
        cp_async16_zf(sb + 32768u + sw,  Khi + gk, vk);
        cp_async16_zf(sb + 49152u + sw,  Klo + gk, vk);
    }
    asm volatile("cp.async.commit_group;" ::: "memory");
    asm volatile("cp.async.wait_group 0;" ::: "memory");
    __syncthreads();

    float acc[4][4][4];
#pragma unroll
    for (int i = 0; i < 4; i++)
#pragma unroll
        for (int j = 0; j < 4; j++)
#pragma unroll
            for (int c = 0; c < 4; c++) acc[i][j][c] = 0.f;

    const int lrow = lane & 15;
    const uint32_t lkoff = (uint32_t)((lane >> 4) << 4);

#pragma unroll
    for (int ks = 0; ks < 2; ks++) {
        uint32_t bh_[4][2], bl_[4][2];
#pragma unroll
        for (int p = 0; p < 2; p++) {
            uint32_t off = (uint32_t)((warp_n * 32 + p * 16 + lrow) * 128)
                         + (uint32_t)(ks * 32) + lkoff;
            uint32_t sw = off ^ ((off >> 3) & 0x70);
            uint32_t r0, r1, r2, r3;
            ldmat_x4(r0, r1, r2, r3, sb + 32768u + sw);
            bh_[p * 2 + 0][0] = r0; bh_[p * 2 + 1][0] = r1;
            bh_[p * 2 + 0][1] = r2; bh_[p * 2 + 1][1] = r3;
            ldmat_x4(r0, r1, r2, r3, sb + 49152u + sw);
            bl_[p * 2 + 0][0] = r0; bl_[p * 2 + 1][0] = r1;
            bl_[p * 2 + 0][1] = r2; bl_[p * 2 + 1][1] = r3;
        }
#pragma unroll
        for (int mt = 0; mt < 4; mt++) {
            uint32_t off = (uint32_t)((warp_m * 64 + mt * 16 + lrow) * 128)
                         + (uint32_t)(ks * 32) + lkoff;
            uint32_t sw = off ^ ((off >> 3) & 0x70);
            uint32_t a0, a1, a2, a3;
            ldmat_x4(a0, a1, a2, a3, sb + sw);
#pragma unroll
            for (int nt = 0; nt < 4; nt++)
                mma_bf16(acc[mt][nt][0], acc[mt][nt][1],
                         acc[mt][nt][2], acc[mt][nt][3],
                         a0, a1, a2, a3, bh_[nt][0], bh_[nt][1]);
#pragma unroll
            for (int nt = 0; nt < 4; nt++)
                mma_bf16(acc[mt][nt][0], acc[mt][nt][1],
                         acc[mt][nt][2], acc[mt][nt][3],
                         a0, a1, a2, a3, bl_[nt][0], bl_[nt][1]);
            ldmat_x4(a0, a1, a2, a3, sb + 16384u + sw);
#pragma unroll
            for (int nt = 0; nt < 4; nt++)
                mma_bf16(acc[mt][nt][0], acc[mt][nt][1],
                         acc[mt][nt][2], acc[mt][nt][3],
                         a0, a1, a2, a3, bh_[nt][0], bh_[nt][1]);
        }
    }

    const int group = lane >> 2, tig = lane & 3;
    const float* abh = ab + h * 196;
    float* lbase = g_logits + (size_t)bh * 196 * 196;
#pragma unroll
    for (int mt = 0; mt < 4; mt++) {
        int nr0 = n0 + warp_m * 64 + mt * 16 + group;
        int nr1 = nr0 + 8;
#pragma unroll
        for (int nt = 0; nt < 4; nt++) {
            int m = m0c + warp_n * 32 + nt * 8 + tig * 2;
            if (m < 196) {
                if (nr0 < 196) {
                    const int* br = bidx + (size_t)nr0 * 196;
                    lbase[(size_t)nr0 * 196 + m]     = acc[mt][nt][0] * SCALEF + abh[br[m]];
                    lbase[(size_t)nr0 * 196 + m + 1] = acc[mt][nt][1] * SCALEF + abh[br[m + 1]];
                }
                if (nr1 < 196) {
                    const int* br = bidx + (size_t)nr1 * 196;
                    lbase[(size_t)nr1 * 196 + m]     = acc[mt][nt][2] * SCALEF + abh[br[m]];
                    lbase[(size_t)nr1 * 196 + m + 1] = acc[mt][nt][3] * SCALEF + abh[br[m + 1]];
                }
            }
        }
    }
}

// ------------------------------------------------------------------
// AV batched mma (unchanged R11/R12): one block per bo, single V pass.
#define AV_STAGE_BYTES 98304
#define AV_SMEM_BYTES  (2 * AV_STAGE_BYTES)

__global__ void __launch_bounds__(256) av_mma_kernel()
{
    extern __shared__ __align__(1024) char smem[];
    const uint32_t sb = s2u(smem);
    const int tid = threadIdx.x;
    const int wid = tid >> 5, lane = tid & 31;
    const int warp_m = wid & 1;
    const int warp_n = wid >> 1;
    const int bo = blockIdx.x;
    const int b  = bo >> 3, o = bo & 7;

    const __nv_bfloat16* Ahi = g_vhi + ((size_t)b * 1024 + o * 128) * KPAD;
    const __nv_bfloat16* Alo = g_vlo + ((size_t)b * 1024 + o * 128) * KPAD;
    const __nv_bfloat16* Bhi = g_phi + ((size_t)bo * 196) * KPAD;
    const __nv_bfloat16* Blo = g_plo + ((size_t)bo * 196) * KPAD;

    float acc0[4][4][4], acc1[4][4][4];
#pragma unroll
    for (int i = 0; i < 4; i++)
#pragma unroll
        for (int j = 0; j < 4; j++)
#pragma unroll
            for (int c = 0; c < 4; c++) { acc0[i][j][c] = 0.f; acc1[i][j][c] = 0.f; }

    const int lrow = lane & 15;
    const uint32_t lkoff = (uint32_t)((lane >> 4) << 4);

    auto issue = [&](int kb, uint32_t stage_off) {
#pragma unroll
        for (int i = 0; i < 4; i++) {
            int q = tid + (i << 8);
            int row = q >> 3, k8 = q & 7;
            uint32_t off = (uint32_t)(row * 128 + k8 * 16);
            uint32_t sw = off ^ ((off >> 3) & 0x70);
            size_t ga = (size_t)row * KPAD + kb + (k8 << 3);
            cp_async16(sb + stage_off + sw,          Ahi + ga);
            cp_async16(sb + stage_off + 16384u + sw, Alo + ga);
            size_t gb0 = (size_t)row * KPAD + kb + (k8 << 3);
            cp_async16(sb + stage_off + 32768u + sw, Bhi + gb0);
            cp_async16(sb + stage_off + 49152u + sw, Blo + gb0);
            int jr = 128 + row;
            int valid = jr < 196;
            size_t gb1 = valid ? ((size_t)jr * KPAD + kb + (k8 << 3)) : 0;
            cp_async16_zf(sb + stage_off + 65536u + sw, Bhi + gb1, valid);
            cp_async16_zf(sb + stage_off + 81920u + sw, Blo + gb1, valid);
        }
        asm volatile("cp.async.commit_group;" ::: "memory");
    };

    issue(0, 0u);
    issue(64, AV_STAGE_BYTES);

    for (int ch = 0; ch < 4; ch++) {
        if (ch + 1 < 4) asm volatile("cp.async.wait_group 1;" ::: "memory");
        else            asm volatile("cp.async.wait_group 0;" ::: "memory");
        __syncthreads();

        const uint32_t buf = (ch & 1) ? (uint32_t)AV_STAGE_BYTES : 0u;
        const int nks = (ch == 3) ? 1 : 4;
        for (int ks = 0; ks < nks; ks++) {
            uint32_t b0h[4][2], b0l[4][2], b1h[4][2], b1l[4][2];
#pragma unroll
            for (int p = 0; p < 2; p++) {
                uint32_t off = (uint32_t)((warp_n * 32 + p * 16 + lrow) * 128)
                             + (uint32_t)(ks * 32) + lkoff;
                uint32_t sw = off ^ ((off >> 3) & 0x70);
                uint32_t r0, r1, r2, r3;
                ldmat_x4(r0, r1, r2, r3, sb + buf + 32768u + sw);
                b0h[p * 2 + 0][0] = r0; b0h[p * 2 + 1][0] = r1;
                b0h[p * 2 + 0][1] = r2; b0h[p * 2 + 1][1] = r3;
                ldmat_x4(r0, r1, r2, r3, sb + buf + 49152u + sw);
                b0l[p * 2 + 0][0] = r0; b0l[p * 2 + 1][0] = r1;
                b0l[p * 2 + 0][1] = r2; b0l[p * 2 + 1][1] = r3;
                ldmat_x4(r0, r1, r2, r3, sb + buf + 65536u + sw);
                b1h[p * 2 + 0][0] = r0; b1h[p * 2 + 1][0] = r1;
                b1h[p * 2 + 0][1] = r2; b1h[p * 2 + 1][1] = r3;
                ldmat_x4(r0, r1, r2, r3, sb + buf + 81920u + sw);
                b1l[p * 2 + 0][0] = r0; b1l[p * 2 + 1][0] = r1;
                b1l[p * 2 + 0][1] = r2; b1l[p * 2 + 1][1] = r3;
            }
#pragma unroll
            for (int mt = 0; mt < 4; mt++) {
                uint32_t off = (uint32_t)((warp_m * 64 + mt * 16 + lrow) * 128)
                             + (uint32_t)(ks * 32) + lkoff;
                uint32_t sw = off ^ ((off >> 3) & 0x70);
                uint32_t a0, a1, a2, a3;
                ldmat_x4(a0, a1, a2, a3, sb + buf + sw);
#pragma unroll
                for (int nt = 0; nt < 4; nt++) {
                    mma_bf16(acc0[mt][nt][0], acc0[mt][nt][1],
                             acc0[mt][nt][2], acc0[mt][nt][3],
                             a0, a1, a2, a3, b0h[nt][0], b0h[nt][1]);
                    mma_bf16(acc0[mt][nt][0], acc0[mt][nt][1],
                             acc0[mt][nt][2], acc0[mt][nt][3],
                             a0, a1, a2, a3, b0l[nt][0], b0l[nt][1]);
                    mma_bf16(acc1[mt][nt][0], acc1[mt][nt][1],
                             acc1[mt][nt][2], acc1[mt][nt][3],
                             a0, a1, a2, a3, b1h[nt][0], b1h[nt][1]);
                    mma_bf16(acc1[mt][nt][0], acc1[mt][nt][1],
                             acc1[mt][nt][2], acc1[mt][nt][3],
                             a0, a1, a2, a3, b1l[nt][0], b1l[nt][1]);
                }
                ldmat_x4(a0, a1, a2, a3, sb + buf + 16384u + sw);
#pragma unroll
                for (int nt = 0; nt < 4; nt++) {
                    mma_bf16(acc0[mt][nt][0], acc0[mt][nt][1],
                             acc0[mt][nt][2], acc0[mt][nt][3],
                             a0, a1, a2, a3, b0h[nt][0], b0h[nt][1]);
                    mma_bf16(acc1[mt][nt][0], acc1[mt][nt][1],
                             acc1[mt][nt][2], acc1[mt][nt][3],
                             a0, a1, a2, a3, b1h[nt][0], b1h[nt][1]);
                }
            }
        }

        if (ch + 2 < 4) {
            __syncthreads();
            issue((ch + 2) << 6, buf);
        }
    }

    const int group = lane >> 2, tig = lane & 3;
    const float* vlbase = g_vloc + ((size_t)b * 1024 + o * 128) * NPIX;
#pragma unroll
    for (int mt = 0; mt < 4; mt++) {
        int e0 = warp_m * 64 + mt * 16 + group;
        int e1 = e0 + 8;
#pragma unroll
        for (int nt = 0; nt < 4; nt++) {
            int jb = warp_n * 32 + nt * 8 + tig * 2;
#pragma unroll
            for (int tile = 0; tile < 2; tile++) {
                int j = jb + tile * 128;
                if (j < 196) {
                    float a0v = tile ? acc1[mt][nt][0] : acc0[mt][nt][0];
                    float a1v = tile ? acc1[mt][nt][1] : acc0[mt][nt][1];
                    float a2v = tile ? acc1[mt][nt][2] : acc0[mt][nt][2];
                    float a3v = tile ? acc1[mt][nt][3] : acc0[mt][nt][3];
                    float v00 = fmaxf(a0v + vlbase[(size_t)e0 * NPIX + j],     0.f);
                    float v01 = fmaxf(a1v + vlbase[(size_t)e0 * NPIX + j + 1], 0.f);
                    float v10 = fmaxf(a2v + vlbase[(size_t)e1 * NPIX + j],     0.f);
                    float v11 = fmaxf(a3v + vlbase[(size_t)e1 * NPIX + j + 1], 0.f);
                    size_t r00 = ((size_t)(b * 196 + j))     * 1024 + o * 128 + e0;
                    size_t r01 = ((size_t)(b * 196 + j + 1)) * 1024 + o * 128 + e0;
                    __nv_bfloat16 h;
                    h = __float2bfloat16(v00); g_pt_hi[r00] = h;
                    g_pt_lo[r00] = __float2bfloat16(v00 - __bfloat162float(h));
                    h = __float2bfloat16(v01); g_pt_hi[r01] = h;
                    g_pt_lo[r01] = __float2bfloat16(v01 - __bfloat162float(h));
                    h = __float2bfloat16(v10); g_pt_hi[r00 + 8] = h;
                    g_pt_lo[r00 + 8] = __float2bfloat16(v10 - __bfloat162float(h));
                    h = __float2bfloat16(v11); g_pt_hi[r01 + 8] = h;
                    g_pt_lo[r01 + 8] = __float2bfloat16(v11 - __bfloat162float(h));
                }
            }
        }
    }
}

// ------------------------------------------------------------------
// Depthwise 3x3 conv (unchanged R11/R12).
__global__ void __launch_bounds__(256) dwconv_kernel(
    const float* __restrict__ wvl, const float* __restrict__ bvl,
    const float* __restrict__ bn)
{
    int c0 = blockIdx.x * 8, b = blockIdx.y;
    __shared__ float p[8 * 256];
    __shared__ float wsh[72];
    __shared__ float cs[8], ct[8];
    int tid = threadIdx.x;
    const __nv_bfloat16* vhi = g_vhi + ((size_t)b * 1024 + c0) * KPAD;
    const __nv_bfloat16* vlo = g_vlo + ((size_t)b * 1024 + c0) * KPAD;

    for (int i = tid; i < 2048; i += 256) p[i] = 0.f;
    if (tid < 72) wsh[tid] = wvl[c0 * 9 + tid];
    if (tid < 8) {
        int c = c0 + tid;
        float s = bn[c] * rsqrtf(bn[3072 + c] + EPSF);
        cs[tid] = s;
        ct[tid] = (bvl[c] - bn[2048 + c]) * s + bn[1024 + c];
    }
    __syncthreads();

    for (int i = tid; i < 392; i += 256) {
        int c = i / 49, q = i - c * 49;
        int pix = q * 4;
        uint2 vh = *(const uint2*)(vhi + (size_t)c * KPAD + pix);
        uint2 vl = *(const uint2*)(vlo + (size_t)c * KPAD + pix);
        const __nv_bfloat162* hp = (const __nv_bfloat162*)&vh;
        const __nv_bfloat162* lp = (const __nv_bfloat162*)&vl;
        float2 h0 = __bfloat1622float2(hp[0]), h1 = __bfloat1622float2(hp[1]);
        float2 l0 = __bfloat1622float2(lp[0]), l1 = __bfloat1622float2(lp[1]);
        float vals[4] = { h0.x + l0.x, h0.y + l0.y, h1.x + l1.x, h1.y + l1.y };
        int y = pix / 14, x = pix - y * 14;
#pragma unroll
        for (int e = 0; e < 4; e++) {
            p[c * 256 + (y + 1) * 16 + (x + 1)] = vals[e];
            if (++x == 14) { x = 0; ++y; }
        }
    }
    __syncthreads();

    int w = tid >> 5, lane = tid & 31;
    if (lane < 28) {
        const float* pc = p + w * 256;
        float w00 = wsh[w * 9 + 0], w01 = wsh[w * 9 + 1], w02 = wsh[w * 9 + 2];
        float w10 = wsh[w * 9 + 3], w11 = wsh[w * 9 + 4], w12 = wsh[w * 9 + 5];
        float w20 = wsh[w * 9 + 6], w21 = wsh[w * 9 + 7], w22 = wsh[w * 9 + 8];
        float s = cs[w], t = ct[w];
        float* dst = g_vloc + (size_t)b * (DHC * NPIX) + (size_t)(c0 + w) * NPIX;
        int xr = lane >= 14;
        int x = lane - xr * 14;
#pragma unroll
        for (int it = 0; it < 7; it++) {
            int y = it * 2 + xr;
            const float* q = pc + y * 16 + x;
            float acc = w00 * q[0]  + w01 * q[1]  + w02 * q[2]
                      + w10 * q[16] + w11 * q[17] + w12 * q[18]
                      + w20 * q[32] + w21 * q[33] + w22 * q[34];
            dst[y * 14 + x] = acc * s + t;
        }
    }
}

// ------------------------------------------------------------------
// Attention core v6 (unchanged R12): paired-m vectorized TH1 / TH2+export.
#define ATTN_SMEM_FLOATS (21952 + 144)

__global__ void __launch_bounds__(256, 2) attn_kernel(
    const float* __restrict__ th1w, const float* __restrict__ th1b,
    const float* __restrict__ th2w, const float* __restrict__ th2b)
{
    extern __shared__ float sm[];
    float* L  = sm;
    float* th = sm + 21952;

    int tid = threadIdx.x;
    int b = blockIdx.y;
    int n0 = blockIdx.x * 14;

    if (tid < 64)       th[tid] = th1w[tid];
    else if (tid < 72)  th[tid] = th1b[tid - 64];
    else if (tid < 136) th[tid] = th2w[tid - 72];
    else if (tid < 144) th[tid] = th2b[tid - 136];
    __syncthreads();

    const float* lgbase = g_logits + (size_t)(b * 8) * 196 * 196;
    for (int idx = tid; idx < 1372; idx += 256) {
        int n_ = idx / 98, m = (idx - n_ * 98) * 2;
        size_t rowoff = (size_t)(n0 + n_) * 196 + m;
        float2 v[8];
#pragma unroll
        for (int hh = 0; hh < 8; hh++)
            v[hh] = *(const float2*)(lgbase + (size_t)hh * 196 * 196 + rowoff);
#pragma unroll
        for (int oo = 0; oo < 8; oo++) {
            float s0 = th[64 + oo], s1 = th[64 + oo];
#pragma unroll
            for (int hh = 0; hh < 8; hh++) {
                float w = th[oo * 8 + hh];
                s0 = fmaf(w, v[hh].x, s0);
                s1 = fmaf(w, v[hh].y, s1);
            }
            *(float2*)(L + (oo * 14 + n_) * 196 + m) = make_float2(s0, s1);
        }
    }
    __syncthreads();

    {
        int w = tid >> 5, lane = tid & 31;
        for (int r = 0; r < 14; r++) {
            float* row = L + (w * 14 + r) * 196;
            float mx = -1e30f;
            for (int m = lane; m < 196; m += 32) mx = fmaxf(mx, row[m]);
#pragma unroll
            for (int off = 16; off > 0; off >>= 1)
                mx = fmaxf(mx, __shfl_xor_sync(0xffffffffu, mx, off));
            float sum = 0.f;
            for (int m = lane; m < 196; m += 32) {
                float e = __expf(row[m] - mx);
                row[m] = e; sum += e;
            }
#pragma unroll
            for (int off = 16; off > 0; off >>= 1)
                sum += __shfl_xor_sync(0xffffffffu, sum, off);
            float inv = 1.f / sum;
            for (int m = lane; m < 196; m += 32) row[m] *= inv;
        }
    }
    __syncthreads();

    for (int idx = tid; idx < 1372; idx += 256) {
        int n_ = idx / 98, m = (idx - n_ * 98) * 2;
        float2 v[8];
#pragma unroll
        for (int hh = 0; hh < 8; hh++)
            v[hh] = *(const float2*)(L + (hh * 14 + n_) * 196 + m);
        size_t rbase = (size_t)(b * 8) * 196 + n0 + n_;
#pragma unroll
        for (int oo = 0; oo < 8; oo++) {
            float s0 = th[136 + oo], s1 = th[136 + oo];
#pragma unroll
            for (int hh = 0; hh < 8; hh++) {
                float w = th[72 + oo * 8 + hh];
                s0 = fmaf(w, v[hh].x, s0);
                s1 = fmaf(w, v[hh].y, s1);
            }
            __nv_bfloat162 hi2 = __floats2bfloat162_rn(s0, s1);
            float r0 = s0 - __bfloat162float(__low2bfloat16(hi2));
            float r1 = s1 - __bfloat162float(__high2bfloat16(hi2));
            __nv_bfloat162 lo2 = __floats2bfloat162_rn(r0, r1);
            size_t row = rbase + (size_t)oo * 196;
            *(__nv_bfloat162*)(g_phi + row * KPAD + m) = hi2;
            *(__nv_bfloat162*)(g_plo + row * KPAD + m) = lo2;
        }
    }
}

// ------------------------------------------------------------------
extern "C" void kernel_launch(void* const* d_in, const int* in_sizes, int n_in,
                              void* d_out, int out_size)
{
    const float* x    = (const float*)d_in[0];
    const float* wq   = (const float*)d_in[1];
    const float* bq   = (const float*)d_in[2];
    const float* bnq  = (const float*)d_in[3];
    const float* wk   = (const float*)d_in[4];
    const float* bk   = (const float*)d_in[5];
    const float* bnk  = (const float*)d_in[6];
    const float* wv   = (const float*)d_in[7];
    const float* bv   = (const float*)d_in[8];
    const float* bnv  = (const float*)d_in[9];
    const float* wvl  = (const float*)d_in[10];
    const float* bvl  = (const float*)d_in[11];
    const float* bnvl = (const float*)d_in[12];
    const float* th1w = (const float*)d_in[13];
    const float* th1b = (const float*)d_in[14];
    const float* th2w = (const float*)d_in[15];
    const float* th2b = (const float*)d_in[16];
    const float* wp   = (const float*)d_in[17];
    const float* bp   = (const float*)d_in[18];
    const float* bnp  = (const float*)d_in[19];
    const float* ab   = (const float*)d_in[20];
    const int*   bidx = (const int*)d_in[21];
    float* out = (float*)d_out;

    const int attn_smem = ATTN_SMEM_FLOATS * (int)sizeof(float);
    cudaFuncSetAttribute(attn_kernel,
                         cudaFuncAttributeMaxDynamicSharedMemorySize, attn_smem);
    cudaFuncSetAttribute(gemm_mma_kernel,
                         cudaFuncAttributeMaxDynamicSharedMemorySize, GEMM_SMEM_BYTES);
    cudaFuncSetAttribute(av_mma_kernel,
                         cudaFuncAttributeMaxDynamicSharedMemorySize, AV_SMEM_BYTES);
    cudaFuncSetAttribute(qk_mma_kernel,
                         cudaFuncAttributeMaxDynamicSharedMemorySize, QK_SMEM_BYTES);

    __nv_bfloat16 *wqkv_hi, *wqkv_lo, *xt_hi, *xt_lo, *wp_hi, *wp_lo, *pt_hi, *pt_lo;
    __nv_bfloat16 *qkh_hi, *qkh_lo;
    float *sv, *tv;
    cudaGetSymbolAddress((void**)&wqkv_hi, g_wqkv_hi);
    cudaGetSymbolAddress((void**)&wqkv_lo, g_wqkv_lo);
    cudaGetSymbolAddress((void**)&xt_hi, g_xt_hi);
    cudaGetSymbolAddress((void**)&xt_lo, g_xt_lo);
    cudaGetSymbolAddress((void**)&wp_hi, g_wp_hi);
    cudaGetSymbolAddress((void**)&wp_lo, g_wp_lo);
    cudaGetSymbolAddress((void**)&pt_hi, g_pt_hi);
    cudaGetSymbolAddress((void**)&pt_lo, g_pt_lo);
    cudaGetSymbolAddress((void**)&qkh_hi, g_qkh_hi);
    cudaGetSymbolAddress((void**)&qkh_lo, g_qkh_lo);
    cudaGetSymbolAddress((void**)&sv, g_s);
    cudaGetSymbolAddress((void**)&tv, g_t);

    // streams/events created once, outside any capture.
    static cudaStream_t s2 = nullptr;
    static cudaEvent_t evA, evB, evC, evD;
    if (s2 == nullptr) {
        cudaStreamCreateWithFlags(&s2, cudaStreamNonBlocking);
        cudaEventCreateWithFlags(&evA, cudaEventDisableTiming);
        cudaEventCreateWithFlags(&evB, cudaEventDisableTiming);
        cudaEventCreateWithFlags(&evC, cudaEventDisableTiming);
        cudaEventCreateWithFlags(&evD, cudaEventDisableTiming);
    }

    // fork: xt_cvt on s2 || prep1 on main
    cudaEventRecord(evA, 0);
    cudaStreamWaitEvent(s2, evA, 0);
    xt_cvt_kernel<<<dim3(7, 12, 64), 256, 0, s2>>>(x);
    prep_kernel<<<1152, 256>>>(wq, wk, wv, bq, bk, bv, bp, bnq, bnk, bnv, bnp);
    cudaEventRecord(evB, s2);
    cudaStreamWaitEvent(0, evB, 0);

    // s2: prep2 (wp split + pad zeroing) overlaps the qkv GEMM on main
    prep2_kernel<<<1152, 256, 0, s2>>>(wp);

    // qkv GEMM: exports q/k (g_qkh) and V (g_vhi/g_vlo); J-tile 256
    gemm_mma_kernel<<<dim3(49, 12), 256, GEMM_SMEM_BYTES>>>(
        wqkv_hi, wqkv_lo, xt_hi, xt_lo, 384, sv, tv, nullptr, 1536, qkh_hi, qkh_lo);

    // fork: dwconv on s2 || (qk -> attn) on main
    cudaEventRecord(evC, 0);
    cudaStreamWaitEvent(s2, evC, 0);
    dwconv_kernel<<<dim3(128, 64), 256, 0, s2>>>(wvl, bvl, bnvl);
    qk_mma_kernel<<<dim3(2, 2, 512), 256, QK_SMEM_BYTES>>>(ab, bidx);
    attn_kernel<<<dim3(14, 64), 256, attn_smem>>>(th1w, th1b, th2w, th2b);
    cudaEventRecord(evD, s2);
    cudaStreamWaitEvent(0, evD, 0);

    // AV (needs attn P + dwconv vloc + prep2 pads), then projection (J-tile 256)
    av_mma_kernel<<<512, 256, AV_SMEM_BYTES>>>();
    gemm_mma_kernel<<<dim3(49, 3), 256, GEMM_SMEM_BYTES>>>(
        wp_hi, wp_lo, pt_hi, pt_lo, 1024, sv + 1536, tv + 1536, out, 384,
        nullptr, nullptr);
}